// round 2
// baseline (speedup 1.0000x reference)
#include <cuda_runtime.h>
#include <math.h>

#define NN    50000
#define EE    600000
#define ETOT  (EE + NN)
#define DD    128
#define EDIM  16
#define NHEAD 4
#define NEG_SLOPE 0.2f

// ---------------- scratch (static device globals; no allocs allowed) -------
__device__ __align__(16) float g_h[NN * DD];
__device__ __align__(16) float g_xl[NN * DD];
__device__ __align__(16) float g_xr[NN * DD];
__device__ __align__(16) float g_logit[(size_t)ETOT * 4];
__device__ __align__(16) float g_loop_attr[NN * EDIM];
__device__ int   g_src[EE];
__device__ int   g_dst[EE];
__device__ int   g_deg[NN];
__device__ int   g_fill[NN];
__device__ int   g_rowptr[NN + 1];
__device__ int2  g_csr[ETOT];   // .x = src node, .y = edge id (eid>=EE -> self loop)
__device__ int   g_is64;

// ---------------- index dtype detection + conversion -----------------------
// If edge_index is int64 (little-endian, values < 2^31), every odd 32-bit
// word is zero. If int32, odd words are random node ids — essentially never
// all zero across 64 samples.
__global__ void k_detect(const int* __restrict__ ei_raw) {
    if (threadIdx.x == 0 && blockIdx.x == 0) {
        int all0 = 1;
        for (int i = 0; i < 64; i++)
            if (ei_raw[2 * i + 1] != 0) { all0 = 0; break; }
        g_is64 = all0;
    }
}

__global__ void k_cvt(const int* __restrict__ ei_raw) {
    int i = blockIdx.x * blockDim.x + threadIdx.x;
    if (i >= 2 * EE) return;
    int v = g_is64 ? ei_raw[2 * i] : ei_raw[i];
    if (i < EE) g_src[i] = v;
    else        g_dst[i - EE] = v;
}

// ---------------- small helpers -------------------------------------------
__global__ void k_zero() {
    int i = blockIdx.x * blockDim.x + threadIdx.x;
    if (i < NN) { g_deg[i] = 0; g_fill[i] = 0; }
}

__global__ void k_deg() {
    int i = blockIdx.x * blockDim.x + threadIdx.x;
    if (i < EE) atomicAdd(&g_deg[g_dst[i]], 1);
}

// single-block inclusive scan of (deg+1) -> rowptr
__global__ void k_scan() {
    __shared__ int sh[1024];
    __shared__ int s_carry;
    int tid = threadIdx.x;
    if (tid == 0) { s_carry = 0; g_rowptr[0] = 0; }
    __syncthreads();
    for (int base = 0; base < NN; base += 1024) {
        int idx = base + tid;
        int v = (idx < NN) ? (g_deg[idx] + 1) : 0;
        sh[tid] = v;
        __syncthreads();
        for (int off = 1; off < 1024; off <<= 1) {
            int t = (tid >= off) ? sh[tid - off] : 0;
            __syncthreads();
            sh[tid] += t;
            __syncthreads();
        }
        int tot = sh[1023];
        if (idx < NN) g_rowptr[idx + 1] = s_carry + sh[tid];
        __syncthreads();
        if (tid == 0) s_carry += tot;
        __syncthreads();
    }
}

__global__ void k_scatter() {
    int i = blockIdx.x * blockDim.x + threadIdx.x;
    if (i < EE) {
        int d = g_dst[i];
        int p = atomicAdd(&g_fill[d], 1);
        g_csr[g_rowptr[d] + p] = make_int2(g_src[i], i);
    } else if (i < ETOT) {
        int n = i - EE;
        g_csr[g_rowptr[n] + g_deg[n]] = make_int2(n, EE + n);  // self loop last
    }
}

// loop_attr[n] = mean of incoming edge_attr (0 if no incoming edges)
__global__ void k_loopattr(const float* __restrict__ edge_attr) {
    int gt = blockIdx.x * blockDim.x + threadIdx.x;
    int node = gt >> 4;
    int k = gt & 15;
    if (node >= NN) return;
    int beg = g_rowptr[node];
    int dg = g_deg[node];
    float s = 0.f;
    for (int i = 0; i < dg; i++) {
        int eid = g_csr[beg + i].y;
        s += edge_attr[(size_t)eid * EDIM + k];
    }
    g_loop_attr[node * EDIM + k] = s / (float)max(dg, 1);
}

// ---------------- SGEMM: out[M,128] = A[M,128] @ W[128,128] + bias ---------
// block = 256 thr = 8 warps, 64 rows/block. Each lane: 8 rows x 4 cols.
__global__ __launch_bounds__(256) void k_gemm(const float* __restrict__ A,
                                              const float* __restrict__ W,
                                              const float* __restrict__ bias,
                                              float* __restrict__ out, int M) {
    __shared__ float W_sh[32][128];       // 16 KB, K-chunk of 32
    __shared__ float A_sh[8][8][32];      // 8 KB: [warp][row][k]
    int tid = threadIdx.x;
    int w = tid >> 5, lane = tid & 31;
    int row0 = blockIdx.x * 64 + w * 8;

    float acc[8][4];
#pragma unroll
    for (int j = 0; j < 8; j++)
#pragma unroll
        for (int c = 0; c < 4; c++) acc[j][c] = 0.f;

    for (int kc = 0; kc < 4; kc++) {
        // load W chunk (32x128) cooperatively
        const float4* Wv = (const float4*)(W + kc * 32 * 128);
        float4* Wsv = (float4*)&W_sh[0][0];
        for (int i = tid; i < 32 * 128 / 4; i += 256) Wsv[i] = Wv[i];
        // load A chunk: each lane -> row=lane>>2, 8 k's at (lane&3)*8
        int r = lane >> 2;
        int ko = (lane & 3) * 8;
        int grow = row0 + r;
        float4 a0 = make_float4(0, 0, 0, 0), a1 = a0;
        if (grow < M) {
            a0 = *(const float4*)(A + (size_t)grow * 128 + kc * 32 + ko);
            a1 = *(const float4*)(A + (size_t)grow * 128 + kc * 32 + ko + 4);
        }
        *(float4*)&A_sh[w][r][ko] = a0;
        *(float4*)&A_sh[w][r][ko + 4] = a1;
        __syncthreads();
#pragma unroll
        for (int k = 0; k < 32; k++) {
            float wv[4];
#pragma unroll
            for (int c = 0; c < 4; c++) wv[c] = W_sh[k][lane + 32 * c];
#pragma unroll
            for (int j = 0; j < 8; j++) {
                float av = A_sh[w][j][k];
                acc[j][0] += av * wv[0];
                acc[j][1] += av * wv[1];
                acc[j][2] += av * wv[2];
                acc[j][3] += av * wv[3];
            }
        }
        __syncthreads();
    }
    float bz[4];
#pragma unroll
    for (int c = 0; c < 4; c++) bz[c] = bias[lane + 32 * c];
#pragma unroll
    for (int j = 0; j < 8; j++) {
        int grow = row0 + j;
        if (grow < M) {
#pragma unroll
            for (int c = 0; c < 4; c++)
                out[(size_t)grow * 128 + lane + 32 * c] = acc[j][c] + bz[c];
        }
    }
}

// ---------------- edge logits: warp per edge -------------------------------
__global__ __launch_bounds__(256) void k_edge(const float* __restrict__ edge_attr,
                                              const float* __restrict__ We,
                                              const float* __restrict__ att) {
    __shared__ float4 We_sh[EDIM * 32];   // [k][lane] = We[k][4*lane..+3]
    __shared__ float4 att_sh[32];
    int tid = threadIdx.x;
    for (int i = tid; i < EDIM * 32; i += 256) We_sh[i] = ((const float4*)We)[i];
    if (tid < 32) att_sh[tid] = ((const float4*)att)[tid];
    __syncthreads();

    int lane = tid & 31;
    int e = blockIdx.x * 8 + (tid >> 5);
    if (e >= ETOT) return;

    int s, d;
    const float* ea;
    if (e < EE) {
        s = g_src[e];
        d = g_dst[e];
        ea = edge_attr + (size_t)e * EDIM;
    } else {
        s = d = e - EE;
        ea = g_loop_attr + (size_t)(e - EE) * EDIM;
    }
    float myea = (lane < EDIM) ? ea[lane] : 0.f;

    float4 ee = make_float4(0, 0, 0, 0);
#pragma unroll
    for (int k = 0; k < EDIM; k++) {
        float a = __shfl_sync(0xffffffffu, myea, k);
        float4 wv = We_sh[k * 32 + lane];
        ee.x += a * wv.x; ee.y += a * wv.y; ee.z += a * wv.z; ee.w += a * wv.w;
    }
    float4 xlv = *(const float4*)(g_xl + (size_t)s * DD + 4 * lane);
    float4 xrv = *(const float4*)(g_xr + (size_t)d * DD + 4 * lane);
    float4 m;
    m.x = xlv.x + xrv.x + ee.x;
    m.y = xlv.y + xrv.y + ee.y;
    m.z = xlv.z + xrv.z + ee.z;
    m.w = xlv.w + xrv.w + ee.w;
    m.x = (m.x > 0.f) ? m.x : NEG_SLOPE * m.x;
    m.y = (m.y > 0.f) ? m.y : NEG_SLOPE * m.y;
    m.z = (m.z > 0.f) ? m.z : NEG_SLOPE * m.z;
    m.w = (m.w > 0.f) ? m.w : NEG_SLOPE * m.w;
    float4 at = att_sh[lane];
    float p = m.x * at.x + m.y * at.y + m.z * at.z + m.w * at.w;
    p += __shfl_xor_sync(0xffffffffu, p, 1);
    p += __shfl_xor_sync(0xffffffffu, p, 2);
    p += __shfl_xor_sync(0xffffffffu, p, 4);
    if ((lane & 7) == 0) g_logit[(size_t)e * 4 + (lane >> 3)] = p;
}

// ---------------- node softmax + aggregation: warp per node ----------------
__global__ __launch_bounds__(256) void k_aggr(const float* __restrict__ cb) {
    int lane = threadIdx.x & 31;
    int n = blockIdx.x * 8 + (threadIdx.x >> 5);
    if (n >= NN) return;
    int beg = g_rowptr[n], end = g_rowptr[n + 1];

    const float NI = -1e30f;
    float4 mx = make_float4(NI, NI, NI, NI);
    for (int i = beg + lane; i < end; i += 32) {
        int eid = g_csr[i].y;
        float4 lg = *(const float4*)(g_logit + (size_t)eid * 4);
        mx.x = fmaxf(mx.x, lg.x); mx.y = fmaxf(mx.y, lg.y);
        mx.z = fmaxf(mx.z, lg.z); mx.w = fmaxf(mx.w, lg.w);
    }
#pragma unroll
    for (int off = 16; off > 0; off >>= 1) {
        mx.x = fmaxf(mx.x, __shfl_xor_sync(0xffffffffu, mx.x, off));
        mx.y = fmaxf(mx.y, __shfl_xor_sync(0xffffffffu, mx.y, off));
        mx.z = fmaxf(mx.z, __shfl_xor_sync(0xffffffffu, mx.z, off));
        mx.w = fmaxf(mx.w, __shfl_xor_sync(0xffffffffu, mx.w, off));
    }
    float4 sm = make_float4(0, 0, 0, 0);
    for (int i = beg + lane; i < end; i += 32) {
        int eid = g_csr[i].y;
        float4 lg = *(const float4*)(g_logit + (size_t)eid * 4);
        sm.x += expf(lg.x - mx.x); sm.y += expf(lg.y - mx.y);
        sm.z += expf(lg.z - mx.z); sm.w += expf(lg.w - mx.w);
    }
#pragma unroll
    for (int off = 16; off > 0; off >>= 1) {
        sm.x += __shfl_xor_sync(0xffffffffu, sm.x, off);
        sm.y += __shfl_xor_sync(0xffffffffu, sm.y, off);
        sm.z += __shfl_xor_sync(0xffffffffu, sm.z, off);
        sm.w += __shfl_xor_sync(0xffffffffu, sm.w, off);
    }
    int h = lane >> 3;
    float mxh = (h == 0) ? mx.x : (h == 1) ? mx.y : (h == 2) ? mx.z : mx.w;
    float dnh = (h == 0) ? sm.x : (h == 1) ? sm.y : (h == 2) ? sm.z : sm.w;
    float inv = 1.f / dnh;

    float4 acc = make_float4(0, 0, 0, 0);
    for (int i = beg; i < end; i++) {
        int2 cs = g_csr[i];
        float a = expf(g_logit[(size_t)cs.y * 4 + h] - mxh) * inv;
        float4 xv = *(const float4*)(g_xl + (size_t)cs.x * DD + 4 * lane);
        acc.x += a * xv.x; acc.y += a * xv.y; acc.z += a * xv.z; acc.w += a * xv.w;
    }
    float4 cbv = *(const float4*)(cb + 4 * lane);
    float4 o;
    o.x = acc.x + cbv.x; o.y = acc.y + cbv.y; o.z = acc.z + cbv.z; o.w = acc.w + cbv.w;
    o.x = (o.x > 0.f) ? o.x : expm1f(o.x);
    o.y = (o.y > 0.f) ? o.y : expm1f(o.y);
    o.z = (o.z > 0.f) ? o.z : expm1f(o.z);
    o.w = (o.w > 0.f) ? o.w : expm1f(o.w);
    *(float4*)(g_h + (size_t)n * DD + 4 * lane) = o;
}

// ---------------- final: LN + MLP head, warp per row -----------------------
__global__ __launch_bounds__(256) void k_final(const float* __restrict__ ln_g,
                                               const float* __restrict__ ln_b,
                                               const float* __restrict__ h1w,
                                               const float* __restrict__ h1b,
                                               const float* __restrict__ h2w,
                                               const float* __restrict__ h2b,
                                               float* __restrict__ out) {
    __shared__ float W1[128 * 64];   // 32 KB
    __shared__ float W2[64 * 3];
    __shared__ float rowbuf[8][128];
    int tid = threadIdx.x;
    for (int i = tid; i < 128 * 64; i += 256) W1[i] = h1w[i];
    if (tid < 64 * 3) W2[tid] = h2w[tid];
    __syncthreads();

    int lane = tid & 31, w = tid >> 5;
    int n = blockIdx.x * 8 + w;
    if (n >= NN) return;

    float4 hv = *(const float4*)(g_h + (size_t)n * DD + 4 * lane);
    float s = hv.x + hv.y + hv.z + hv.w;
#pragma unroll
    for (int off = 16; off > 0; off >>= 1) s += __shfl_xor_sync(0xffffffffu, s, off);
    float mu = s / 128.f;
    float4 dm = make_float4(hv.x - mu, hv.y - mu, hv.z - mu, hv.w - mu);
    float v = dm.x * dm.x + dm.y * dm.y + dm.z * dm.z + dm.w * dm.w;
#pragma unroll
    for (int off = 16; off > 0; off >>= 1) v += __shfl_xor_sync(0xffffffffu, v, off);
    float r = rsqrtf(v / 128.f + 1e-5f);
    float4 g4 = *(const float4*)(ln_g + 4 * lane);
    float4 b4 = *(const float4*)(ln_b + 4 * lane);
    float4 hn;
    hn.x = dm.x * r * g4.x + b4.x;
    hn.y = dm.y * r * g4.y + b4.y;
    hn.z = dm.z * r * g4.z + b4.z;
    hn.w = dm.w * r * g4.w + b4.w;
    *(float4*)&rowbuf[w][4 * lane] = hn;
    __syncwarp();

    float m0 = h1b[lane], m1 = h1b[lane + 32];
#pragma unroll 4
    for (int k = 0; k < 128; k++) {
        float a = rowbuf[w][k];
        m0 += a * W1[k * 64 + lane];
        m1 += a * W1[k * 64 + lane + 32];
    }
    m0 = fmaxf(m0, 0.f);
    m1 = fmaxf(m1, 0.f);
    float p0 = m0 * W2[lane * 3 + 0] + m1 * W2[(lane + 32) * 3 + 0];
    float p1 = m0 * W2[lane * 3 + 1] + m1 * W2[(lane + 32) * 3 + 1];
    float p2 = m0 * W2[lane * 3 + 2] + m1 * W2[(lane + 32) * 3 + 2];
#pragma unroll
    for (int off = 16; off > 0; off >>= 1) {
        p0 += __shfl_xor_sync(0xffffffffu, p0, off);
        p1 += __shfl_xor_sync(0xffffffffu, p1, off);
        p2 += __shfl_xor_sync(0xffffffffu, p2, off);
    }
    if (lane == 0) {
        out[(size_t)n * 3 + 0] = p0 + h2b[0];
        out[(size_t)n * 3 + 1] = p1 + h2b[1];
        out[(size_t)n * 3 + 2] = p2 + h2b[2];
    }
}

// ---------------- host launcher -------------------------------------------
extern "C" void kernel_launch(void* const* d_in, const int* in_sizes, int n_in,
                              void* d_out, int out_size) {
    const float* x         = (const float*)d_in[0];
    const int*   ei_raw    = (const int*)d_in[1];    // int32 OR int64 (detected)
    const float* edge_attr = (const float*)d_in[2];
    const float* in_w      = (const float*)d_in[3];
    const float* in_b      = (const float*)d_in[4];
    const float* Wl        = (const float*)d_in[5];
    const float* bl        = (const float*)d_in[6];
    const float* Wr        = (const float*)d_in[7];
    const float* br        = (const float*)d_in[8];
    const float* We        = (const float*)d_in[9];
    const float* att       = (const float*)d_in[10];
    const float* cb        = (const float*)d_in[11];
    const float* ln_g      = (const float*)d_in[12];
    const float* ln_b      = (const float*)d_in[13];
    const float* h1w       = (const float*)d_in[14];
    const float* h1b       = (const float*)d_in[15];
    const float* h2w       = (const float*)d_in[16];
    const float* h2b       = (const float*)d_in[17];

    float *hp, *xlp, *xrp;
    cudaGetSymbolAddress((void**)&hp,  g_h);
    cudaGetSymbolAddress((void**)&xlp, g_xl);
    cudaGetSymbolAddress((void**)&xrp, g_xr);

    // index ingestion (dtype-robust) + graph preprocessing
    k_detect<<<1, 32>>>(ei_raw);
    k_cvt<<<(2 * EE + 255) / 256, 256>>>(ei_raw);
    k_zero<<<(NN + 255) / 256, 256>>>();
    k_deg<<<(EE + 255) / 256, 256>>>();
    k_scan<<<1, 1024>>>();
    k_scatter<<<(ETOT + 255) / 256, 256>>>();
    k_loopattr<<<(NN * 16 + 255) / 256, 256>>>(edge_attr);

    // input projection
    k_gemm<<<(NN + 63) / 64, 256>>>(x, in_w, in_b, hp, NN);

    for (int l = 0; l < 2; l++) {
        const float* Wl_l  = Wl + l * 128 * 128;
        const float* Wr_l  = Wr + l * 128 * 128;
        const float* bl_l  = bl + l * 128;
        const float* br_l  = br + l * 128;
        const float* We_l  = We + l * EDIM * 128;
        const float* att_l = att + l * 128;
        const float* cb_l  = cb + l * 128;

        k_gemm<<<(NN + 63) / 64, 256>>>(hp, Wl_l, bl_l, xlp, NN);
        k_gemm<<<(NN + 63) / 64, 256>>>(hp, Wr_l, br_l, xrp, NN);
        k_edge<<<(ETOT + 7) / 8, 256>>>(edge_attr, We_l, att_l);
        k_aggr<<<(NN + 7) / 8, 256>>>(cb_l);
    }

    k_final<<<(NN + 7) / 8, 256>>>(ln_g, ln_b, h1w, h1b, h2w, h2b, (float*)d_out);
}

// round 5
// speedup vs baseline: 1.2250x; 1.2250x over previous
#include <cuda_runtime.h>
#include <math.h>

#define NN    50000
#define EE    600000
#define ETOT  (EE + NN)
#define DD    128
#define EDIM  16
#define NEG_SLOPE 0.2f

// ---------------- scratch (static device globals; no allocs allowed) -------
__device__ __align__(16) float g_h[NN * DD];
__device__ __align__(16) float g_xl[NN * DD];
__device__ __align__(16) float g_xr[NN * DD];
__device__ __align__(16) float g_logit[(size_t)ETOT * 4];
__device__ __align__(16) float g_loop_attr[NN * EDIM];
__device__ int   g_src[EE];
__device__ int   g_dst[EE];
__device__ int   g_deg[NN];
__device__ int   g_fill[NN];
__device__ int   g_rowptr[NN + 1];
__device__ int2  g_csr[ETOT];   // .x = src node, .y = edge id (eid>=EE -> self loop)
__device__ int   g_is64;

// ---------------- index dtype detection + conversion -----------------------
__global__ void k_detect(const int* __restrict__ ei_raw) {
    if (threadIdx.x == 0 && blockIdx.x == 0) {
        int all0 = 1;
        for (int i = 0; i < 64; i++)
            if (ei_raw[2 * i + 1] != 0) { all0 = 0; break; }
        g_is64 = all0;
    }
}

__global__ void k_cvt(const int* __restrict__ ei_raw) {
    int i = blockIdx.x * blockDim.x + threadIdx.x;
    if (i >= 2 * EE) return;
    int v = g_is64 ? ei_raw[2 * i] : ei_raw[i];
    if (i < EE) g_src[i] = v;
    else        g_dst[i - EE] = v;
}

// ---------------- small helpers -------------------------------------------
__global__ void k_zero() {
    int i = blockIdx.x * blockDim.x + threadIdx.x;
    if (i < NN) { g_deg[i] = 0; g_fill[i] = 0; }
}

__global__ void k_deg() {
    int i = blockIdx.x * blockDim.x + threadIdx.x;
    if (i < EE) atomicAdd(&g_deg[g_dst[i]], 1);
}

// single-block scan of (deg+1) -> rowptr; 4 elems/thread, shfl warp scans
__global__ __launch_bounds__(1024) void k_scan() {
    __shared__ int warp_tot[32];
    __shared__ int s_carry;
    int tid = threadIdx.x, lane = tid & 31, wid = tid >> 5;
    if (tid == 0) { s_carry = 0; g_rowptr[0] = 0; }
    __syncthreads();
    for (int base = 0; base < NN; base += 4096) {
        int idx0 = base + tid * 4;
        int v[4], s = 0;
#pragma unroll
        for (int t = 0; t < 4; t++) {
            int i = idx0 + t;
            v[t] = (i < NN) ? (g_deg[i] + 1) : 0;
            s += v[t];
        }
        int ss = s;
#pragma unroll
        for (int off = 1; off < 32; off <<= 1) {
            int t = __shfl_up_sync(0xffffffffu, ss, off);
            if (lane >= off) ss += t;
        }
        if (lane == 31) warp_tot[wid] = ss;
        __syncthreads();
        if (wid == 0) {
            int wv = warp_tot[lane];
#pragma unroll
            for (int off = 1; off < 32; off <<= 1) {
                int t = __shfl_up_sync(0xffffffffu, wv, off);
                if (lane >= off) wv += t;
            }
            warp_tot[lane] = wv;   // inclusive warp totals
        }
        __syncthreads();
        int warp_prefix = (wid == 0) ? 0 : warp_tot[wid - 1];
        int run = s_carry + warp_prefix + (ss - s);
#pragma unroll
        for (int t = 0; t < 4; t++) {
            run += v[t];
            if (idx0 + t < NN) g_rowptr[idx0 + t + 1] = run;
        }
        __syncthreads();
        if (tid == 0) s_carry += warp_tot[31];
        __syncthreads();
    }
}

__global__ void k_scatter() {
    int i = blockIdx.x * blockDim.x + threadIdx.x;
    if (i < EE) {
        int d = g_dst[i];
        int p = atomicAdd(&g_fill[d], 1);
        g_csr[g_rowptr[d] + p] = make_int2(g_src[i], i);
    } else if (i < ETOT) {
        int n = i - EE;
        g_csr[g_rowptr[n] + g_deg[n]] = make_int2(n, EE + n);  // self loop last
    }
}

// loop_attr[n] = mean of incoming edge_attr (0 if no incoming edges)
__global__ void k_loopattr(const float* __restrict__ edge_attr) {
    int gt = blockIdx.x * blockDim.x + threadIdx.x;
    int node = gt >> 4;
    int k = gt & 15;
    if (node >= NN) return;
    int beg = g_rowptr[node];
    int dg = g_deg[node];
    float s = 0.f;
    for (int i = 0; i < dg; i++) {
        int eid = g_csr[beg + i].y;
        s += edge_attr[(size_t)eid * EDIM + k];
    }
    g_loop_attr[node * EDIM + k] = s / (float)max(dg, 1);
}

// ---------------- SGEMM single: out[M,128] = A[M,128]@W + b ---------------
// 256 thr, 64 rows/block, warp=8 rows, lane cols 4*lane..4*lane+3.
__global__ __launch_bounds__(256) void k_gemm1(const float* __restrict__ A,
                                               const float* __restrict__ W,
                                               const float* __restrict__ bias,
                                               float* __restrict__ out, int M) {
    __shared__ float W_sh[32][128];     // 16 KB
    __shared__ float A_sh[8][32][8];    // 8 KB  [warp][k][row]
    int tid = threadIdx.x;
    int w = tid >> 5, lane = tid & 31;
    int row0 = blockIdx.x * 64 + w * 8;

    float acc[8][4];
#pragma unroll
    for (int j = 0; j < 8; j++)
#pragma unroll
        for (int c = 0; c < 4; c++) acc[j][c] = 0.f;

    for (int kc = 0; kc < 4; kc++) {
        const float4* Wv = (const float4*)(W + kc * 32 * 128);
        float4* Wsv = (float4*)&W_sh[0][0];
        for (int i = tid; i < 32 * 128 / 4; i += 256) Wsv[i] = Wv[i];
        int r = lane >> 2;
        int ko = (lane & 3) * 8;
        int grow = row0 + r;
        float4 a0 = make_float4(0, 0, 0, 0), a1 = a0;
        if (grow < M) {
            a0 = *(const float4*)(A + (size_t)grow * 128 + kc * 32 + ko);
            a1 = *(const float4*)(A + (size_t)grow * 128 + kc * 32 + ko + 4);
        }
        A_sh[w][ko + 0][r] = a0.x; A_sh[w][ko + 1][r] = a0.y;
        A_sh[w][ko + 2][r] = a0.z; A_sh[w][ko + 3][r] = a0.w;
        A_sh[w][ko + 4][r] = a1.x; A_sh[w][ko + 5][r] = a1.y;
        A_sh[w][ko + 6][r] = a1.z; A_sh[w][ko + 7][r] = a1.w;
        __syncthreads();
#pragma unroll
        for (int k = 0; k < 32; k++) {
            float4 a03 = *(const float4*)&A_sh[w][k][0];
            float4 a47 = *(const float4*)&A_sh[w][k][4];
            float4 wv  = *(const float4*)&W_sh[k][4 * lane];
            float av[8] = {a03.x, a03.y, a03.z, a03.w, a47.x, a47.y, a47.z, a47.w};
#pragma unroll
            for (int j = 0; j < 8; j++) {
                acc[j][0] += av[j] * wv.x;
                acc[j][1] += av[j] * wv.y;
                acc[j][2] += av[j] * wv.z;
                acc[j][3] += av[j] * wv.w;
            }
        }
        __syncthreads();
    }
    float4 bz = *(const float4*)(bias + 4 * lane);
#pragma unroll
    for (int j = 0; j < 8; j++) {
        int grow = row0 + j;
        if (grow < M) {
            float4 o = make_float4(acc[j][0] + bz.x, acc[j][1] + bz.y,
                                   acc[j][2] + bz.z, acc[j][3] + bz.w);
            *(float4*)(out + (size_t)grow * 128 + 4 * lane) = o;
        }
    }
}

// ---------------- SGEMM dual: xl = A@W1+b1, xr = A@W2+b2 -------------------
__global__ __launch_bounds__(256) void k_gemm2(const float* __restrict__ A,
                                               const float* __restrict__ W1,
                                               const float* __restrict__ b1,
                                               const float* __restrict__ W2,
                                               const float* __restrict__ b2,
                                               float* __restrict__ out1,
                                               float* __restrict__ out2, int M) {
    __shared__ float W1_sh[32][128];
    __shared__ float W2_sh[32][128];
    __shared__ float A_sh[8][32][8];
    int tid = threadIdx.x;
    int w = tid >> 5, lane = tid & 31;
    int row0 = blockIdx.x * 64 + w * 8;

    float acc1[8][4], acc2[8][4];
#pragma unroll
    for (int j = 0; j < 8; j++)
#pragma unroll
        for (int c = 0; c < 4; c++) { acc1[j][c] = 0.f; acc2[j][c] = 0.f; }

    for (int kc = 0; kc < 4; kc++) {
        const float4* W1v = (const float4*)(W1 + kc * 32 * 128);
        const float4* W2v = (const float4*)(W2 + kc * 32 * 128);
        float4* W1s = (float4*)&W1_sh[0][0];
        float4* W2s = (float4*)&W2_sh[0][0];
        for (int i = tid; i < 32 * 128 / 4; i += 256) { W1s[i] = W1v[i]; W2s[i] = W2v[i]; }
        int r = lane >> 2;
        int ko = (lane & 3) * 8;
        int grow = row0 + r;
        float4 a0 = make_float4(0, 0, 0, 0), a1 = a0;
        if (grow < M) {
            a0 = *(const float4*)(A + (size_t)grow * 128 + kc * 32 + ko);
            a1 = *(const float4*)(A + (size_t)grow * 128 + kc * 32 + ko + 4);
        }
        A_sh[w][ko + 0][r] = a0.x; A_sh[w][ko + 1][r] = a0.y;
        A_sh[w][ko + 2][r] = a0.z; A_sh[w][ko + 3][r] = a0.w;
        A_sh[w][ko + 4][r] = a1.x; A_sh[w][ko + 5][r] = a1.y;
        A_sh[w][ko + 6][r] = a1.z; A_sh[w][ko + 7][r] = a1.w;
        __syncthreads();
#pragma unroll
        for (int k = 0; k < 32; k++) {
            float4 a03 = *(const float4*)&A_sh[w][k][0];
            float4 a47 = *(const float4*)&A_sh[w][k][4];
            float4 w1  = *(const float4*)&W1_sh[k][4 * lane];
            float4 w2  = *(const float4*)&W2_sh[k][4 * lane];
            float av[8] = {a03.x, a03.y, a03.z, a03.w, a47.x, a47.y, a47.z, a47.w};
#pragma unroll
            for (int j = 0; j < 8; j++) {
                acc1[j][0] += av[j] * w1.x; acc1[j][1] += av[j] * w1.y;
                acc1[j][2] += av[j] * w1.z; acc1[j][3] += av[j] * w1.w;
                acc2[j][0] += av[j] * w2.x; acc2[j][1] += av[j] * w2.y;
                acc2[j][2] += av[j] * w2.z; acc2[j][3] += av[j] * w2.w;
            }
        }
        __syncthreads();
    }
    float4 bz1 = *(const float4*)(b1 + 4 * lane);
    float4 bz2 = *(const float4*)(b2 + 4 * lane);
#pragma unroll
    for (int j = 0; j < 8; j++) {
        int grow = row0 + j;
        if (grow < M) {
            float4 o1 = make_float4(acc1[j][0] + bz1.x, acc1[j][1] + bz1.y,
                                    acc1[j][2] + bz1.z, acc1[j][3] + bz1.w);
            float4 o2 = make_float4(acc2[j][0] + bz2.x, acc2[j][1] + bz2.y,
                                    acc2[j][2] + bz2.z, acc2[j][3] + bz2.w);
            *(float4*)(out1 + (size_t)grow * 128 + 4 * lane) = o1;
            *(float4*)(out2 + (size_t)grow * 128 + 4 * lane) = o2;
        }
    }
}

// ---------------- fused attention: warp per dst node -----------------------
// pass1: per-edge logits (write g_logit, track per-head running max in reg)
// pass2: acc += exp(logit-max)*xl[src], den += exp(logit-max); normalize.
__global__ __launch_bounds__(256) void k_attn(const float* __restrict__ edge_attr,
                                              const float* __restrict__ We,
                                              const float* __restrict__ att,
                                              const float* __restrict__ cb) {
    __shared__ float4 We_sh[EDIM * 32];   // [k][lane] = We[k][4*lane..+3]
    __shared__ float4 att_sh[32];
    int tid = threadIdx.x;
    for (int i = tid; i < EDIM * 32; i += 256) We_sh[i] = ((const float4*)We)[i];
    if (tid < 32) att_sh[tid] = ((const float4*)att)[tid];
    __syncthreads();

    int lane = tid & 31;
    int n = blockIdx.x * 8 + (tid >> 5);
    if (n >= NN) return;
    int beg = g_rowptr[n], end = g_rowptr[n + 1];
    int h = lane >> 3;  // this lane's 4 channels (4*lane..+3) belong to head h

    float4 xr4 = *(const float4*)(g_xr + (size_t)n * DD + 4 * lane);
    float4 at  = att_sh[lane];

    // ---- pass 1: logits + per-head max ----
    float mxh = -1e30f;
    for (int i = beg; i < end; i++) {
        int2 cs = g_csr[i];
        const float* ea = (cs.y < EE) ? (edge_attr + (size_t)cs.y * EDIM)
                                      : (g_loop_attr + (size_t)n * EDIM);
        float myea = (lane < EDIM) ? ea[lane] : 0.f;
        float4 ee = make_float4(0, 0, 0, 0);
#pragma unroll
        for (int k = 0; k < EDIM; k++) {
            float a = __shfl_sync(0xffffffffu, myea, k);
            float4 wv = We_sh[k * 32 + lane];
            ee.x += a * wv.x; ee.y += a * wv.y; ee.z += a * wv.z; ee.w += a * wv.w;
        }
        float4 xlv = *(const float4*)(g_xl + (size_t)cs.x * DD + 4 * lane);
        float4 m;
        m.x = xlv.x + xr4.x + ee.x;
        m.y = xlv.y + xr4.y + ee.y;
        m.z = xlv.z + xr4.z + ee.z;
        m.w = xlv.w + xr4.w + ee.w;
        m.x = (m.x > 0.f) ? m.x : NEG_SLOPE * m.x;
        m.y = (m.y > 0.f) ? m.y : NEG_SLOPE * m.y;
        m.z = (m.z > 0.f) ? m.z : NEG_SLOPE * m.z;
        m.w = (m.w > 0.f) ? m.w : NEG_SLOPE * m.w;
        float p = m.x * at.x + m.y * at.y + m.z * at.z + m.w * at.w;
        p += __shfl_xor_sync(0xffffffffu, p, 1);
        p += __shfl_xor_sync(0xffffffffu, p, 2);
        p += __shfl_xor_sync(0xffffffffu, p, 4);   // all 8 lanes of head hold logit
        mxh = fmaxf(mxh, p);
        if ((lane & 7) == 0) g_logit[(size_t)cs.y * 4 + h] = p;
    }
    __syncwarp();

    // ---- pass 2: weighted gather + denominator (unnormalized) ----
    float4 acc = make_float4(0, 0, 0, 0);
    float den = 0.f;
    for (int i = beg; i < end; i++) {
        int2 cs = g_csr[i];
        float lg = g_logit[(size_t)cs.y * 4 + h];
        float a = __expf(lg - mxh);
        den += a;
        float4 xv = *(const float4*)(g_xl + (size_t)cs.x * DD + 4 * lane);
        acc.x += a * xv.x; acc.y += a * xv.y; acc.z += a * xv.z; acc.w += a * xv.w;
    }
    float inv = 1.f / den;
    float4 cbv = *(const float4*)(cb + 4 * lane);
    float4 o;
    o.x = acc.x * inv + cbv.x;
    o.y = acc.y * inv + cbv.y;
    o.z = acc.z * inv + cbv.z;
    o.w = acc.w * inv + cbv.w;
    o.x = (o.x > 0.f) ? o.x : expm1f(o.x);
    o.y = (o.y > 0.f) ? o.y : expm1f(o.y);
    o.z = (o.z > 0.f) ? o.z : expm1f(o.z);
    o.w = (o.w > 0.f) ? o.w : expm1f(o.w);
    *(float4*)(g_h + (size_t)n * DD + 4 * lane) = o;
}

// ---------------- final: LN + MLP head, warp per row -----------------------
__global__ __launch_bounds__(256) void k_final(const float* __restrict__ ln_g,
                                               const float* __restrict__ ln_b,
                                               const float* __restrict__ h1w,
                                               const float* __restrict__ h1b,
                                               const float* __restrict__ h2w,
                                               const float* __restrict__ h2b,
                                               float* __restrict__ out) {
    __shared__ float W1[128 * 64];   // 32 KB
    __shared__ float W2[64 * 3];
    __shared__ float rowbuf[8][128];
    int tid = threadIdx.x;
    for (int i = tid; i < 128 * 64; i += 256) W1[i] = h1w[i];
    if (tid < 64 * 3) W2[tid] = h2w[tid];
    __syncthreads();

    int lane = tid & 31, w = tid >> 5;
    int n = blockIdx.x * 8 + w;
    if (n >= NN) return;

    float4 hv = *(const float4*)(g_h + (size_t)n * DD + 4 * lane);
    float s = hv.x + hv.y + hv.z + hv.w;
#pragma unroll
    for (int off = 16; off > 0; off >>= 1) s += __shfl_xor_sync(0xffffffffu, s, off);
    float mu = s / 128.f;
    float4 dm = make_float4(hv.x - mu, hv.y - mu, hv.z - mu, hv.w - mu);
    float v = dm.x * dm.x + dm.y * dm.y + dm.z * dm.z + dm.w * dm.w;
#pragma unroll
    for (int off = 16; off > 0; off >>= 1) v += __shfl_xor_sync(0xffffffffu, v, off);
    float r = rsqrtf(v / 128.f + 1e-5f);
    float4 g4 = *(const float4*)(ln_g + 4 * lane);
    float4 b4 = *(const float4*)(ln_b + 4 * lane);
    float4 hn;
    hn.x = dm.x * r * g4.x + b4.x;
    hn.y = dm.y * r * g4.y + b4.y;
    hn.z = dm.z * r * g4.z + b4.z;
    hn.w = dm.w * r * g4.w + b4.w;
    *(float4*)&rowbuf[w][4 * lane] = hn;
    __syncwarp();

    float m0 = h1b[lane], m1 = h1b[lane + 32];
#pragma unroll 4
    for (int k = 0; k < 128; k++) {
        float a = rowbuf[w][k];
        m0 += a * W1[k * 64 + lane];
        m1 += a * W1[k * 64 + lane + 32];
    }
    m0 = fmaxf(m0, 0.f);
    m1 = fmaxf(m1, 0.f);
    float p0 = m0 * W2[lane * 3 + 0] + m1 * W2[(lane + 32) * 3 + 0];
    float p1 = m0 * W2[lane * 3 + 1] + m1 * W2[(lane + 32) * 3 + 1];
    float p2 = m0 * W2[lane * 3 + 2] + m1 * W2[(lane + 32) * 3 + 2];
#pragma unroll
    for (int off = 16; off > 0; off >>= 1) {
        p0 += __shfl_xor_sync(0xffffffffu, p0, off);
        p1 += __shfl_xor_sync(0xffffffffu, p1, off);
        p2 += __shfl_xor_sync(0xffffffffu, p2, off);
    }
    if (lane == 0) {
        out[(size_t)n * 3 + 0] = p0 + h2b[0];
        out[(size_t)n * 3 + 1] = p1 + h2b[1];
        out[(size_t)n * 3 + 2] = p2 + h2b[2];
    }
}

// ---------------- host launcher -------------------------------------------
extern "C" void kernel_launch(void* const* d_in, const int* in_sizes, int n_in,
                              void* d_out, int out_size) {
    const float* x         = (const float*)d_in[0];
    const int*   ei_raw    = (const int*)d_in[1];    // int32 OR int64 (detected)
    const float* edge_attr = (const float*)d_in[2];
    const float* in_w      = (const float*)d_in[3];
    const float* in_b      = (const float*)d_in[4];
    const float* Wl        = (const float*)d_in[5];
    const float* bl        = (const float*)d_in[6];
    const float* Wr        = (const float*)d_in[7];
    const float* br        = (const float*)d_in[8];
    const float* We        = (const float*)d_in[9];
    const float* att       = (const float*)d_in[10];
    const float* cb        = (const float*)d_in[11];
    const float* ln_g      = (const float*)d_in[12];
    const float* ln_b      = (const float*)d_in[13];
    const float* h1w       = (const float*)d_in[14];
    const float* h1b       = (const float*)d_in[15];
    const float* h2w       = (const float*)d_in[16];
    const float* h2b       = (const float*)d_in[17];

    float *hp, *xlp, *xrp;
    cudaGetSymbolAddress((void**)&hp,  g_h);
    cudaGetSymbolAddress((void**)&xlp, g_xl);
    cudaGetSymbolAddress((void**)&xrp, g_xr);

    // index ingestion (dtype-robust) + graph preprocessing
    k_detect<<<1, 32>>>(ei_raw);
    k_cvt<<<(2 * EE + 255) / 256, 256>>>(ei_raw);
    k_zero<<<(NN + 255) / 256, 256>>>();
    k_deg<<<(EE + 255) / 256, 256>>>();
    k_scan<<<1, 1024>>>();
    k_scatter<<<(ETOT + 255) / 256, 256>>>();
    k_loopattr<<<(NN * 16 + 255) / 256, 256>>>(edge_attr);

    // input projection
    k_gemm1<<<(NN + 63) / 64, 256>>>(x, in_w, in_b, hp, NN);

    for (int l = 0; l < 2; l++) {
        const float* Wl_l  = Wl + l * 128 * 128;
        const float* Wr_l  = Wr + l * 128 * 128;
        const float* bl_l  = bl + l * 128;
        const float* br_l  = br + l * 128;
        const float* We_l  = We + l * EDIM * 128;
        const float* att_l = att + l * 128;
        const float* cb_l  = cb + l * 128;

        k_gemm2<<<(NN + 63) / 64, 256>>>(hp, Wl_l, bl_l, Wr_l, br_l, xlp, xrp, NN);
        k_attn<<<(NN + 7) / 8, 256>>>(edge_attr, We_l, att_l, cb_l);
    }

    k_final<<<(NN + 7) / 8, 256>>>(ln_g, ln_b, h1w, h1b, h2w, h2b, (float*)d_out);
}

// round 8
// speedup vs baseline: 1.2456x; 1.0168x over previous
#include <cuda_runtime.h>
#include <math.h>

#define NN    50000
#define EE    600000
#define ETOT  (EE + NN)
#define DD    128
#define EDIM  16
#define NEG_SLOPE 0.2f

typedef unsigned long long ull;

// packed f32x2 ops (sm_100+; ptxas never auto-fuses these)
#define FFMA2(d, a, b) asm("fma.rn.f32x2 %0, %1, %2, %0;" : "+l"(d) : "l"(a), "l"(b))
#define FADD2(d, a, b) asm("add.rn.f32x2 %0, %1, %2;" : "=l"(d) : "l"(a), "l"(b))
#define DUP2(d, s)     asm("mov.b64 %0, {%1, %1};" : "=l"(d) : "f"(s))
#define PACK2(d, lo, hi) asm("mov.b64 %0, {%1, %2};" : "=l"(d) : "f"(lo), "f"(hi))
#define UNPK2(lo, hi, p) asm("mov.b64 {%0, %1}, %2;" : "=f"(lo), "=f"(hi) : "l"(p))

// ---------------- scratch (static device globals; no allocs allowed) -------
__device__ __align__(16) float g_h[NN * DD];
__device__ __align__(16) float g_xl[NN * DD];
__device__ __align__(16) float g_xr[NN * DD];
__device__ __align__(16) float g_logit[(size_t)ETOT * 4];
__device__ __align__(16) float g_loop_attr[NN * EDIM];
__device__ int   g_src[EE];
__device__ int   g_dst[EE];
__device__ int   g_deg[NN];
__device__ int   g_fill[NN];
__device__ int   g_rowptr[NN + 1];
__device__ int2  g_csr[ETOT];   // .x = src node, .y = edge id (eid>=EE -> self loop)
__device__ int   g_is64;

// ---------------- zero + index dtype detection -----------------------------
__global__ void k_zero(const int* __restrict__ ei_raw) {
    int i = blockIdx.x * blockDim.x + threadIdx.x;
    if (i < NN) { g_deg[i] = 0; g_fill[i] = 0; }
    if (i == 0) {
        int all0 = 1;
        for (int t = 0; t < 64; t++)
            if (ei_raw[2 * t + 1] != 0) { all0 = 0; break; }
        g_is64 = all0;
    }
}

// convert indices to int32 AND build degree histogram in one pass
__global__ void k_cvt_deg(const int* __restrict__ ei_raw) {
    int i = blockIdx.x * blockDim.x + threadIdx.x;
    if (i >= 2 * EE) return;
    int v = g_is64 ? ei_raw[2 * i] : ei_raw[i];
    if (i < EE) {
        g_src[i] = v;
    } else {
        g_dst[i - EE] = v;
        atomicAdd(&g_deg[v], 1);
    }
}

// single-block scan of (deg+1) -> rowptr; 4 elems/thread, shfl warp scans
__global__ __launch_bounds__(1024) void k_scan() {
    __shared__ int warp_tot[32];
    __shared__ int s_carry;
    int tid = threadIdx.x, lane = tid & 31, wid = tid >> 5;
    if (tid == 0) { s_carry = 0; g_rowptr[0] = 0; }
    __syncthreads();
    for (int base = 0; base < NN; base += 4096) {
        int idx0 = base + tid * 4;
        int v[4], s = 0;
#pragma unroll
        for (int t = 0; t < 4; t++) {
            int i = idx0 + t;
            v[t] = (i < NN) ? (g_deg[i] + 1) : 0;
            s += v[t];
        }
        int ss = s;
#pragma unroll
        for (int off = 1; off < 32; off <<= 1) {
            int t = __shfl_up_sync(0xffffffffu, ss, off);
            if (lane >= off) ss += t;
        }
        if (lane == 31) warp_tot[wid] = ss;
        __syncthreads();
        if (wid == 0) {
            int wv = warp_tot[lane];
#pragma unroll
            for (int off = 1; off < 32; off <<= 1) {
                int t = __shfl_up_sync(0xffffffffu, wv, off);
                if (lane >= off) wv += t;
            }
            warp_tot[lane] = wv;   // inclusive warp totals
        }
        __syncthreads();
        int warp_prefix = (wid == 0) ? 0 : warp_tot[wid - 1];
        int run = s_carry + warp_prefix + (ss - s);
#pragma unroll
        for (int t = 0; t < 4; t++) {
            run += v[t];
            if (idx0 + t < NN) g_rowptr[idx0 + t + 1] = run;
        }
        __syncthreads();
        if (tid == 0) s_carry += warp_tot[31];
        __syncthreads();
    }
}

__global__ void k_scatter() {
    int i = blockIdx.x * blockDim.x + threadIdx.x;
    if (i < EE) {
        int d = g_dst[i];
        int p = atomicAdd(&g_fill[d], 1);
        g_csr[g_rowptr[d] + p] = make_int2(g_src[i], i);
    } else if (i < ETOT) {
        int n = i - EE;
        g_csr[g_rowptr[n] + g_deg[n]] = make_int2(n, EE + n);  // self loop last
    }
}

// loop_attr[n] = mean of incoming edge_attr (0 if no incoming edges)
__global__ void k_loopattr(const float* __restrict__ edge_attr) {
    int gt = blockIdx.x * blockDim.x + threadIdx.x;
    int node = gt >> 4;
    int k = gt & 15;
    if (node >= NN) return;
    int beg = g_rowptr[node];
    int dg = g_deg[node];
    float s = 0.f;
    for (int i = 0; i < dg; i++) {
        int eid = g_csr[beg + i].y;
        s += edge_attr[(size_t)eid * EDIM + k];
    }
    g_loop_attr[node * EDIM + k] = s / (float)max(dg, 1);
}

// ---------------- SGEMM single (f32x2): out = A@W + b ----------------------
// 256 thr, 64 rows/block, warp=8 rows (4 row-pairs), lane cols 4*lane..+3.
__global__ __launch_bounds__(256) void k_gemm1(const float* __restrict__ A,
                                               const float* __restrict__ W,
                                               const float* __restrict__ bias,
                                               float* __restrict__ out, int M) {
    __shared__ float W_sh[32][128];     // 16 KB
    __shared__ float A_sh[8][32][8];    // 8 KB  [warp][k][row]
    int tid = threadIdx.x;
    int w = tid >> 5, lane = tid & 31;
    int row0 = blockIdx.x * 64 + w * 8;

    ull acc[4][4];                      // [row-pair][col]
#pragma unroll
    for (int jp = 0; jp < 4; jp++)
#pragma unroll
        for (int c = 0; c < 4; c++) acc[jp][c] = 0ULL;

    for (int kc = 0; kc < 4; kc++) {
        const float4* Wv = (const float4*)(W + kc * 32 * 128);
        float4* Wsv = (float4*)&W_sh[0][0];
        for (int i = tid; i < 32 * 128 / 4; i += 256) Wsv[i] = Wv[i];
        int r = lane >> 2;
        int ko = (lane & 3) * 8;
        int grow = row0 + r;
        float4 a0 = make_float4(0, 0, 0, 0), a1 = a0;
        if (grow < M) {
            a0 = *(const float4*)(A + (size_t)grow * 128 + kc * 32 + ko);
            a1 = *(const float4*)(A + (size_t)grow * 128 + kc * 32 + ko + 4);
        }
        A_sh[w][ko + 0][r] = a0.x; A_sh[w][ko + 1][r] = a0.y;
        A_sh[w][ko + 2][r] = a0.z; A_sh[w][ko + 3][r] = a0.w;
        A_sh[w][ko + 4][r] = a1.x; A_sh[w][ko + 5][r] = a1.y;
        A_sh[w][ko + 6][r] = a1.z; A_sh[w][ko + 7][r] = a1.w;
        __syncthreads();
#pragma unroll
        for (int k = 0; k < 32; k++) {
            ulonglong2 apA = *(const ulonglong2*)&A_sh[w][k][0];  // pairs (r0,r1)(r2,r3)
            ulonglong2 apB = *(const ulonglong2*)&A_sh[w][k][4];  // pairs (r4,r5)(r6,r7)
            float4 wv = *(const float4*)&W_sh[k][4 * lane];
            ull wd0, wd1, wd2, wd3;
            DUP2(wd0, wv.x); DUP2(wd1, wv.y); DUP2(wd2, wv.z); DUP2(wd3, wv.w);
            ull ap[4] = {apA.x, apA.y, apB.x, apB.y};
#pragma unroll
            for (int jp = 0; jp < 4; jp++) {
                FFMA2(acc[jp][0], ap[jp], wd0);
                FFMA2(acc[jp][1], ap[jp], wd1);
                FFMA2(acc[jp][2], ap[jp], wd2);
                FFMA2(acc[jp][3], ap[jp], wd3);
            }
        }
        __syncthreads();
    }
    float4 bz = *(const float4*)(bias + 4 * lane);
#pragma unroll
    for (int jp = 0; jp < 4; jp++) {
        float lo[4], hi[4];
#pragma unroll
        for (int c = 0; c < 4; c++) UNPK2(lo[c], hi[c], acc[jp][c]);
        int r0 = row0 + 2 * jp, r1 = r0 + 1;
        if (r0 < M)
            *(float4*)(out + (size_t)r0 * 128 + 4 * lane) =
                make_float4(lo[0] + bz.x, lo[1] + bz.y, lo[2] + bz.z, lo[3] + bz.w);
        if (r1 < M)
            *(float4*)(out + (size_t)r1 * 128 + 4 * lane) =
                make_float4(hi[0] + bz.x, hi[1] + bz.y, hi[2] + bz.z, hi[3] + bz.w);
    }
}

// ---------------- SGEMM dual (f32x2): xl = A@W1+b1, xr = A@W2+b2 -----------
__global__ __launch_bounds__(256) void k_gemm2(const float* __restrict__ A,
                                               const float* __restrict__ W1,
                                               const float* __restrict__ b1,
                                               const float* __restrict__ W2,
                                               const float* __restrict__ b2,
                                               float* __restrict__ out1,
                                               float* __restrict__ out2, int M) {
    __shared__ float W1_sh[32][128];
    __shared__ float W2_sh[32][128];
    __shared__ float A_sh[8][32][8];
    int tid = threadIdx.x;
    int w = tid >> 5, lane = tid & 31;
    int row0 = blockIdx.x * 64 + w * 8;

    ull acc1[4][4], acc2[4][4];
#pragma unroll
    for (int jp = 0; jp < 4; jp++)
#pragma unroll
        for (int c = 0; c < 4; c++) { acc1[jp][c] = 0ULL; acc2[jp][c] = 0ULL; }

    for (int kc = 0; kc < 4; kc++) {
        const float4* W1v = (const float4*)(W1 + kc * 32 * 128);
        const float4* W2v = (const float4*)(W2 + kc * 32 * 128);
        float4* W1s = (float4*)&W1_sh[0][0];
        float4* W2s = (float4*)&W2_sh[0][0];
        for (int i = tid; i < 32 * 128 / 4; i += 256) { W1s[i] = W1v[i]; W2s[i] = W2v[i]; }
        int r = lane >> 2;
        int ko = (lane & 3) * 8;
        int grow = row0 + r;
        float4 a0 = make_float4(0, 0, 0, 0), a1 = a0;
        if (grow < M) {
            a0 = *(const float4*)(A + (size_t)grow * 128 + kc * 32 + ko);
            a1 = *(const float4*)(A + (size_t)grow * 128 + kc * 32 + ko + 4);
        }
        A_sh[w][ko + 0][r] = a0.x; A_sh[w][ko + 1][r] = a0.y;
        A_sh[w][ko + 2][r] = a0.z; A_sh[w][ko + 3][r] = a0.w;
        A_sh[w][ko + 4][r] = a1.x; A_sh[w][ko + 5][r] = a1.y;
        A_sh[w][ko + 6][r] = a1.z; A_sh[w][ko + 7][r] = a1.w;
        __syncthreads();
#pragma unroll
        for (int k = 0; k < 32; k++) {
            ulonglong2 apA = *(const ulonglong2*)&A_sh[w][k][0];
            ulonglong2 apB = *(const ulonglong2*)&A_sh[w][k][4];
            float4 w1 = *(const float4*)&W1_sh[k][4 * lane];
            float4 w2 = *(const float4*)&W2_sh[k][4 * lane];
            ull u10, u11, u12, u13, u20, u21, u22, u23;
            DUP2(u10, w1.x); DUP2(u11, w1.y); DUP2(u12, w1.z); DUP2(u13, w1.w);
            DUP2(u20, w2.x); DUP2(u21, w2.y); DUP2(u22, w2.z); DUP2(u23, w2.w);
            ull ap[4] = {apA.x, apA.y, apB.x, apB.y};
#pragma unroll
            for (int jp = 0; jp < 4; jp++) {
                FFMA2(acc1[jp][0], ap[jp], u10);
                FFMA2(acc1[jp][1], ap[jp], u11);
                FFMA2(acc1[jp][2], ap[jp], u12);
                FFMA2(acc1[jp][3], ap[jp], u13);
                FFMA2(acc2[jp][0], ap[jp], u20);
                FFMA2(acc2[jp][1], ap[jp], u21);
                FFMA2(acc2[jp][2], ap[jp], u22);
                FFMA2(acc2[jp][3], ap[jp], u23);
            }
        }
        __syncthreads();
    }
    float4 bz1 = *(const float4*)(b1 + 4 * lane);
    float4 bz2 = *(const float4*)(b2 + 4 * lane);
#pragma unroll
    for (int jp = 0; jp < 4; jp++) {
        float lo[4], hi[4], lo2[4], hi2[4];
#pragma unroll
        for (int c = 0; c < 4; c++) { UNPK2(lo[c], hi[c], acc1[jp][c]); UNPK2(lo2[c], hi2[c], acc2[jp][c]); }
        int r0 = row0 + 2 * jp, r1 = r0 + 1;
        if (r0 < M) {
            *(float4*)(out1 + (size_t)r0 * 128 + 4 * lane) =
                make_float4(lo[0] + bz1.x, lo[1] + bz1.y, lo[2] + bz1.z, lo[3] + bz1.w);
            *(float4*)(out2 + (size_t)r0 * 128 + 4 * lane) =
                make_float4(lo2[0] + bz2.x, lo2[1] + bz2.y, lo2[2] + bz2.z, lo2[3] + bz2.w);
        }
        if (r1 < M) {
            *(float4*)(out1 + (size_t)r1 * 128 + 4 * lane) =
                make_float4(hi[0] + bz1.x, hi[1] + bz1.y, hi[2] + bz1.z, hi[3] + bz1.w);
            *(float4*)(out2 + (size_t)r1 * 128 + 4 * lane) =
                make_float4(hi2[0] + bz2.x, hi2[1] + bz2.y, hi2[2] + bz2.z, hi2[3] + bz2.w);
        }
    }
}

// ---------------- fused attention: warp per dst node -----------------------
__global__ __launch_bounds__(256) void k_attn(const float* __restrict__ edge_attr,
                                              const float* __restrict__ We,
                                              const float* __restrict__ att,
                                              const float* __restrict__ cb) {
    __shared__ float4 We_sh[EDIM * 32];   // [k][lane] = We[k][4*lane..+3]
    __shared__ float4 att_sh[32];
    int tid = threadIdx.x;
    for (int i = tid; i < EDIM * 32; i += 256) We_sh[i] = ((const float4*)We)[i];
    if (tid < 32) att_sh[tid] = ((const float4*)att)[tid];
    __syncthreads();

    int lane = tid & 31;
    int n = blockIdx.x * 8 + (tid >> 5);
    if (n >= NN) return;
    int beg = g_rowptr[n], end = g_rowptr[n + 1];
    int h = lane >> 3;  // this lane's 4 channels (4*lane..+3) belong to head h

    float4 xr4 = *(const float4*)(g_xr + (size_t)n * DD + 4 * lane);
    float4 at  = att_sh[lane];
    ull xrp0, xrp1;
    PACK2(xrp0, xr4.x, xr4.y);
    PACK2(xrp1, xr4.z, xr4.w);

    // ---- pass 1: logits + per-head max ----
    float mxh = -1e30f;
    for (int i = beg; i < end; i++) {
        int2 cs = g_csr[i];
        const float* ea = (cs.y < EE) ? (edge_attr + (size_t)cs.y * EDIM)
                                      : (g_loop_attr + (size_t)n * EDIM);
        float myea = (lane < EDIM) ? ea[lane] : 0.f;
        ull ee0 = 0ULL, ee1 = 0ULL;
#pragma unroll
        for (int k = 0; k < EDIM; k++) {
            float a = __shfl_sync(0xffffffffu, myea, k);
            ull ad; DUP2(ad, a);
            ulonglong2 wp = *(const ulonglong2*)&We_sh[k * 32 + lane];
            FFMA2(ee0, ad, wp.x);
            FFMA2(ee1, ad, wp.y);
        }
        float4 xlv = *(const float4*)(g_xl + (size_t)cs.x * DD + 4 * lane);
        ull xlp0, xlp1;
        PACK2(xlp0, xlv.x, xlv.y);
        PACK2(xlp1, xlv.z, xlv.w);
        ull m0p, m1p;
        FADD2(m0p, xlp0, xrp0); FADD2(m0p, m0p, ee0);
        FADD2(m1p, xlp1, xrp1); FADD2(m1p, m1p, ee1);
        float4 m;
        UNPK2(m.x, m.y, m0p);
        UNPK2(m.z, m.w, m1p);
        m.x = (m.x > 0.f) ? m.x : NEG_SLOPE * m.x;
        m.y = (m.y > 0.f) ? m.y : NEG_SLOPE * m.y;
        m.z = (m.z > 0.f) ? m.z : NEG_SLOPE * m.z;
        m.w = (m.w > 0.f) ? m.w : NEG_SLOPE * m.w;
        float p = m.x * at.x + m.y * at.y + m.z * at.z + m.w * at.w;
        p += __shfl_xor_sync(0xffffffffu, p, 1);
        p += __shfl_xor_sync(0xffffffffu, p, 2);
        p += __shfl_xor_sync(0xffffffffu, p, 4);   // all 8 lanes of head hold logit
        mxh = fmaxf(mxh, p);
        if ((lane & 7) == 0) g_logit[(size_t)cs.y * 4 + h] = p;
    }
    __syncwarp();

    // ---- pass 2: weighted gather + denominator (unnormalized) ----
    float4 acc = make_float4(0, 0, 0, 0);
    float den = 0.f;
    for (int i = beg; i < end; i++) {
        int2 cs = g_csr[i];
        float lg = g_logit[(size_t)cs.y * 4 + h];
        float a = __expf(lg - mxh);
        den += a;
        float4 xv = *(const float4*)(g_xl + (size_t)cs.x * DD + 4 * lane);
        acc.x += a * xv.x; acc.y += a * xv.y; acc.z += a * xv.z; acc.w += a * xv.w;
    }
    float inv = 1.f / den;
    float4 cbv = *(const float4*)(cb + 4 * lane);
    float4 o;
    o.x = acc.x * inv + cbv.x;
    o.y = acc.y * inv + cbv.y;
    o.z = acc.z * inv + cbv.z;
    o.w = acc.w * inv + cbv.w;
    o.x = (o.x > 0.f) ? o.x : expm1f(o.x);
    o.y = (o.y > 0.f) ? o.y : expm1f(o.y);
    o.z = (o.z > 0.f) ? o.z : expm1f(o.z);
    o.w = (o.w > 0.f) ? o.w : expm1f(o.w);
    *(float4*)(g_h + (size_t)n * DD + 4 * lane) = o;
}

// ---------------- final: LN + MLP head, warp per row -----------------------
__global__ __launch_bounds__(256) void k_final(const float* __restrict__ ln_g,
                                               const float* __restrict__ ln_b,
                                               const float* __restrict__ h1w,
                                               const float* __restrict__ h1b,
                                               const float* __restrict__ h2w,
                                               const float* __restrict__ h2b,
                                               float* __restrict__ out) {
    __shared__ float W1[128 * 64];   // 32 KB
    __shared__ float W2[64 * 3];
    __shared__ float rowbuf[8][128];
    int tid = threadIdx.x;
    for (int i = tid; i < 128 * 64; i += 256) W1[i] = h1w[i];
    if (tid < 64 * 3) W2[tid] = h2w[tid];
    __syncthreads();

    int lane = tid & 31, w = tid >> 5;
    int n = blockIdx.x * 8 + w;
    if (n >= NN) return;

    float4 hv = *(const float4*)(g_h + (size_t)n * DD + 4 * lane);
    float s = hv.x + hv.y + hv.z + hv.w;
#pragma unroll
    for (int off = 16; off > 0; off >>= 1) s += __shfl_xor_sync(0xffffffffu, s, off);
    float mu = s / 128.f;
    float4 dm = make_float4(hv.x - mu, hv.y - mu, hv.z - mu, hv.w - mu);
    float v = dm.x * dm.x + dm.y * dm.y + dm.z * dm.z + dm.w * dm.w;
#pragma unroll
    for (int off = 16; off > 0; off >>= 1) v += __shfl_xor_sync(0xffffffffu, v, off);
    float r = rsqrtf(v / 128.f + 1e-5f);
    float4 g4 = *(const float4*)(ln_g + 4 * lane);
    float4 b4 = *(const float4*)(ln_b + 4 * lane);
    float4 hn;
    hn.x = dm.x * r * g4.x + b4.x;
    hn.y = dm.y * r * g4.y + b4.y;
    hn.z = dm.z * r * g4.z + b4.z;
    hn.w = dm.w * r * g4.w + b4.w;
    *(float4*)&rowbuf[w][4 * lane] = hn;
    __syncwarp();

    float m0 = h1b[lane], m1 = h1b[lane + 32];
#pragma unroll 4
    for (int k = 0; k < 128; k++) {
        float a = rowbuf[w][k];
        m0 += a * W1[k * 64 + lane];
        m1 += a * W1[k * 64 + lane + 32];
    }
    m0 = fmaxf(m0, 0.f);
    m1 = fmaxf(m1, 0.f);
    float p0 = m0 * W2[lane * 3 + 0] + m1 * W2[(lane + 32) * 3 + 0];
    float p1 = m0 * W2[lane * 3 + 1] + m1 * W2[(lane + 32) * 3 + 1];
    float p2 = m0 * W2[lane * 3 + 2] + m1 * W2[(lane + 32) * 3 + 2];
#pragma unroll
    for (int off = 16; off > 0; off >>= 1) {
        p0 += __shfl_xor_sync(0xffffffffu, p0, off);
        p1 += __shfl_xor_sync(0xffffffffu, p1, off);
        p2 += __shfl_xor_sync(0xffffffffu, p2, off);
    }
    if (lane == 0) {
        out[(size_t)n * 3 + 0] = p0 + h2b[0];
        out[(size_t)n * 3 + 1] = p1 + h2b[1];
        out[(size_t)n * 3 + 2] = p2 + h2b[2];
    }
}

// ---------------- host launcher -------------------------------------------
extern "C" void kernel_launch(void* const* d_in, const int* in_sizes, int n_in,
                              void* d_out, int out_size) {
    const float* x         = (const float*)d_in[0];
    const int*   ei_raw    = (const int*)d_in[1];    // int32 OR int64 (detected)
    const float* edge_attr = (const float*)d_in[2];
    const float* in_w      = (const float*)d_in[3];
    const float* in_b      = (const float*)d_in[4];
    const float* Wl        = (const float*)d_in[5];
    const float* bl        = (const float*)d_in[6];
    const float* Wr        = (const float*)d_in[7];
    const float* br        = (const float*)d_in[8];
    const float* We        = (const float*)d_in[9];
    const float* att       = (const float*)d_in[10];
    const float* cb        = (const float*)d_in[11];
    const float* ln_g      = (const float*)d_in[12];
    const float* ln_b      = (const float*)d_in[13];
    const float* h1w       = (const float*)d_in[14];
    const float* h1b       = (const float*)d_in[15];
    const float* h2w       = (const float*)d_in[16];
    const float* h2b       = (const float*)d_in[17];

    float *hp, *xlp, *xrp;
    cudaGetSymbolAddress((void**)&hp,  g_h);
    cudaGetSymbolAddress((void**)&xlp, g_xl);
    cudaGetSymbolAddress((void**)&xrp, g_xr);

    // preprocessing: zero+detect, cvt+deg, scan, scatter, loop_attr
    k_zero<<<(NN + 255) / 256, 256>>>(ei_raw);
    k_cvt_deg<<<(2 * EE + 255) / 256, 256>>>(ei_raw);
    k_scan<<<1, 1024>>>();
    k_scatter<<<(ETOT + 255) / 256, 256>>>();
    k_loopattr<<<(NN * 16 + 255) / 256, 256>>>(edge_attr);

    // input projection
    k_gemm1<<<(NN + 63) / 64, 256>>>(x, in_w, in_b, hp, NN);

    for (int l = 0; l < 2; l++) {
        const float* Wl_l  = Wl + l * 128 * 128;
        const float* Wr_l  = Wr + l * 128 * 128;
        const float* bl_l  = bl + l * 128;
        const float* br_l  = br + l * 128;
        const float* We_l  = We + l * EDIM * 128;
        const float* att_l = att + l * 128;
        const float* cb_l  = cb + l * 128;

        k_gemm2<<<(NN + 63) / 64, 256>>>(hp, Wl_l, bl_l, Wr_l, br_l, xlp, xrp, NN);
        k_attn<<<(NN + 7) / 8, 256>>>(edge_attr, We_l, att_l, cb_l);
    }

    k_final<<<(NN + 7) / 8, 256>>>(ln_g, ln_b, h1w, h1b, h2w, h2b, (float*)d_out);
}

// round 9
// speedup vs baseline: 1.3584x; 1.0906x over previous
#include <cuda_runtime.h>
#include <math.h>

#define NN    50000
#define EE    600000
#define ETOT  (EE + NN)
#define DD    128
#define EDIM  16
#define NEG_SLOPE 0.2f

typedef unsigned long long ull;

// packed f32x2 ops (sm_100+; ptxas never auto-fuses these)
#define FFMA2(d, a, b) asm("fma.rn.f32x2 %0, %1, %2, %0;" : "+l"(d) : "l"(a), "l"(b))
#define FADD2(d, a, b) asm("add.rn.f32x2 %0, %1, %2;" : "=l"(d) : "l"(a), "l"(b))
#define DUP2(d, s)     asm("mov.b64 %0, {%1, %1};" : "=l"(d) : "f"(s))
#define PACK2(d, lo, hi) asm("mov.b64 %0, {%1, %2};" : "=l"(d) : "f"(lo), "f"(hi))
#define UNPK2(lo, hi, p) asm("mov.b64 {%0, %1}, %2;" : "=f"(lo), "=f"(hi) : "l"(p))

// ---------------- scratch (static device globals; no allocs allowed) -------
__device__ __align__(16) float g_h[NN * DD];
__device__ __align__(16) float g_xl[NN * DD];
__device__ __align__(16) float g_xr[NN * DD];
__device__ int   g_src[EE];
__device__ int   g_dst[EE];
__device__ int   g_deg[NN];
__device__ int   g_fill[NN];
__device__ int   g_rowptr[NN + 1];
__device__ int2  g_csr[ETOT];   // .x = src node, .y = edge id (eid>=EE -> self loop, LAST in bucket)
__device__ int   g_is64;

// ---------------- zero + index dtype detection -----------------------------
__global__ void k_zero(const int* __restrict__ ei_raw) {
    int i = blockIdx.x * blockDim.x + threadIdx.x;
    if (i < NN) { g_deg[i] = 0; g_fill[i] = 0; }
    if (i == 0) {
        int all0 = 1;
        for (int t = 0; t < 64; t++)
            if (ei_raw[2 * t + 1] != 0) { all0 = 0; break; }
        g_is64 = all0;
    }
}

// convert indices to int32 AND build degree histogram in one pass
__global__ void k_cvt_deg(const int* __restrict__ ei_raw) {
    int i = blockIdx.x * blockDim.x + threadIdx.x;
    if (i >= 2 * EE) return;
    int v = g_is64 ? ei_raw[2 * i] : ei_raw[i];
    if (i < EE) {
        g_src[i] = v;
    } else {
        g_dst[i - EE] = v;
        atomicAdd(&g_deg[v], 1);
    }
}

// single-block scan of (deg+1) -> rowptr; 4 elems/thread, shfl warp scans
__global__ __launch_bounds__(1024) void k_scan() {
    __shared__ int warp_tot[32];
    __shared__ int s_carry;
    int tid = threadIdx.x, lane = tid & 31, wid = tid >> 5;
    if (tid == 0) { s_carry = 0; g_rowptr[0] = 0; }
    __syncthreads();
    for (int base = 0; base < NN; base += 4096) {
        int idx0 = base + tid * 4;
        int v[4], s = 0;
#pragma unroll
        for (int t = 0; t < 4; t++) {
            int i = idx0 + t;
            v[t] = (i < NN) ? (g_deg[i] + 1) : 0;
            s += v[t];
        }
        int ss = s;
#pragma unroll
        for (int off = 1; off < 32; off <<= 1) {
            int t = __shfl_up_sync(0xffffffffu, ss, off);
            if (lane >= off) ss += t;
        }
        if (lane == 31) warp_tot[wid] = ss;
        __syncthreads();
        if (wid == 0) {
            int wv = warp_tot[lane];
#pragma unroll
            for (int off = 1; off < 32; off <<= 1) {
                int t = __shfl_up_sync(0xffffffffu, wv, off);
                if (lane >= off) wv += t;
            }
            warp_tot[lane] = wv;   // inclusive warp totals
        }
        __syncthreads();
        int warp_prefix = (wid == 0) ? 0 : warp_tot[wid - 1];
        int run = s_carry + warp_prefix + (ss - s);
#pragma unroll
        for (int t = 0; t < 4; t++) {
            run += v[t];
            if (idx0 + t < NN) g_rowptr[idx0 + t + 1] = run;
        }
        __syncthreads();
        if (tid == 0) s_carry += warp_tot[31];
        __syncthreads();
    }
}

__global__ void k_scatter() {
    int i = blockIdx.x * blockDim.x + threadIdx.x;
    if (i < EE) {
        int d = g_dst[i];
        int p = atomicAdd(&g_fill[d], 1);
        g_csr[g_rowptr[d] + p] = make_int2(g_src[i], i);
    } else if (i < ETOT) {
        int n = i - EE;
        g_csr[g_rowptr[n] + g_deg[n]] = make_int2(n, EE + n);  // self loop LAST
    }
}

// ---------------- SGEMM single (f32x2): out = A@W + b ----------------------
__global__ __launch_bounds__(256) void k_gemm1(const float* __restrict__ A,
                                               const float* __restrict__ W,
                                               const float* __restrict__ bias,
                                               float* __restrict__ out, int M) {
    __shared__ float W_sh[32][128];     // 16 KB
    __shared__ float A_sh[8][32][8];    // 8 KB  [warp][k][row]
    int tid = threadIdx.x;
    int w = tid >> 5, lane = tid & 31;
    int row0 = blockIdx.x * 64 + w * 8;

    ull acc[4][4];                      // [row-pair][col]
#pragma unroll
    for (int jp = 0; jp < 4; jp++)
#pragma unroll
        for (int c = 0; c < 4; c++) acc[jp][c] = 0ULL;

    for (int kc = 0; kc < 4; kc++) {
        const float4* Wv = (const float4*)(W + kc * 32 * 128);
        float4* Wsv = (float4*)&W_sh[0][0];
        for (int i = tid; i < 32 * 128 / 4; i += 256) Wsv[i] = Wv[i];
        int r = lane >> 2;
        int ko = (lane & 3) * 8;
        int grow = row0 + r;
        float4 a0 = make_float4(0, 0, 0, 0), a1 = a0;
        if (grow < M) {
            a0 = *(const float4*)(A + (size_t)grow * 128 + kc * 32 + ko);
            a1 = *(const float4*)(A + (size_t)grow * 128 + kc * 32 + ko + 4);
        }
        A_sh[w][ko + 0][r] = a0.x; A_sh[w][ko + 1][r] = a0.y;
        A_sh[w][ko + 2][r] = a0.z; A_sh[w][ko + 3][r] = a0.w;
        A_sh[w][ko + 4][r] = a1.x; A_sh[w][ko + 5][r] = a1.y;
        A_sh[w][ko + 6][r] = a1.z; A_sh[w][ko + 7][r] = a1.w;
        __syncthreads();
#pragma unroll
        for (int k = 0; k < 32; k++) {
            ulonglong2 apA = *(const ulonglong2*)&A_sh[w][k][0];
            ulonglong2 apB = *(const ulonglong2*)&A_sh[w][k][4];
            float4 wv = *(const float4*)&W_sh[k][4 * lane];
            ull wd0, wd1, wd2, wd3;
            DUP2(wd0, wv.x); DUP2(wd1, wv.y); DUP2(wd2, wv.z); DUP2(wd3, wv.w);
            ull ap[4] = {apA.x, apA.y, apB.x, apB.y};
#pragma unroll
            for (int jp = 0; jp < 4; jp++) {
                FFMA2(acc[jp][0], ap[jp], wd0);
                FFMA2(acc[jp][1], ap[jp], wd1);
                FFMA2(acc[jp][2], ap[jp], wd2);
                FFMA2(acc[jp][3], ap[jp], wd3);
            }
        }
        __syncthreads();
    }
    float4 bz = *(const float4*)(bias + 4 * lane);
#pragma unroll
    for (int jp = 0; jp < 4; jp++) {
        float lo[4], hi[4];
#pragma unroll
        for (int c = 0; c < 4; c++) UNPK2(lo[c], hi[c], acc[jp][c]);
        int r0 = row0 + 2 * jp, r1 = r0 + 1;
        if (r0 < M)
            *(float4*)(out + (size_t)r0 * 128 + 4 * lane) =
                make_float4(lo[0] + bz.x, lo[1] + bz.y, lo[2] + bz.z, lo[3] + bz.w);
        if (r1 < M)
            *(float4*)(out + (size_t)r1 * 128 + 4 * lane) =
                make_float4(hi[0] + bz.x, hi[1] + bz.y, hi[2] + bz.z, hi[3] + bz.w);
    }
}

// ---------------- SGEMM dual (f32x2): xl = A@W1+b1, xr = A@W2+b2 -----------
__global__ __launch_bounds__(256) void k_gemm2(const float* __restrict__ A,
                                               const float* __restrict__ W1,
                                               const float* __restrict__ b1,
                                               const float* __restrict__ W2,
                                               const float* __restrict__ b2,
                                               float* __restrict__ out1,
                                               float* __restrict__ out2, int M) {
    __shared__ float W1_sh[32][128];
    __shared__ float W2_sh[32][128];
    __shared__ float A_sh[8][32][8];
    int tid = threadIdx.x;
    int w = tid >> 5, lane = tid & 31;
    int row0 = blockIdx.x * 64 + w * 8;

    ull acc1[4][4], acc2[4][4];
#pragma unroll
    for (int jp = 0; jp < 4; jp++)
#pragma unroll
        for (int c = 0; c < 4; c++) { acc1[jp][c] = 0ULL; acc2[jp][c] = 0ULL; }

    for (int kc = 0; kc < 4; kc++) {
        const float4* W1v = (const float4*)(W1 + kc * 32 * 128);
        const float4* W2v = (const float4*)(W2 + kc * 32 * 128);
        float4* W1s = (float4*)&W1_sh[0][0];
        float4* W2s = (float4*)&W2_sh[0][0];
        for (int i = tid; i < 32 * 128 / 4; i += 256) { W1s[i] = W1v[i]; W2s[i] = W2v[i]; }
        int r = lane >> 2;
        int ko = (lane & 3) * 8;
        int grow = row0 + r;
        float4 a0 = make_float4(0, 0, 0, 0), a1 = a0;
        if (grow < M) {
            a0 = *(const float4*)(A + (size_t)grow * 128 + kc * 32 + ko);
            a1 = *(const float4*)(A + (size_t)grow * 128 + kc * 32 + ko + 4);
        }
        A_sh[w][ko + 0][r] = a0.x; A_sh[w][ko + 1][r] = a0.y;
        A_sh[w][ko + 2][r] = a0.z; A_sh[w][ko + 3][r] = a0.w;
        A_sh[w][ko + 4][r] = a1.x; A_sh[w][ko + 5][r] = a1.y;
        A_sh[w][ko + 6][r] = a1.z; A_sh[w][ko + 7][r] = a1.w;
        __syncthreads();
#pragma unroll
        for (int k = 0; k < 32; k++) {
            ulonglong2 apA = *(const ulonglong2*)&A_sh[w][k][0];
            ulonglong2 apB = *(const ulonglong2*)&A_sh[w][k][4];
            float4 w1 = *(const float4*)&W1_sh[k][4 * lane];
            float4 w2 = *(const float4*)&W2_sh[k][4 * lane];
            ull u10, u11, u12, u13, u20, u21, u22, u23;
            DUP2(u10, w1.x); DUP2(u11, w1.y); DUP2(u12, w1.z); DUP2(u13, w1.w);
            DUP2(u20, w2.x); DUP2(u21, w2.y); DUP2(u22, w2.z); DUP2(u23, w2.w);
            ull ap[4] = {apA.x, apA.y, apB.x, apB.y};
#pragma unroll
            for (int jp = 0; jp < 4; jp++) {
                FFMA2(acc1[jp][0], ap[jp], u10);
                FFMA2(acc1[jp][1], ap[jp], u11);
                FFMA2(acc1[jp][2], ap[jp], u12);
                FFMA2(acc1[jp][3], ap[jp], u13);
                FFMA2(acc2[jp][0], ap[jp], u20);
                FFMA2(acc2[jp][1], ap[jp], u21);
                FFMA2(acc2[jp][2], ap[jp], u22);
                FFMA2(acc2[jp][3], ap[jp], u23);
            }
        }
        __syncthreads();
    }
    float4 bz1 = *(const float4*)(b1 + 4 * lane);
    float4 bz2 = *(const float4*)(b2 + 4 * lane);
#pragma unroll
    for (int jp = 0; jp < 4; jp++) {
        float lo[4], hi[4], lo2[4], hi2[4];
#pragma unroll
        for (int c = 0; c < 4; c++) { UNPK2(lo[c], hi[c], acc1[jp][c]); UNPK2(lo2[c], hi2[c], acc2[jp][c]); }
        int r0 = row0 + 2 * jp, r1 = r0 + 1;
        if (r0 < M) {
            *(float4*)(out1 + (size_t)r0 * 128 + 4 * lane) =
                make_float4(lo[0] + bz1.x, lo[1] + bz1.y, lo[2] + bz1.z, lo[3] + bz1.w);
            *(float4*)(out2 + (size_t)r0 * 128 + 4 * lane) =
                make_float4(lo2[0] + bz2.x, lo2[1] + bz2.y, lo2[2] + bz2.z, lo2[3] + bz2.w);
        }
        if (r1 < M) {
            *(float4*)(out1 + (size_t)r1 * 128 + 4 * lane) =
                make_float4(hi[0] + bz1.x, hi[1] + bz1.y, hi[2] + bz1.z, hi[3] + bz1.w);
            *(float4*)(out2 + (size_t)r1 * 128 + 4 * lane) =
                make_float4(hi2[0] + bz2.x, hi2[1] + bz2.y, hi2[2] + bz2.z, hi2[3] + bz2.w);
        }
    }
}

// ---------------- fused attention: ONE edge sweep, online softmax ----------
// warp per dst node. Self loop is the LAST csr entry of each node; its
// edge_attr (mean of incoming) is accumulated on the fly -> no loop_attr
// array, no logit array, no second gather pass.
__global__ __launch_bounds__(256) void k_attn(const float* __restrict__ edge_attr,
                                              const float* __restrict__ We,
                                              const float* __restrict__ att,
                                              const float* __restrict__ cb) {
    __shared__ float4 We_sh[EDIM * 32];   // [k][lane] = We[k][4*lane..+3]
    __shared__ float4 att_sh[32];
    int tid = threadIdx.x;
    for (int i = tid; i < EDIM * 32; i += 256) We_sh[i] = ((const float4*)We)[i];
    if (tid < 32) att_sh[tid] = ((const float4*)att)[tid];
    __syncthreads();

    int lane = tid & 31;
    int n = blockIdx.x * 8 + (tid >> 5);
    if (n >= NN) return;
    int beg = g_rowptr[n], end = g_rowptr[n + 1];
    int dg = end - beg - 1;               // real incoming edges (excl self loop)
    float inv_deg = 1.f / (float)max(dg, 1);

    float4 xr4 = *(const float4*)(g_xr + (size_t)n * DD + 4 * lane);
    float4 at  = att_sh[lane];
    ull xrp0, xrp1;
    PACK2(xrp0, xr4.x, xr4.y);
    PACK2(xrp1, xr4.z, xr4.w);

    float mxh = -1e30f, den = 0.f;
    float4 acc = make_float4(0, 0, 0, 0);
    float ea_sum = 0.f;

    for (int i = beg; i < end; i++) {
        int2 cs = g_csr[i];
        float myea;
        if (i < end - 1) {                // real edge
            myea = (lane < EDIM) ? edge_attr[(size_t)cs.y * EDIM + lane] : 0.f;
            ea_sum += myea;
        } else {                          // self loop: mean of incoming attrs
            myea = ea_sum * inv_deg;
        }
        ull ee0 = 0ULL, ee1 = 0ULL;
#pragma unroll
        for (int k = 0; k < EDIM; k++) {
            float a = __shfl_sync(0xffffffffu, myea, k);
            ull ad; DUP2(ad, a);
            ulonglong2 wp = *(const ulonglong2*)&We_sh[k * 32 + lane];
            FFMA2(ee0, ad, wp.x);
            FFMA2(ee1, ad, wp.y);
        }
        float4 xlv = *(const float4*)(g_xl + (size_t)cs.x * DD + 4 * lane);
        ull xlp0, xlp1;
        PACK2(xlp0, xlv.x, xlv.y);
        PACK2(xlp1, xlv.z, xlv.w);
        ull m0p, m1p;
        FADD2(m0p, xlp0, xrp0); FADD2(m0p, m0p, ee0);
        FADD2(m1p, xlp1, xrp1); FADD2(m1p, m1p, ee1);
        float4 m;
        UNPK2(m.x, m.y, m0p);
        UNPK2(m.z, m.w, m1p);
        m.x = (m.x > 0.f) ? m.x : NEG_SLOPE * m.x;
        m.y = (m.y > 0.f) ? m.y : NEG_SLOPE * m.y;
        m.z = (m.z > 0.f) ? m.z : NEG_SLOPE * m.z;
        m.w = (m.w > 0.f) ? m.w : NEG_SLOPE * m.w;
        float p = m.x * at.x + m.y * at.y + m.z * at.z + m.w * at.w;
        p += __shfl_xor_sync(0xffffffffu, p, 1);
        p += __shfl_xor_sync(0xffffffffu, p, 2);
        p += __shfl_xor_sync(0xffffffffu, p, 4);   // 8 lanes of head hold logit

        // online softmax update
        float newmx = fmaxf(mxh, p);
        float s = __expf(mxh - newmx);            // 1 if no update; 0 on first iter
        float a = __expf(p - newmx);
        mxh = newmx;
        den = fmaf(den, s, a);
        acc.x = fmaf(acc.x, s, a * xlv.x);
        acc.y = fmaf(acc.y, s, a * xlv.y);
        acc.z = fmaf(acc.z, s, a * xlv.z);
        acc.w = fmaf(acc.w, s, a * xlv.w);
    }

    float inv = 1.f / den;
    float4 cbv = *(const float4*)(cb + 4 * lane);
    float4 o;
    o.x = acc.x * inv + cbv.x;
    o.y = acc.y * inv + cbv.y;
    o.z = acc.z * inv + cbv.z;
    o.w = acc.w * inv + cbv.w;
    o.x = (o.x > 0.f) ? o.x : expm1f(o.x);
    o.y = (o.y > 0.f) ? o.y : expm1f(o.y);
    o.z = (o.z > 0.f) ? o.z : expm1f(o.z);
    o.w = (o.w > 0.f) ? o.w : expm1f(o.w);
    *(float4*)(g_h + (size_t)n * DD + 4 * lane) = o;
}

// ---------------- final: LN + MLP head, warp per row -----------------------
__global__ __launch_bounds__(256) void k_final(const float* __restrict__ ln_g,
                                               const float* __restrict__ ln_b,
                                               const float* __restrict__ h1w,
                                               const float* __restrict__ h1b,
                                               const float* __restrict__ h2w,
                                               const float* __restrict__ h2b,
                                               float* __restrict__ out) {
    __shared__ ull  W1p[128 * 32];   // 32 KB: [k][lane] = (W1[k][lane], W1[k][lane+32])
    __shared__ float W2[64 * 3];
    __shared__ float rowbuf[8][128];
    int tid = threadIdx.x;
    for (int idx = tid; idx < 128 * 32; idx += 256) {
        int k = idx >> 5, c = idx & 31;
        ull p; PACK2(p, h1w[k * 64 + c], h1w[k * 64 + c + 32]);
        W1p[idx] = p;
    }
    if (tid < 64 * 3) W2[tid] = h2w[tid];
    __syncthreads();

    int lane = tid & 31, w = tid >> 5;
    int n = blockIdx.x * 8 + w;
    if (n >= NN) return;

    float4 hv = *(const float4*)(g_h + (size_t)n * DD + 4 * lane);
    float s = hv.x + hv.y + hv.z + hv.w;
#pragma unroll
    for (int off = 16; off > 0; off >>= 1) s += __shfl_xor_sync(0xffffffffu, s, off);
    float mu = s / 128.f;
    float4 dm = make_float4(hv.x - mu, hv.y - mu, hv.z - mu, hv.w - mu);
    float v = dm.x * dm.x + dm.y * dm.y + dm.z * dm.z + dm.w * dm.w;
#pragma unroll
    for (int off = 16; off > 0; off >>= 1) v += __shfl_xor_sync(0xffffffffu, v, off);
    float r = rsqrtf(v / 128.f + 1e-5f);
    float4 g4 = *(const float4*)(ln_g + 4 * lane);
    float4 b4 = *(const float4*)(ln_b + 4 * lane);
    float4 hn;
    hn.x = dm.x * r * g4.x + b4.x;
    hn.y = dm.y * r * g4.y + b4.y;
    hn.z = dm.z * r * g4.z + b4.z;
    hn.w = dm.w * r * g4.w + b4.w;
    *(float4*)&rowbuf[w][4 * lane] = hn;
    __syncwarp();

    ull m01;
    PACK2(m01, h1b[lane], h1b[lane + 32]);
#pragma unroll 8
    for (int k = 0; k < 128; k++) {
        float a = rowbuf[w][k];
        ull ad; DUP2(ad, a);
        FFMA2(m01, ad, W1p[k * 32 + lane]);
    }
    float m0, m1;
    UNPK2(m0, m1, m01);
    m0 = fmaxf(m0, 0.f);
    m1 = fmaxf(m1, 0.f);
    float p0 = m0 * W2[lane * 3 + 0] + m1 * W2[(lane + 32) * 3 + 0];
    float p1 = m0 * W2[lane * 3 + 1] + m1 * W2[(lane + 32) * 3 + 1];
    float p2 = m0 * W2[lane * 3 + 2] + m1 * W2[(lane + 32) * 3 + 2];
#pragma unroll
    for (int off = 16; off > 0; off >>= 1) {
        p0 += __shfl_xor_sync(0xffffffffu, p0, off);
        p1 += __shfl_xor_sync(0xffffffffu, p1, off);
        p2 += __shfl_xor_sync(0xffffffffu, p2, off);
    }
    if (lane == 0) {
        out[(size_t)n * 3 + 0] = p0 + h2b[0];
        out[(size_t)n * 3 + 1] = p1 + h2b[1];
        out[(size_t)n * 3 + 2] = p2 + h2b[2];
    }
}

// ---------------- host launcher -------------------------------------------
extern "C" void kernel_launch(void* const* d_in, const int* in_sizes, int n_in,
                              void* d_out, int out_size) {
    const float* x         = (const float*)d_in[0];
    const int*   ei_raw    = (const int*)d_in[1];    // int32 OR int64 (detected)
    const float* edge_attr = (const float*)d_in[2];
    const float* in_w      = (const float*)d_in[3];
    const float* in_b      = (const float*)d_in[4];
    const float* Wl        = (const float*)d_in[5];
    const float* bl        = (const float*)d_in[6];
    const float* Wr        = (const float*)d_in[7];
    const float* br        = (const float*)d_in[8];
    const float* We        = (const float*)d_in[9];
    const float* att       = (const float*)d_in[10];
    const float* cb        = (const float*)d_in[11];
    const float* ln_g      = (const float*)d_in[12];
    const float* ln_b      = (const float*)d_in[13];
    const float* h1w       = (const float*)d_in[14];
    const float* h1b       = (const float*)d_in[15];
    const float* h2w       = (const float*)d_in[16];
    const float* h2b       = (const float*)d_in[17];

    float *hp, *xlp, *xrp;
    cudaGetSymbolAddress((void**)&hp,  g_h);
    cudaGetSymbolAddress((void**)&xlp, g_xl);
    cudaGetSymbolAddress((void**)&xrp, g_xr);

    // preprocessing: zero+detect, cvt+deg, scan, scatter
    k_zero<<<(NN + 255) / 256, 256>>>(ei_raw);
    k_cvt_deg<<<(2 * EE + 255) / 256, 256>>>(ei_raw);
    k_scan<<<1, 1024>>>();
    k_scatter<<<(ETOT + 255) / 256, 256>>>();

    // input projection
    k_gemm1<<<(NN + 63) / 64, 256>>>(x, in_w, in_b, hp, NN);

    for (int l = 0; l < 2; l++) {
        const float* Wl_l  = Wl + l * 128 * 128;
        const float* Wr_l  = Wr + l * 128 * 128;
        const float* bl_l  = bl + l * 128;
        const float* br_l  = br + l * 128;
        const float* We_l  = We + l * EDIM * 128;
        const float* att_l = att + l * 128;
        const float* cb_l  = cb + l * 128;

        k_gemm2<<<(NN + 63) / 64, 256>>>(hp, Wl_l, bl_l, Wr_l, br_l, xlp, xrp, NN);
        k_attn<<<(NN + 7) / 8, 256>>>(edge_attr, We_l, att_l, cb_l);
    }

    k_final<<<(NN + 7) / 8, 256>>>(ln_g, ln_b, h1w, h1b, h2w, h2b, (float*)d_out);
}

// round 11
// speedup vs baseline: 1.4018x; 1.0319x over previous
#include <cuda_runtime.h>
#include <math.h>

#define NN    50000
#define EE    600000
#define ETOT  (EE + NN)
#define DD    128
#define EDIM  16
#define NEG_SLOPE 0.2f

typedef unsigned long long ull;

// packed f32x2 ops (sm_100+; ptxas never auto-fuses these)
#define FFMA2(d, a, b) asm("fma.rn.f32x2 %0, %1, %2, %0;" : "+l"(d) : "l"(a), "l"(b))
#define FADD2(d, a, b) asm("add.rn.f32x2 %0, %1, %2;" : "=l"(d) : "l"(a), "l"(b))
#define DUP2(d, s)     asm("mov.b64 %0, {%1, %1};" : "=l"(d) : "f"(s))
#define PACK2(d, lo, hi) asm("mov.b64 %0, {%1, %2};" : "=l"(d) : "f"(lo), "f"(hi))
#define UNPK2(lo, hi, p) asm("mov.b64 {%0, %1}, %2;" : "=f"(lo), "=f"(hi) : "l"(p))

// ---------------- scratch (static device globals; no allocs allowed) -------
__device__ __align__(16) float g_h[NN * DD];
__device__ __align__(16) float g_xl[NN * DD];
__device__ __align__(16) float g_xr[NN * DD];
__device__ int   g_src[EE];
__device__ int   g_dst[EE];
__device__ int   g_deg[NN];
__device__ int   g_fill[NN];
__device__ int   g_rowptr[NN + 1];
__device__ int2  g_csr[ETOT];   // .x = src node, .y = edge id (eid>=EE -> self loop, LAST in bucket)
__device__ int   g_is64;

// ---------------- zero + index dtype detection -----------------------------
__global__ void k_zero(const int* __restrict__ ei_raw) {
    int i = blockIdx.x * blockDim.x + threadIdx.x;
    if (i < NN) { g_deg[i] = 0; g_fill[i] = 0; }
    if (i == 0) {
        int all0 = 1;
        for (int t = 0; t < 64; t++)
            if (ei_raw[2 * t + 1] != 0) { all0 = 0; break; }
        g_is64 = all0;
    }
}

// convert indices to int32 AND build degree histogram in one pass
__global__ void k_cvt_deg(const int* __restrict__ ei_raw) {
    int i = blockIdx.x * blockDim.x + threadIdx.x;
    if (i >= 2 * EE) return;
    int v = g_is64 ? ei_raw[2 * i] : ei_raw[i];
    if (i < EE) {
        g_src[i] = v;
    } else {
        g_dst[i - EE] = v;
        atomicAdd(&g_deg[v], 1);
    }
}

// single-block scan of (deg+1) -> rowptr; 4 elems/thread, shfl warp scans
__global__ __launch_bounds__(1024) void k_scan() {
    __shared__ int warp_tot[32];
    __shared__ int s_carry;
    int tid = threadIdx.x, lane = tid & 31, wid = tid >> 5;
    if (tid == 0) { s_carry = 0; g_rowptr[0] = 0; }
    __syncthreads();
    for (int base = 0; base < NN; base += 4096) {
        int idx0 = base + tid * 4;
        int v[4], s = 0;
#pragma unroll
        for (int t = 0; t < 4; t++) {
            int i = idx0 + t;
            v[t] = (i < NN) ? (g_deg[i] + 1) : 0;
            s += v[t];
        }
        int ss = s;
#pragma unroll
        for (int off = 1; off < 32; off <<= 1) {
            int t = __shfl_up_sync(0xffffffffu, ss, off);
            if (lane >= off) ss += t;
        }
        if (lane == 31) warp_tot[wid] = ss;
        __syncthreads();
        if (wid == 0) {
            int wv = warp_tot[lane];
#pragma unroll
            for (int off = 1; off < 32; off <<= 1) {
                int t = __shfl_up_sync(0xffffffffu, wv, off);
                if (lane >= off) wv += t;
            }
            warp_tot[lane] = wv;   // inclusive warp totals
        }
        __syncthreads();
        int warp_prefix = (wid == 0) ? 0 : warp_tot[wid - 1];
        int run = s_carry + warp_prefix + (ss - s);
#pragma unroll
        for (int t = 0; t < 4; t++) {
            run += v[t];
            if (idx0 + t < NN) g_rowptr[idx0 + t + 1] = run;
        }
        __syncthreads();
        if (tid == 0) s_carry += warp_tot[31];
        __syncthreads();
    }
}

__global__ void k_scatter() {
    int i = blockIdx.x * blockDim.x + threadIdx.x;
    if (i < EE) {
        int d = g_dst[i];
        int p = atomicAdd(&g_fill[d], 1);
        g_csr[g_rowptr[d] + p] = make_int2(g_src[i], i);
    } else if (i < ETOT) {
        int n = i - EE;
        g_csr[g_rowptr[n] + g_deg[n]] = make_int2(n, EE + n);  // self loop LAST
    }
}

// ---------------- SGEMM single (f32x2): out = A@W + b ----------------------
__global__ __launch_bounds__(256) void k_gemm1(const float* __restrict__ A,
                                               const float* __restrict__ W,
                                               const float* __restrict__ bias,
                                               float* __restrict__ out, int M) {
    __shared__ float W_sh[32][128];     // 16 KB
    __shared__ float A_sh[8][32][8];    // 8 KB  [warp][k][row]
    int tid = threadIdx.x;
    int w = tid >> 5, lane = tid & 31;
    int row0 = blockIdx.x * 64 + w * 8;

    ull acc[4][4];                      // [row-pair][col]
#pragma unroll
    for (int jp = 0; jp < 4; jp++)
#pragma unroll
        for (int c = 0; c < 4; c++) acc[jp][c] = 0ULL;

    for (int kc = 0; kc < 4; kc++) {
        const float4* Wv = (const float4*)(W + kc * 32 * 128);
        float4* Wsv = (float4*)&W_sh[0][0];
        for (int i = tid; i < 32 * 128 / 4; i += 256) Wsv[i] = Wv[i];
        int r = lane >> 2;
        int ko = (lane & 3) * 8;
        int grow = row0 + r;
        float4 a0 = make_float4(0, 0, 0, 0), a1 = a0;
        if (grow < M) {
            a0 = *(const float4*)(A + (size_t)grow * 128 + kc * 32 + ko);
            a1 = *(const float4*)(A + (size_t)grow * 128 + kc * 32 + ko + 4);
        }
        A_sh[w][ko + 0][r] = a0.x; A_sh[w][ko + 1][r] = a0.y;
        A_sh[w][ko + 2][r] = a0.z; A_sh[w][ko + 3][r] = a0.w;
        A_sh[w][ko + 4][r] = a1.x; A_sh[w][ko + 5][r] = a1.y;
        A_sh[w][ko + 6][r] = a1.z; A_sh[w][ko + 7][r] = a1.w;
        __syncthreads();
#pragma unroll
        for (int k = 0; k < 32; k++) {
            ulonglong2 apA = *(const ulonglong2*)&A_sh[w][k][0];
            ulonglong2 apB = *(const ulonglong2*)&A_sh[w][k][4];
            float4 wv = *(const float4*)&W_sh[k][4 * lane];
            ull wd0, wd1, wd2, wd3;
            DUP2(wd0, wv.x); DUP2(wd1, wv.y); DUP2(wd2, wv.z); DUP2(wd3, wv.w);
            ull ap[4] = {apA.x, apA.y, apB.x, apB.y};
#pragma unroll
            for (int jp = 0; jp < 4; jp++) {
                FFMA2(acc[jp][0], ap[jp], wd0);
                FFMA2(acc[jp][1], ap[jp], wd1);
                FFMA2(acc[jp][2], ap[jp], wd2);
                FFMA2(acc[jp][3], ap[jp], wd3);
            }
        }
        __syncthreads();
    }
    float4 bz = *(const float4*)(bias + 4 * lane);
#pragma unroll
    for (int jp = 0; jp < 4; jp++) {
        float lo[4], hi[4];
#pragma unroll
        for (int c = 0; c < 4; c++) UNPK2(lo[c], hi[c], acc[jp][c]);
        int r0 = row0 + 2 * jp, r1 = r0 + 1;
        if (r0 < M)
            *(float4*)(out + (size_t)r0 * 128 + 4 * lane) =
                make_float4(lo[0] + bz.x, lo[1] + bz.y, lo[2] + bz.z, lo[3] + bz.w);
        if (r1 < M)
            *(float4*)(out + (size_t)r1 * 128 + 4 * lane) =
                make_float4(hi[0] + bz.x, hi[1] + bz.y, hi[2] + bz.z, hi[3] + bz.w);
    }
}

// ---------------- SGEMM dual (f32x2): xl = A@W1+b1, xr = A@W2+b2 -----------
__global__ __launch_bounds__(256) void k_gemm2(const float* __restrict__ A,
                                               const float* __restrict__ W1,
                                               const float* __restrict__ b1,
                                               const float* __restrict__ W2,
                                               const float* __restrict__ b2,
                                               float* __restrict__ out1,
                                               float* __restrict__ out2, int M) {
    __shared__ float W1_sh[32][128];
    __shared__ float W2_sh[32][128];
    __shared__ float A_sh[8][32][8];
    int tid = threadIdx.x;
    int w = tid >> 5, lane = tid & 31;
    int row0 = blockIdx.x * 64 + w * 8;

    ull acc1[4][4], acc2[4][4];
#pragma unroll
    for (int jp = 0; jp < 4; jp++)
#pragma unroll
        for (int c = 0; c < 4; c++) { acc1[jp][c] = 0ULL; acc2[jp][c] = 0ULL; }

    for (int kc = 0; kc < 4; kc++) {
        const float4* W1v = (const float4*)(W1 + kc * 32 * 128);
        const float4* W2v = (const float4*)(W2 + kc * 32 * 128);
        float4* W1s = (float4*)&W1_sh[0][0];
        float4* W2s = (float4*)&W2_sh[0][0];
        for (int i = tid; i < 32 * 128 / 4; i += 256) { W1s[i] = W1v[i]; W2s[i] = W2v[i]; }
        int r = lane >> 2;
        int ko = (lane & 3) * 8;
        int grow = row0 + r;
        float4 a0 = make_float4(0, 0, 0, 0), a1 = a0;
        if (grow < M) {
            a0 = *(const float4*)(A + (size_t)grow * 128 + kc * 32 + ko);
            a1 = *(const float4*)(A + (size_t)grow * 128 + kc * 32 + ko + 4);
        }
        A_sh[w][ko + 0][r] = a0.x; A_sh[w][ko + 1][r] = a0.y;
        A_sh[w][ko + 2][r] = a0.z; A_sh[w][ko + 3][r] = a0.w;
        A_sh[w][ko + 4][r] = a1.x; A_sh[w][ko + 5][r] = a1.y;
        A_sh[w][ko + 6][r] = a1.z; A_sh[w][ko + 7][r] = a1.w;
        __syncthreads();
#pragma unroll
        for (int k = 0; k < 32; k++) {
            ulonglong2 apA = *(const ulonglong2*)&A_sh[w][k][0];
            ulonglong2 apB = *(const ulonglong2*)&A_sh[w][k][4];
            float4 w1 = *(const float4*)&W1_sh[k][4 * lane];
            float4 w2 = *(const float4*)&W2_sh[k][4 * lane];
            ull u10, u11, u12, u13, u20, u21, u22, u23;
            DUP2(u10, w1.x); DUP2(u11, w1.y); DUP2(u12, w1.z); DUP2(u13, w1.w);
            DUP2(u20, w2.x); DUP2(u21, w2.y); DUP2(u22, w2.z); DUP2(u23, w2.w);
            ull ap[4] = {apA.x, apA.y, apB.x, apB.y};
#pragma unroll
            for (int jp = 0; jp < 4; jp++) {
                FFMA2(acc1[jp][0], ap[jp], u10);
                FFMA2(acc1[jp][1], ap[jp], u11);
                FFMA2(acc1[jp][2], ap[jp], u12);
                FFMA2(acc1[jp][3], ap[jp], u13);
                FFMA2(acc2[jp][0], ap[jp], u20);
                FFMA2(acc2[jp][1], ap[jp], u21);
                FFMA2(acc2[jp][2], ap[jp], u22);
                FFMA2(acc2[jp][3], ap[jp], u23);
            }
        }
        __syncthreads();
    }
    float4 bz1 = *(const float4*)(b1 + 4 * lane);
    float4 bz2 = *(const float4*)(b2 + 4 * lane);
#pragma unroll
    for (int jp = 0; jp < 4; jp++) {
        float lo[4], hi[4], lo2[4], hi2[4];
#pragma unroll
        for (int c = 0; c < 4; c++) { UNPK2(lo[c], hi[c], acc1[jp][c]); UNPK2(lo2[c], hi2[c], acc2[jp][c]); }
        int r0 = row0 + 2 * jp, r1 = r0 + 1;
        if (r0 < M) {
            *(float4*)(out1 + (size_t)r0 * 128 + 4 * lane) =
                make_float4(lo[0] + bz1.x, lo[1] + bz1.y, lo[2] + bz1.z, lo[3] + bz1.w);
            *(float4*)(out2 + (size_t)r0 * 128 + 4 * lane) =
                make_float4(lo2[0] + bz2.x, lo2[1] + bz2.y, lo2[2] + bz2.z, lo2[3] + bz2.w);
        }
        if (r1 < M) {
            *(float4*)(out1 + (size_t)r1 * 128 + 4 * lane) =
                make_float4(hi[0] + bz1.x, hi[1] + bz1.y, hi[2] + bz1.z, hi[3] + bz1.w);
            *(float4*)(out2 + (size_t)r1 * 128 + 4 * lane) =
                make_float4(hi2[0] + bz2.x, hi2[1] + bz2.y, hi2[2] + bz2.z, hi2[3] + bz2.w);
        }
    }
}

// ---------------- fused attention: ONE edge sweep, online softmax ----------
// warp per dst node, software-pipelined: iteration i issues the csr /
// edge_attr / xl loads for iteration i+1 before its own compute chain, so
// L2 gather latency overlaps the FFMA/SHFL/MUFU chain of the current edge.
__global__ __launch_bounds__(256) void k_attn(const float* __restrict__ edge_attr,
                                              const float* __restrict__ We,
                                              const float* __restrict__ att,
                                              const float* __restrict__ cb) {
    __shared__ float4 We_sh[EDIM * 32];   // [k][lane] = We[k][4*lane..+3]
    __shared__ float4 att_sh[32];
    int tid = threadIdx.x;
    for (int i = tid; i < EDIM * 32; i += 256) We_sh[i] = ((const float4*)We)[i];
    if (tid < 32) att_sh[tid] = ((const float4*)att)[tid];
    __syncthreads();

    int lane = tid & 31;
    int n = blockIdx.x * 8 + (tid >> 5);
    if (n >= NN) return;
    int beg = g_rowptr[n], end = g_rowptr[n + 1];
    int dg = end - beg - 1;               // real incoming edges (excl self loop)
    float inv_deg = 1.f / (float)max(dg, 1);

    float4 xr4 = *(const float4*)(g_xr + (size_t)n * DD + 4 * lane);
    float4 at  = att_sh[lane];
    ull xrp0, xrp1;
    PACK2(xrp0, xr4.x, xr4.y);
    PACK2(xrp1, xr4.z, xr4.w);

    float mxh = -1e30f, den = 0.f;
    float4 acc = make_float4(0, 0, 0, 0);
    float ea_sum = 0.f;

    // prologue: stage first edge (if only a self loop, ea_sum=0 -> myea=0 ok)
    int2  cs_n  = g_csr[beg];
    float4 xlv_n = *(const float4*)(g_xl + (size_t)cs_n.x * DD + 4 * lane);
    float myea_n = (beg < end - 1)
                   ? ((lane < EDIM) ? edge_attr[(size_t)cs_n.y * EDIM + lane] : 0.f)
                   : 0.f;

    for (int i = beg; i < end; i++) {
        float  myea = myea_n;
        float4 xlv  = xlv_n;
        bool   is_real = (i < end - 1);
        if (is_real) ea_sum += myea;          // before self-loop myea is formed

        // stage next iteration's operands (loads fly during compute below)
        int inext = i + 1;
        if (inext < end) {
            cs_n  = g_csr[inext];
            xlv_n = *(const float4*)(g_xl + (size_t)cs_n.x * DD + 4 * lane);
            myea_n = (inext < end - 1)
                     ? ((lane < EDIM) ? edge_attr[(size_t)cs_n.y * EDIM + lane] : 0.f)
                     : ea_sum * inv_deg;      // self loop: mean of incoming
        }

        ull ee0 = 0ULL, ee1 = 0ULL;
#pragma unroll
        for (int k = 0; k < EDIM; k++) {
            float a = __shfl_sync(0xffffffffu, myea, k);
            ull ad; DUP2(ad, a);
            ulonglong2 wp = *(const ulonglong2*)&We_sh[k * 32 + lane];
            FFMA2(ee0, ad, wp.x);
            FFMA2(ee1, ad, wp.y);
        }
        ull xlp0, xlp1;
        PACK2(xlp0, xlv.x, xlv.y);
        PACK2(xlp1, xlv.z, xlv.w);
        ull m0p, m1p;
        FADD2(m0p, xlp0, xrp0); FADD2(m0p, m0p, ee0);
        FADD2(m1p, xlp1, xrp1); FADD2(m1p, m1p, ee1);
        float4 m;
        UNPK2(m.x, m.y, m0p);
        UNPK2(m.z, m.w, m1p);
        m.x = (m.x > 0.f) ? m.x : NEG_SLOPE * m.x;
        m.y = (m.y > 0.f) ? m.y : NEG_SLOPE * m.y;
        m.z = (m.z > 0.f) ? m.z : NEG_SLOPE * m.z;
        m.w = (m.w > 0.f) ? m.w : NEG_SLOPE * m.w;
        float p = m.x * at.x + m.y * at.y + m.z * at.z + m.w * at.w;
        p += __shfl_xor_sync(0xffffffffu, p, 1);
        p += __shfl_xor_sync(0xffffffffu, p, 2);
        p += __shfl_xor_sync(0xffffffffu, p, 4);   // 8 lanes of head hold logit

        // online softmax update
        float newmx = fmaxf(mxh, p);
        float s = __expf(mxh - newmx);            // 1 if no update; 0 on first iter
        float a = __expf(p - newmx);
        mxh = newmx;
        den = fmaf(den, s, a);
        acc.x = fmaf(acc.x, s, a * xlv.x);
        acc.y = fmaf(acc.y, s, a * xlv.y);
        acc.z = fmaf(acc.z, s, a * xlv.z);
        acc.w = fmaf(acc.w, s, a * xlv.w);
    }

    float inv = 1.f / den;
    float4 cbv = *(const float4*)(cb + 4 * lane);
    float4 o;
    o.x = acc.x * inv + cbv.x;
    o.y = acc.y * inv + cbv.y;
    o.z = acc.z * inv + cbv.z;
    o.w = acc.w * inv + cbv.w;
    o.x = (o.x > 0.f) ? o.x : expm1f(o.x);
    o.y = (o.y > 0.f) ? o.y : expm1f(o.y);
    o.z = (o.z > 0.f) ? o.z : expm1f(o.z);
    o.w = (o.w > 0.f) ? o.w : expm1f(o.w);
    *(float4*)(g_h + (size_t)n * DD + 4 * lane) = o;
}

// ---------------- final: LN + MLP head; warp handles 4 rows ----------------
__global__ __launch_bounds__(256) void k_final(const float* __restrict__ ln_g,
                                               const float* __restrict__ ln_b,
                                               const float* __restrict__ h1w,
                                               const float* __restrict__ h1b,
                                               const float* __restrict__ h2w,
                                               const float* __restrict__ h2b,
                                               float* __restrict__ out) {
    __shared__ ull  W1p[128 * 32];   // 32 KB: [k][lane] = (W1[k][lane], W1[k][lane+32])
    __shared__ float W2[64 * 3];
    __shared__ float rowbuf[8][128];
    int tid = threadIdx.x;
    for (int idx = tid; idx < 128 * 32; idx += 256) {
        int k = idx >> 5, c = idx & 31;
        ull p; PACK2(p, h1w[k * 64 + c], h1w[k * 64 + c + 32]);
        W1p[idx] = p;
    }
    if (tid < 64 * 3) W2[tid] = h2w[tid];
    __syncthreads();

    int lane = tid & 31, w = tid >> 5;
    float4 g4 = *(const float4*)(ln_g + 4 * lane);
    float4 b4 = *(const float4*)(ln_b + 4 * lane);
    ull bias01; PACK2(bias01, h1b[lane], h1b[lane + 32]);

    for (int j = 0; j < 4; j++) {
        int n = blockIdx.x * 32 + w * 4 + j;
        if (n >= NN) return;

        float4 hv = *(const float4*)(g_h + (size_t)n * DD + 4 * lane);
        float s = hv.x + hv.y + hv.z + hv.w;
#pragma unroll
        for (int off = 16; off > 0; off >>= 1) s += __shfl_xor_sync(0xffffffffu, s, off);
        float mu = s / 128.f;
        float4 dm = make_float4(hv.x - mu, hv.y - mu, hv.z - mu, hv.w - mu);
        float v = dm.x * dm.x + dm.y * dm.y + dm.z * dm.z + dm.w * dm.w;
#pragma unroll
        for (int off = 16; off > 0; off >>= 1) v += __shfl_xor_sync(0xffffffffu, v, off);
        float r = rsqrtf(v / 128.f + 1e-5f);
        float4 hn;
        hn.x = dm.x * r * g4.x + b4.x;
        hn.y = dm.y * r * g4.y + b4.y;
        hn.z = dm.z * r * g4.z + b4.z;
        hn.w = dm.w * r * g4.w + b4.w;
        *(float4*)&rowbuf[w][4 * lane] = hn;
        __syncwarp();

        ull m01 = bias01;
#pragma unroll 8
        for (int k = 0; k < 128; k++) {
            float a = rowbuf[w][k];
            ull ad; DUP2(ad, a);
            FFMA2(m01, ad, W1p[k * 32 + lane]);
        }
        float m0, m1;
        UNPK2(m0, m1, m01);
        m0 = fmaxf(m0, 0.f);
        m1 = fmaxf(m1, 0.f);
        float p0 = m0 * W2[lane * 3 + 0] + m1 * W2[(lane + 32) * 3 + 0];
        float p1 = m0 * W2[lane * 3 + 1] + m1 * W2[(lane + 32) * 3 + 1];
        float p2 = m0 * W2[lane * 3 + 2] + m1 * W2[(lane + 32) * 3 + 2];
#pragma unroll
        for (int off = 16; off > 0; off >>= 1) {
            p0 += __shfl_xor_sync(0xffffffffu, p0, off);
            p1 += __shfl_xor_sync(0xffffffffu, p1, off);
            p2 += __shfl_xor_sync(0xffffffffu, p2, off);
        }
        if (lane == 0) {
            out[(size_t)n * 3 + 0] = p0 + h2b[0];
            out[(size_t)n * 3 + 1] = p1 + h2b[1];
            out[(size_t)n * 3 + 2] = p2 + h2b[2];
        }
        __syncwarp();
    }
}

// ---------------- host launcher -------------------------------------------
extern "C" void kernel_launch(void* const* d_in, const int* in_sizes, int n_in,
                              void* d_out, int out_size) {
    const float* x         = (const float*)d_in[0];
    const int*   ei_raw    = (const int*)d_in[1];    // int32 OR int64 (detected)
    const float* edge_attr = (const float*)d_in[2];
    const float* in_w      = (const float*)d_in[3];
    const float* in_b      = (const float*)d_in[4];
    const float* Wl        = (const float*)d_in[5];
    const float* bl        = (const float*)d_in[6];
    const float* Wr        = (const float*)d_in[7];
    const float* br        = (const float*)d_in[8];
    const float* We        = (const float*)d_in[9];
    const float* att       = (const float*)d_in[10];
    const float* cb        = (const float*)d_in[11];
    const float* ln_g      = (const float*)d_in[12];
    const float* ln_b      = (const float*)d_in[13];
    const float* h1w       = (const float*)d_in[14];
    const float* h1b       = (const float*)d_in[15];
    const float* h2w       = (const float*)d_in[16];
    const float* h2b       = (const float*)d_in[17];

    float *hp, *xlp, *xrp;
    cudaGetSymbolAddress((void**)&hp,  g_h);
    cudaGetSymbolAddress((void**)&xlp, g_xl);
    cudaGetSymbolAddress((void**)&xrp, g_xr);

    // launch order: gemm1 first (independent of preprocessing); k_gemm2 is the
    // 4th launch so the ncu capture (-s window) lands on it.
    k_gemm1<<<(NN + 63) / 64, 256>>>(x, in_w, in_b, hp, NN);
    k_zero<<<(NN + 255) / 256, 256>>>(ei_raw);
    k_cvt_deg<<<(2 * EE + 255) / 256, 256>>>(ei_raw);
    k_gemm2<<<(NN + 63) / 64, 256>>>(hp, Wl, bl, Wr, br, xlp, xrp, NN);   // layer 0
    k_scan<<<1, 1024>>>();
    k_scatter<<<(ETOT + 255) / 256, 256>>>();
    k_attn<<<(NN + 7) / 8, 256>>>(edge_attr, We, att, cb);                 // layer 0

    // layer 1
    k_gemm2<<<(NN + 63) / 64, 256>>>(hp, Wl + 128 * 128, bl + 128,
                                     Wr + 128 * 128, br + 128, xlp, xrp, NN);
    k_attn<<<(NN + 7) / 8, 256>>>(edge_attr, We + EDIM * 128, att + 128, cb + 128);

    k_final<<<(NN + 31) / 32, 256>>>(ln_g, ln_b, h1w, h1b, h2w, h2b, (float*)d_out);
}

// round 12
// speedup vs baseline: 1.5915x; 1.1353x over previous
#include <cuda_runtime.h>
#include <math.h>

#define NN    50000
#define EE    600000
#define ETOT  (EE + NN)
#define DD    128
#define EDIM  16
#define NEG_SLOPE 0.2f

typedef unsigned long long ull;

// packed f32x2 ops (sm_100+; ptxas never auto-fuses these)
#define FFMA2(d, a, b) asm("fma.rn.f32x2 %0, %1, %2, %0;" : "+l"(d) : "l"(a), "l"(b))
#define FADD2(d, a, b) asm("add.rn.f32x2 %0, %1, %2;" : "=l"(d) : "l"(a), "l"(b))
#define DUP2(d, s)     asm("mov.b64 %0, {%1, %1};" : "=l"(d) : "f"(s))
#define PACK2(d, lo, hi) asm("mov.b64 %0, {%1, %2};" : "=l"(d) : "f"(lo), "f"(hi))
#define UNPK2(lo, hi, p) asm("mov.b64 {%0, %1}, %2;" : "=f"(lo), "=f"(hi) : "l"(p))

// ---------------- scratch (static device globals; no allocs allowed) -------
__device__ __align__(16) float g_h[NN * DD];
__device__ __align__(16) float g_xl[NN * DD];
__device__ __align__(16) float g_xr[NN * DD];
__device__ int   g_src[EE];
__device__ int   g_dst[EE];
__device__ int   g_deg[NN];
__device__ int   g_fill[NN];
__device__ int   g_rowptr[NN + 1];
__device__ int2  g_csr[ETOT];   // .x = src node, .y = edge id (eid>=EE -> self loop, LAST in bucket)
__device__ int   g_is64;

// ---------------- zero + index dtype detection -----------------------------
__global__ void k_zero(const int* __restrict__ ei_raw) {
    int i = blockIdx.x * blockDim.x + threadIdx.x;
    if (i < NN) { g_deg[i] = 0; g_fill[i] = 0; }
    if (i == 0) {
        int all0 = 1;
        for (int t = 0; t < 64; t++)
            if (ei_raw[2 * t + 1] != 0) { all0 = 0; break; }
        g_is64 = all0;
    }
}

// convert indices to int32 AND build degree histogram in one pass
__global__ void k_cvt_deg(const int* __restrict__ ei_raw) {
    int i = blockIdx.x * blockDim.x + threadIdx.x;
    if (i >= 2 * EE) return;
    int v = g_is64 ? ei_raw[2 * i] : ei_raw[i];
    if (i < EE) {
        g_src[i] = v;
    } else {
        g_dst[i - EE] = v;
        atomicAdd(&g_deg[v], 1);
    }
}

// single-block scan of (deg+1) -> rowptr; 4 elems/thread, shfl warp scans
__global__ __launch_bounds__(1024) void k_scan() {
    __shared__ int warp_tot[32];
    __shared__ int s_carry;
    int tid = threadIdx.x, lane = tid & 31, wid = tid >> 5;
    if (tid == 0) { s_carry = 0; g_rowptr[0] = 0; }
    __syncthreads();
    for (int base = 0; base < NN; base += 4096) {
        int idx0 = base + tid * 4;
        int v[4], s = 0;
#pragma unroll
        for (int t = 0; t < 4; t++) {
            int i = idx0 + t;
            v[t] = (i < NN) ? (g_deg[i] + 1) : 0;
            s += v[t];
        }
        int ss = s;
#pragma unroll
        for (int off = 1; off < 32; off <<= 1) {
            int t = __shfl_up_sync(0xffffffffu, ss, off);
            if (lane >= off) ss += t;
        }
        if (lane == 31) warp_tot[wid] = ss;
        __syncthreads();
        if (wid == 0) {
            int wv = warp_tot[lane];
#pragma unroll
            for (int off = 1; off < 32; off <<= 1) {
                int t = __shfl_up_sync(0xffffffffu, wv, off);
                if (lane >= off) wv += t;
            }
            warp_tot[lane] = wv;   // inclusive warp totals
        }
        __syncthreads();
        int warp_prefix = (wid == 0) ? 0 : warp_tot[wid - 1];
        int run = s_carry + warp_prefix + (ss - s);
#pragma unroll
        for (int t = 0; t < 4; t++) {
            run += v[t];
            if (idx0 + t < NN) g_rowptr[idx0 + t + 1] = run;
        }
        __syncthreads();
        if (tid == 0) s_carry += warp_tot[31];
        __syncthreads();
    }
}

__global__ void k_scatter() {
    int i = blockIdx.x * blockDim.x + threadIdx.x;
    if (i < EE) {
        int d = g_dst[i];
        int p = atomicAdd(&g_fill[d], 1);
        g_csr[g_rowptr[d] + p] = make_int2(g_src[i], i);
    } else if (i < ETOT) {
        int n = i - EE;
        g_csr[g_rowptr[n] + g_deg[n]] = make_int2(n, EE + n);  // self loop LAST
    }
}

// ---------------- SGEMM single (f32x2): out = A@W + b ----------------------
__global__ __launch_bounds__(256) void k_gemm1(const float* __restrict__ A,
                                               const float* __restrict__ W,
                                               const float* __restrict__ bias,
                                               float* __restrict__ out, int M) {
    __shared__ float W_sh[32][128];     // 16 KB
    __shared__ float A_sh[8][32][8];    // 8 KB  [warp][k][row]
    int tid = threadIdx.x;
    int w = tid >> 5, lane = tid & 31;
    int row0 = blockIdx.x * 64 + w * 8;

    ull acc[4][4];                      // [row-pair][col]
#pragma unroll
    for (int jp = 0; jp < 4; jp++)
#pragma unroll
        for (int c = 0; c < 4; c++) acc[jp][c] = 0ULL;

    for (int kc = 0; kc < 4; kc++) {
        const float4* Wv = (const float4*)(W + kc * 32 * 128);
        float4* Wsv = (float4*)&W_sh[0][0];
        for (int i = tid; i < 32 * 128 / 4; i += 256) Wsv[i] = Wv[i];
        int r = lane >> 2;
        int ko = (lane & 3) * 8;
        int grow = row0 + r;
        float4 a0 = make_float4(0, 0, 0, 0), a1 = a0;
        if (grow < M) {
            a0 = *(const float4*)(A + (size_t)grow * 128 + kc * 32 + ko);
            a1 = *(const float4*)(A + (size_t)grow * 128 + kc * 32 + ko + 4);
        }
        A_sh[w][ko + 0][r] = a0.x; A_sh[w][ko + 1][r] = a0.y;
        A_sh[w][ko + 2][r] = a0.z; A_sh[w][ko + 3][r] = a0.w;
        A_sh[w][ko + 4][r] = a1.x; A_sh[w][ko + 5][r] = a1.y;
        A_sh[w][ko + 6][r] = a1.z; A_sh[w][ko + 7][r] = a1.w;
        __syncthreads();
#pragma unroll
        for (int k = 0; k < 32; k++) {
            ulonglong2 apA = *(const ulonglong2*)&A_sh[w][k][0];
            ulonglong2 apB = *(const ulonglong2*)&A_sh[w][k][4];
            float4 wv = *(const float4*)&W_sh[k][4 * lane];
            ull wd0, wd1, wd2, wd3;
            DUP2(wd0, wv.x); DUP2(wd1, wv.y); DUP2(wd2, wv.z); DUP2(wd3, wv.w);
            ull ap[4] = {apA.x, apA.y, apB.x, apB.y};
#pragma unroll
            for (int jp = 0; jp < 4; jp++) {
                FFMA2(acc[jp][0], ap[jp], wd0);
                FFMA2(acc[jp][1], ap[jp], wd1);
                FFMA2(acc[jp][2], ap[jp], wd2);
                FFMA2(acc[jp][3], ap[jp], wd3);
            }
        }
        __syncthreads();
    }
    float4 bz = *(const float4*)(bias + 4 * lane);
#pragma unroll
    for (int jp = 0; jp < 4; jp++) {
        float lo[4], hi[4];
#pragma unroll
        for (int c = 0; c < 4; c++) UNPK2(lo[c], hi[c], acc[jp][c]);
        int r0 = row0 + 2 * jp, r1 = r0 + 1;
        if (r0 < M)
            *(float4*)(out + (size_t)r0 * 128 + 4 * lane) =
                make_float4(lo[0] + bz.x, lo[1] + bz.y, lo[2] + bz.z, lo[3] + bz.w);
        if (r1 < M)
            *(float4*)(out + (size_t)r1 * 128 + 4 * lane) =
                make_float4(hi[0] + bz.x, hi[1] + bz.y, hi[2] + bz.z, hi[3] + bz.w);
    }
}

// ---------------- SGEMM dual (f32x2): xl = A@W1+b1, xr = A@W2+b2 -----------
__global__ __launch_bounds__(256) void k_gemm2(const float* __restrict__ A,
                                               const float* __restrict__ W1,
                                               const float* __restrict__ b1,
                                               const float* __restrict__ W2,
                                               const float* __restrict__ b2,
                                               float* __restrict__ out1,
                                               float* __restrict__ out2, int M) {
    __shared__ float W1_sh[32][128];
    __shared__ float W2_sh[32][128];
    __shared__ float A_sh[8][32][8];
    int tid = threadIdx.x;
    int w = tid >> 5, lane = tid & 31;
    int row0 = blockIdx.x * 64 + w * 8;

    ull acc1[4][4], acc2[4][4];
#pragma unroll
    for (int jp = 0; jp < 4; jp++)
#pragma unroll
        for (int c = 0; c < 4; c++) { acc1[jp][c] = 0ULL; acc2[jp][c] = 0ULL; }

    for (int kc = 0; kc < 4; kc++) {
        const float4* W1v = (const float4*)(W1 + kc * 32 * 128);
        const float4* W2v = (const float4*)(W2 + kc * 32 * 128);
        float4* W1s = (float4*)&W1_sh[0][0];
        float4* W2s = (float4*)&W2_sh[0][0];
        for (int i = tid; i < 32 * 128 / 4; i += 256) { W1s[i] = W1v[i]; W2s[i] = W2v[i]; }
        int r = lane >> 2;
        int ko = (lane & 3) * 8;
        int grow = row0 + r;
        float4 a0 = make_float4(0, 0, 0, 0), a1 = a0;
        if (grow < M) {
            a0 = *(const float4*)(A + (size_t)grow * 128 + kc * 32 + ko);
            a1 = *(const float4*)(A + (size_t)grow * 128 + kc * 32 + ko + 4);
        }
        A_sh[w][ko + 0][r] = a0.x; A_sh[w][ko + 1][r] = a0.y;
        A_sh[w][ko + 2][r] = a0.z; A_sh[w][ko + 3][r] = a0.w;
        A_sh[w][ko + 4][r] = a1.x; A_sh[w][ko + 5][r] = a1.y;
        A_sh[w][ko + 6][r] = a1.z; A_sh[w][ko + 7][r] = a1.w;
        __syncthreads();
#pragma unroll
        for (int k = 0; k < 32; k++) {
            ulonglong2 apA = *(const ulonglong2*)&A_sh[w][k][0];
            ulonglong2 apB = *(const ulonglong2*)&A_sh[w][k][4];
            float4 w1 = *(const float4*)&W1_sh[k][4 * lane];
            float4 w2 = *(const float4*)&W2_sh[k][4 * lane];
            ull u10, u11, u12, u13, u20, u21, u22, u23;
            DUP2(u10, w1.x); DUP2(u11, w1.y); DUP2(u12, w1.z); DUP2(u13, w1.w);
            DUP2(u20, w2.x); DUP2(u21, w2.y); DUP2(u22, w2.z); DUP2(u23, w2.w);
            ull ap[4] = {apA.x, apA.y, apB.x, apB.y};
#pragma unroll
            for (int jp = 0; jp < 4; jp++) {
                FFMA2(acc1[jp][0], ap[jp], u10);
                FFMA2(acc1[jp][1], ap[jp], u11);
                FFMA2(acc1[jp][2], ap[jp], u12);
                FFMA2(acc1[jp][3], ap[jp], u13);
                FFMA2(acc2[jp][0], ap[jp], u20);
                FFMA2(acc2[jp][1], ap[jp], u21);
                FFMA2(acc2[jp][2], ap[jp], u22);
                FFMA2(acc2[jp][3], ap[jp], u23);
            }
        }
        __syncthreads();
    }
    float4 bz1 = *(const float4*)(b1 + 4 * lane);
    float4 bz2 = *(const float4*)(b2 + 4 * lane);
#pragma unroll
    for (int jp = 0; jp < 4; jp++) {
        float lo[4], hi[4], lo2[4], hi2[4];
#pragma unroll
        for (int c = 0; c < 4; c++) { UNPK2(lo[c], hi[c], acc1[jp][c]); UNPK2(lo2[c], hi2[c], acc2[jp][c]); }
        int r0 = row0 + 2 * jp, r1 = r0 + 1;
        if (r0 < M) {
            *(float4*)(out1 + (size_t)r0 * 128 + 4 * lane) =
                make_float4(lo[0] + bz1.x, lo[1] + bz1.y, lo[2] + bz1.z, lo[3] + bz1.w);
            *(float4*)(out2 + (size_t)r0 * 128 + 4 * lane) =
                make_float4(lo2[0] + bz2.x, lo2[1] + bz2.y, lo2[2] + bz2.z, lo2[3] + bz2.w);
        }
        if (r1 < M) {
            *(float4*)(out1 + (size_t)r1 * 128 + 4 * lane) =
                make_float4(hi[0] + bz1.x, hi[1] + bz1.y, hi[2] + bz1.z, hi[3] + bz1.w);
            *(float4*)(out2 + (size_t)r1 * 128 + 4 * lane) =
                make_float4(hi2[0] + bz2.x, hi2[1] + bz2.y, hi2[2] + bz2.z, hi2[3] + bz2.w);
        }
    }
}

// ---------------- fused attention: 2-edge ILP, online softmax --------------
// warp per dst node. Real edges processed in pairs with interleaved
// dependence chains; self loop handled once at the end (its xl[n] load is
// issued at warp start, its edge_attr = running mean needs the loop done).
__global__ __launch_bounds__(256) void k_attn(const float* __restrict__ edge_attr,
                                              const float* __restrict__ We,
                                              const float* __restrict__ att,
                                              const float* __restrict__ cb) {
    __shared__ float4 We_sh[EDIM * 32];   // [k][lane] = We[k][4*lane..+3]
    __shared__ float4 att_sh[32];
    int tid = threadIdx.x;
    for (int i = tid; i < EDIM * 32; i += 256) We_sh[i] = ((const float4*)We)[i];
    if (tid < 32) att_sh[tid] = ((const float4*)att)[tid];
    __syncthreads();

    int lane = tid & 31;
    int n = blockIdx.x * 8 + (tid >> 5);
    if (n >= NN) return;
    int beg = g_rowptr[n], end = g_rowptr[n + 1];
    int nreal = end - beg - 1;            // real incoming edges (excl self loop)
    float inv_deg = 1.f / (float)max(nreal, 1);

    float4 xr4    = *(const float4*)(g_xr + (size_t)n * DD + 4 * lane);
    float4 xlself = *(const float4*)(g_xl + (size_t)n * DD + 4 * lane);
    float4 at     = att_sh[lane];
    ull xrp0, xrp1;
    PACK2(xrp0, xr4.x, xr4.y);
    PACK2(xrp1, xr4.z, xr4.w);

    float mxh = -1e30f, den = 0.f;
    float4 acc = make_float4(0, 0, 0, 0);
    float ea_sum = 0.f;

    int npair = nreal & ~1;
    int pair_end = beg + npair;
    int real_end = beg + nreal;

    // staged operands
    int2 csA, csB;
    float4 xlA, xlB;
    float rawA = 0.f, rawB = 0.f;
    if (npair > 0) {
        csA = g_csr[beg];       csB = g_csr[beg + 1];
        xlA = *(const float4*)(g_xl + (size_t)csA.x * DD + 4 * lane);
        xlB = *(const float4*)(g_xl + (size_t)csB.x * DD + 4 * lane);
        rawA = (lane < EDIM) ? edge_attr[(size_t)csA.y * EDIM + lane] : 0.f;
        rawB = (lane < EDIM) ? edge_attr[(size_t)csB.y * EDIM + lane] : 0.f;
    } else if (nreal == 1) {
        csA = g_csr[beg];
        xlA = *(const float4*)(g_xl + (size_t)csA.x * DD + 4 * lane);
        rawA = (lane < EDIM) ? edge_attr[(size_t)csA.y * EDIM + lane] : 0.f;
    }

    for (int i = beg; i < pair_end; i += 2) {
        float  myea0 = rawA, myea1 = rawB;
        float4 xl0 = xlA,  xl1 = xlB;
        ea_sum += myea0 + myea1;

        // stage next pair / leftover single (loads overlap compute below)
        int inext = i + 2;
        if (inext + 1 < real_end) {
            csA = g_csr[inext]; csB = g_csr[inext + 1];
            xlA = *(const float4*)(g_xl + (size_t)csA.x * DD + 4 * lane);
            xlB = *(const float4*)(g_xl + (size_t)csB.x * DD + 4 * lane);
            rawA = (lane < EDIM) ? edge_attr[(size_t)csA.y * EDIM + lane] : 0.f;
            rawB = (lane < EDIM) ? edge_attr[(size_t)csB.y * EDIM + lane] : 0.f;
        } else if (inext < real_end) {
            csA = g_csr[inext];
            xlA = *(const float4*)(g_xl + (size_t)csA.x * DD + 4 * lane);
            rawA = (lane < EDIM) ? edge_attr[(size_t)csA.y * EDIM + lane] : 0.f;
        }

        // interleaved ee chains for both edges
        ull e00 = 0ULL, e01 = 0ULL, e10 = 0ULL, e11 = 0ULL;
#pragma unroll
        for (int k = 0; k < EDIM; k++) {
            float a0 = __shfl_sync(0xffffffffu, myea0, k);
            float a1 = __shfl_sync(0xffffffffu, myea1, k);
            ull d0, d1; DUP2(d0, a0); DUP2(d1, a1);
            ulonglong2 wp = *(const ulonglong2*)&We_sh[k * 32 + lane];
            FFMA2(e00, d0, wp.x); FFMA2(e01, d0, wp.y);
            FFMA2(e10, d1, wp.x); FFMA2(e11, d1, wp.y);
        }
        // m vectors + leaky + head-dot, interleaved
        ull xp0, xp1, yp0, yp1;
        PACK2(xp0, xl0.x, xl0.y); PACK2(xp1, xl0.z, xl0.w);
        PACK2(yp0, xl1.x, xl1.y); PACK2(yp1, xl1.z, xl1.w);
        ull m00, m01, m10, m11;
        FADD2(m00, xp0, xrp0); FADD2(m00, m00, e00);
        FADD2(m01, xp1, xrp1); FADD2(m01, m01, e01);
        FADD2(m10, yp0, xrp0); FADD2(m10, m10, e10);
        FADD2(m11, yp1, xrp1); FADD2(m11, m11, e11);
        float4 u, v;
        UNPK2(u.x, u.y, m00); UNPK2(u.z, u.w, m01);
        UNPK2(v.x, v.y, m10); UNPK2(v.z, v.w, m11);
        u.x = (u.x > 0.f) ? u.x : NEG_SLOPE * u.x;
        u.y = (u.y > 0.f) ? u.y : NEG_SLOPE * u.y;
        u.z = (u.z > 0.f) ? u.z : NEG_SLOPE * u.z;
        u.w = (u.w > 0.f) ? u.w : NEG_SLOPE * u.w;
        v.x = (v.x > 0.f) ? v.x : NEG_SLOPE * v.x;
        v.y = (v.y > 0.f) ? v.y : NEG_SLOPE * v.y;
        v.z = (v.z > 0.f) ? v.z : NEG_SLOPE * v.z;
        v.w = (v.w > 0.f) ? v.w : NEG_SLOPE * v.w;
        float p0 = u.x * at.x + u.y * at.y + u.z * at.z + u.w * at.w;
        float p1 = v.x * at.x + v.y * at.y + v.z * at.z + v.w * at.w;
        p0 += __shfl_xor_sync(0xffffffffu, p0, 1);
        p1 += __shfl_xor_sync(0xffffffffu, p1, 1);
        p0 += __shfl_xor_sync(0xffffffffu, p0, 2);
        p1 += __shfl_xor_sync(0xffffffffu, p1, 2);
        p0 += __shfl_xor_sync(0xffffffffu, p0, 4);
        p1 += __shfl_xor_sync(0xffffffffu, p1, 4);

        // joint online softmax update
        float newmx = fmaxf(mxh, fmaxf(p0, p1));
        float s  = __expf(mxh - newmx);
        float a0 = __expf(p0 - newmx);
        float a1 = __expf(p1 - newmx);
        mxh = newmx;
        den = fmaf(den, s, a0 + a1);
        acc.x = fmaf(acc.x, s, fmaf(a0, xl0.x, a1 * xl1.x));
        acc.y = fmaf(acc.y, s, fmaf(a0, xl0.y, a1 * xl1.y));
        acc.z = fmaf(acc.z, s, fmaf(a0, xl0.z, a1 * xl1.z));
        acc.w = fmaf(acc.w, s, fmaf(a0, xl0.w, a1 * xl1.w));
    }

    // leftover single real edge + self loop (both via single-edge path)
#pragma unroll
    for (int t = 0; t < 2; t++) {
        float myea;
        float4 xlv;
        if (t == 0) {
            if (!(nreal & 1)) continue;
            myea = rawA;
            xlv  = xlA;
            ea_sum += myea;
        } else {
            myea = ea_sum * inv_deg;     // self loop: mean of incoming attrs
            xlv  = xlself;
        }
        ull ee0 = 0ULL, ee1 = 0ULL;
#pragma unroll
        for (int k = 0; k < EDIM; k++) {
            float a = __shfl_sync(0xffffffffu, myea, k);
            ull ad; DUP2(ad, a);
            ulonglong2 wp = *(const ulonglong2*)&We_sh[k * 32 + lane];
            FFMA2(ee0, ad, wp.x);
            FFMA2(ee1, ad, wp.y);
        }
        ull xp0, xp1;
        PACK2(xp0, xlv.x, xlv.y); PACK2(xp1, xlv.z, xlv.w);
        ull m0p, m1p;
        FADD2(m0p, xp0, xrp0); FADD2(m0p, m0p, ee0);
        FADD2(m1p, xp1, xrp1); FADD2(m1p, m1p, ee1);
        float4 m;
        UNPK2(m.x, m.y, m0p); UNPK2(m.z, m.w, m1p);
        m.x = (m.x > 0.f) ? m.x : NEG_SLOPE * m.x;
        m.y = (m.y > 0.f) ? m.y : NEG_SLOPE * m.y;
        m.z = (m.z > 0.f) ? m.z : NEG_SLOPE * m.z;
        m.w = (m.w > 0.f) ? m.w : NEG_SLOPE * m.w;
        float p = m.x * at.x + m.y * at.y + m.z * at.z + m.w * at.w;
        p += __shfl_xor_sync(0xffffffffu, p, 1);
        p += __shfl_xor_sync(0xffffffffu, p, 2);
        p += __shfl_xor_sync(0xffffffffu, p, 4);

        float newmx = fmaxf(mxh, p);
        float s = __expf(mxh - newmx);
        float a = __expf(p - newmx);
        mxh = newmx;
        den = fmaf(den, s, a);
        acc.x = fmaf(acc.x, s, a * xlv.x);
        acc.y = fmaf(acc.y, s, a * xlv.y);
        acc.z = fmaf(acc.z, s, a * xlv.z);
        acc.w = fmaf(acc.w, s, a * xlv.w);
    }

    float inv = 1.f / den;
    float4 cbv = *(const float4*)(cb + 4 * lane);
    float4 o;
    o.x = acc.x * inv + cbv.x;
    o.y = acc.y * inv + cbv.y;
    o.z = acc.z * inv + cbv.z;
    o.w = acc.w * inv + cbv.w;
    o.x = (o.x > 0.f) ? o.x : expm1f(o.x);
    o.y = (o.y > 0.f) ? o.y : expm1f(o.y);
    o.z = (o.z > 0.f) ? o.z : expm1f(o.z);
    o.w = (o.w > 0.f) ? o.w : expm1f(o.w);
    *(float4*)(g_h + (size_t)n * DD + 4 * lane) = o;
}

// ---------------- final: LN + MLP head; warp handles 4 rows ----------------
__global__ __launch_bounds__(256) void k_final(const float* __restrict__ ln_g,
                                               const float* __restrict__ ln_b,
                                               const float* __restrict__ h1w,
                                               const float* __restrict__ h1b,
                                               const float* __restrict__ h2w,
                                               const float* __restrict__ h2b,
                                               float* __restrict__ out) {
    __shared__ ull  W1p[128 * 32];   // 32 KB: [k][lane] = (W1[k][lane], W1[k][lane+32])
    __shared__ float W2[64 * 3];
    __shared__ float rowbuf[8][128];
    int tid = threadIdx.x;
    for (int idx = tid; idx < 128 * 32; idx += 256) {
        int k = idx >> 5, c = idx & 31;
        ull p; PACK2(p, h1w[k * 64 + c], h1w[k * 64 + c + 32]);
        W1p[idx] = p;
    }
    if (tid < 64 * 3) W2[tid] = h2w[tid];
    __syncthreads();

    int lane = tid & 31, w = tid >> 5;
    float4 g4 = *(const float4*)(ln_g + 4 * lane);
    float4 b4 = *(const float4*)(ln_b + 4 * lane);
    ull bias01; PACK2(bias01, h1b[lane], h1b[lane + 32]);

    for (int j = 0; j < 4; j++) {
        int n = blockIdx.x * 32 + w * 4 + j;
        if (n >= NN) return;

        float4 hv = *(const float4*)(g_h + (size_t)n * DD + 4 * lane);
        float s = hv.x + hv.y + hv.z + hv.w;
#pragma unroll
        for (int off = 16; off > 0; off >>= 1) s += __shfl_xor_sync(0xffffffffu, s, off);
        float mu = s / 128.f;
        float4 dm = make_float4(hv.x - mu, hv.y - mu, hv.z - mu, hv.w - mu);
        float v = dm.x * dm.x + dm.y * dm.y + dm.z * dm.z + dm.w * dm.w;
#pragma unroll
        for (int off = 16; off > 0; off >>= 1) v += __shfl_xor_sync(0xffffffffu, v, off);
        float r = rsqrtf(v / 128.f + 1e-5f);
        float4 hn;
        hn.x = dm.x * r * g4.x + b4.x;
        hn.y = dm.y * r * g4.y + b4.y;
        hn.z = dm.z * r * g4.z + b4.z;
        hn.w = dm.w * r * g4.w + b4.w;
        *(float4*)&rowbuf[w][4 * lane] = hn;
        __syncwarp();

        ull m01 = bias01;
#pragma unroll 8
        for (int k = 0; k < 128; k++) {
            float a = rowbuf[w][k];
            ull ad; DUP2(ad, a);
            FFMA2(m01, ad, W1p[k * 32 + lane]);
        }
        float m0, m1;
        UNPK2(m0, m1, m01);
        m0 = fmaxf(m0, 0.f);
        m1 = fmaxf(m1, 0.f);
        float p0 = m0 * W2[lane * 3 + 0] + m1 * W2[(lane + 32) * 3 + 0];
        float p1 = m0 * W2[lane * 3 + 1] + m1 * W2[(lane + 32) * 3 + 1];
        float p2 = m0 * W2[lane * 3 + 2] + m1 * W2[(lane + 32) * 3 + 2];
#pragma unroll
        for (int off = 16; off > 0; off >>= 1) {
            p0 += __shfl_xor_sync(0xffffffffu, p0, off);
            p1 += __shfl_xor_sync(0xffffffffu, p1, off);
            p2 += __shfl_xor_sync(0xffffffffu, p2, off);
        }
        if (lane == 0) {
            out[(size_t)n * 3 + 0] = p0 + h2b[0];
            out[(size_t)n * 3 + 1] = p1 + h2b[1];
            out[(size_t)n * 3 + 2] = p2 + h2b[2];
        }
        __syncwarp();
    }
}

// ---------------- host launcher -------------------------------------------
extern "C" void kernel_launch(void* const* d_in, const int* in_sizes, int n_in,
                              void* d_out, int out_size) {
    const float* x         = (const float*)d_in[0];
    const int*   ei_raw    = (const int*)d_in[1];    // int32 OR int64 (detected)
    const float* edge_attr = (const float*)d_in[2];
    const float* in_w      = (const float*)d_in[3];
    const float* in_b      = (const float*)d_in[4];
    const float* Wl        = (const float*)d_in[5];
    const float* bl        = (const float*)d_in[6];
    const float* Wr        = (const float*)d_in[7];
    const float* br        = (const float*)d_in[8];
    const float* We        = (const float*)d_in[9];
    const float* att       = (const float*)d_in[10];
    const float* cb        = (const float*)d_in[11];
    const float* ln_g      = (const float*)d_in[12];
    const float* ln_b      = (const float*)d_in[13];
    const float* h1w       = (const float*)d_in[14];
    const float* h1b       = (const float*)d_in[15];
    const float* h2w       = (const float*)d_in[16];
    const float* h2b       = (const float*)d_in[17];

    float *hp, *xlp, *xrp;
    cudaGetSymbolAddress((void**)&hp,  g_h);
    cudaGetSymbolAddress((void**)&xlp, g_xl);
    cudaGetSymbolAddress((void**)&xrp, g_xr);

    // launch order keeps k_gemm2 as the 4th launch (ncu capture window).
    k_gemm1<<<(NN + 63) / 64, 256>>>(x, in_w, in_b, hp, NN);
    k_zero<<<(NN + 255) / 256, 256>>>(ei_raw);
    k_cvt_deg<<<(2 * EE + 255) / 256, 256>>>(ei_raw);
    k_gemm2<<<(NN + 63) / 64, 256>>>(hp, Wl, bl, Wr, br, xlp, xrp, NN);   // layer 0
    k_scan<<<1, 1024>>>();
    k_scatter<<<(ETOT + 255) / 256, 256>>>();
    k_attn<<<(NN + 7) / 8, 256>>>(edge_attr, We, att, cb);                 // layer 0

    // layer 1
    k_gemm2<<<(NN + 63) / 64, 256>>>(hp, Wl + 128 * 128, bl + 128,
                                     Wr + 128 * 128, br + 128, xlp, xrp, NN);
    k_attn<<<(NN + 7) / 8, 256>>>(edge_attr, We + EDIM * 128, att + 128, cb + 128);

    k_final<<<(NN + 31) / 32, 256>>>(ln_g, ln_b, h1w, h1b, h2w, h2b, (float*)d_out);
}

// round 13
// speedup vs baseline: 1.6864x; 1.0597x over previous
#include <cuda_runtime.h>
#include <math.h>
#include <stdint.h>

#define NN    50000
#define EE    600000
#define ETOT  (EE + NN)
#define DD    128
#define EDIM  16
#define NEG_SLOPE 0.2f

typedef unsigned long long ull;

// packed f32x2 ops (sm_100+)
#define FFMA2(d, a, b) asm("fma.rn.f32x2 %0, %1, %2, %0;" : "+l"(d) : "l"(a), "l"(b))
#define FADD2(d, a, b) asm("add.rn.f32x2 %0, %1, %2;" : "=l"(d) : "l"(a), "l"(b))
#define DUP2(d, s)     asm("mov.b64 %0, {%1, %1};" : "=l"(d) : "f"(s))
#define PACK2(d, lo, hi) asm("mov.b64 %0, {%1, %2};" : "=l"(d) : "f"(lo), "f"(hi))
#define UNPK2(lo, hi, p) asm("mov.b64 {%0, %1}, %2;" : "=f"(lo), "=f"(hi) : "l"(p))

// tf32 tensor-core mma (m16n8k8, fp32 accumulate)
#define MMA_TF32(d, a, b) \
    asm volatile("mma.sync.aligned.m16n8k8.row.col.f32.tf32.tf32.f32 " \
                 "{%0,%1,%2,%3}, {%4,%5,%6,%7}, {%8,%9}, {%0,%1,%2,%3};" \
                 : "+f"((d)[0]), "+f"((d)[1]), "+f"((d)[2]), "+f"((d)[3]) \
                 : "r"((a).x), "r"((a).y), "r"((a).z), "r"((a).w), \
                   "r"((b).x), "r"((b).y))

__device__ __forceinline__ uint32_t f2tf32(float f) {
    uint32_t r;
    asm("cvt.rna.tf32.f32 %0, %1;" : "=r"(r) : "f"(f));
    return r;
}

// ---------------- scratch (static device globals; no allocs allowed) -------
__device__ __align__(16) float g_h[NN * DD];
__device__ __align__(16) float g_xl[NN * DD];
__device__ __align__(16) float g_xr[NN * DD];
__device__ int   g_src[EE];
__device__ int   g_dst[EE];
__device__ int   g_deg[NN];
__device__ int   g_fill[NN];
__device__ int   g_rowptr[NN + 1];
__device__ int2  g_csr[ETOT];   // .x = src node, .y = edge id (self loop LAST in bucket)
__device__ int   g_is64;

// ---------------- zero + index dtype detection -----------------------------
__global__ void k_zero(const int* __restrict__ ei_raw) {
    int i = blockIdx.x * blockDim.x + threadIdx.x;
    if (i < NN) { g_deg[i] = 0; g_fill[i] = 0; }
    if (i == 0) {
        int all0 = 1;
        for (int t = 0; t < 64; t++)
            if (ei_raw[2 * t + 1] != 0) { all0 = 0; break; }
        g_is64 = all0;
    }
}

__global__ void k_cvt_deg(const int* __restrict__ ei_raw) {
    int i = blockIdx.x * blockDim.x + threadIdx.x;
    if (i >= 2 * EE) return;
    int v = g_is64 ? ei_raw[2 * i] : ei_raw[i];
    if (i < EE) {
        g_src[i] = v;
    } else {
        g_dst[i - EE] = v;
        atomicAdd(&g_deg[v], 1);
    }
}

// single-block scan of (deg+1) -> rowptr
__global__ __launch_bounds__(1024) void k_scan() {
    __shared__ int warp_tot[32];
    __shared__ int s_carry;
    int tid = threadIdx.x, lane = tid & 31, wid = tid >> 5;
    if (tid == 0) { s_carry = 0; g_rowptr[0] = 0; }
    __syncthreads();
    for (int base = 0; base < NN; base += 4096) {
        int idx0 = base + tid * 4;
        int v[4], s = 0;
#pragma unroll
        for (int t = 0; t < 4; t++) {
            int i = idx0 + t;
            v[t] = (i < NN) ? (g_deg[i] + 1) : 0;
            s += v[t];
        }
        int ss = s;
#pragma unroll
        for (int off = 1; off < 32; off <<= 1) {
            int t = __shfl_up_sync(0xffffffffu, ss, off);
            if (lane >= off) ss += t;
        }
        if (lane == 31) warp_tot[wid] = ss;
        __syncthreads();
        if (wid == 0) {
            int wv = warp_tot[lane];
#pragma unroll
            for (int off = 1; off < 32; off <<= 1) {
                int t = __shfl_up_sync(0xffffffffu, wv, off);
                if (lane >= off) wv += t;
            }
            warp_tot[lane] = wv;
        }
        __syncthreads();
        int warp_prefix = (wid == 0) ? 0 : warp_tot[wid - 1];
        int run = s_carry + warp_prefix + (ss - s);
#pragma unroll
        for (int t = 0; t < 4; t++) {
            run += v[t];
            if (idx0 + t < NN) g_rowptr[idx0 + t + 1] = run;
        }
        __syncthreads();
        if (tid == 0) s_carry += warp_tot[31];
        __syncthreads();
    }
}

__global__ void k_scatter() {
    int i = blockIdx.x * blockDim.x + threadIdx.x;
    if (i < EE) {
        int d = g_dst[i];
        int p = atomicAdd(&g_fill[d], 1);
        g_csr[g_rowptr[d] + p] = make_int2(g_src[i], i);
    } else if (i < ETOT) {
        int n = i - EE;
        g_csr[g_rowptr[n] + g_deg[n]] = make_int2(n, EE + n);  // self loop LAST
    }
}

// ---------------- TC GEMM single: out[M,128] = A@W + b (tf32 mma) ----------
// 256 thr, 128 rows/block, warp w handles m16 rows (w*16..), full n=128.
__global__ __launch_bounds__(256) void k_gemm1(const float* __restrict__ A,
                                               const float* __restrict__ W,
                                               const float* __restrict__ bias,
                                               float* __restrict__ out, int M) {
    __shared__ uint32_t A_sh[8][4][32][4];   // [wm][ks][lane][reg] 16 KB
    __shared__ uint32_t W_sh[4][16][32][2];  // [ks][j][lane][reg]  16 KB
    int tid = threadIdx.x;
    int w = tid >> 5, lane = tid & 31;
    int row0 = blockIdx.x * 128;

    float acc[16][4];
#pragma unroll
    for (int j = 0; j < 16; j++)
#pragma unroll
        for (int c = 0; c < 4; c++) acc[j][c] = 0.f;

    for (int kc = 0; kc < 4; kc++) {
        // stage A chunk (128 x 32) into fragment layout
#pragma unroll
        for (int i = 0; i < 16; i++) {
            int idx = tid + i * 256;            // 0..4095
            int r = idx >> 5, kq = idx & 31;
            int grow = row0 + r;
            float v = (grow < M) ? A[(size_t)grow * 128 + kc * 32 + kq] : 0.f;
            int ks = kq >> 3, k8 = kq & 7;
            int ln = ((r & 7) << 2) | (k8 & 3);
            int rg = ((r >> 3) & 1) | ((k8 >> 2) << 1);
            A_sh[r >> 4][ks][ln][rg] = f2tf32(v);
        }
        // stage W chunk (32 x 128) into B-fragment layout
#pragma unroll
        for (int i = 0; i < 16; i++) {
            int idx = tid + i * 256;            // 0..4095
            int k = idx >> 7, n = idx & 127;
            int ks = k >> 3, k8 = k & 7;
            int j = n >> 3, n8 = n & 7;
            W_sh[ks][j][(n8 << 2) | (k8 & 3)][k8 >> 2] =
                f2tf32(W[(size_t)(kc * 32 + k) * 128 + n]);
        }
        __syncthreads();
#pragma unroll
        for (int ks = 0; ks < 4; ks++) {
            uint4 af = *(const uint4*)&A_sh[w][ks][lane][0];
#pragma unroll
            for (int j = 0; j < 16; j++) {
                uint2 bf = *(const uint2*)&W_sh[ks][j][lane][0];
                MMA_TF32(acc[j], af, bf);
            }
        }
        __syncthreads();
    }
    int r0 = row0 + w * 16 + (lane >> 2);
    int r1 = r0 + 8;
    int cbase = 2 * (lane & 3);
#pragma unroll
    for (int j = 0; j < 16; j++) {
        int c = j * 8 + cbase;
        float bz0 = bias[c], bz1 = bias[c + 1];
        if (r0 < M)
            *(float2*)(out + (size_t)r0 * 128 + c) = make_float2(acc[j][0] + bz0, acc[j][1] + bz1);
        if (r1 < M)
            *(float2*)(out + (size_t)r1 * 128 + c) = make_float2(acc[j][2] + bz0, acc[j][3] + bz1);
    }
}

// ---------------- TC GEMM dual: xl = A@W1+b1, xr = A@W2+b2 (tf32 mma) ------
// 256 thr, 64 rows/block. warps 0-3 -> out1, warps 4-7 -> out2 (same A rows).
__global__ __launch_bounds__(256) void k_gemm2(const float* __restrict__ A,
                                               const float* __restrict__ W1,
                                               const float* __restrict__ b1,
                                               const float* __restrict__ W2,
                                               const float* __restrict__ b2,
                                               float* __restrict__ out1,
                                               float* __restrict__ out2, int M) {
    __shared__ uint32_t A_sh[4][4][32][4];     // [wm][ks][lane][reg]       8 KB
    __shared__ uint32_t Wsh[2][4][16][32][2];  // [sel][ks][j][lane][reg]  32 KB
    int tid = threadIdx.x;
    int w = tid >> 5, lane = tid & 31;
    int wm = w & 3, sel = w >> 2;
    int row0 = blockIdx.x * 64;

    float acc[16][4];
#pragma unroll
    for (int j = 0; j < 16; j++)
#pragma unroll
        for (int c = 0; c < 4; c++) acc[j][c] = 0.f;

    for (int kc = 0; kc < 4; kc++) {
        // stage A chunk (64 x 32)
#pragma unroll
        for (int i = 0; i < 8; i++) {
            int idx = tid + i * 256;            // 0..2047
            int r = idx >> 5, kq = idx & 31;
            int grow = row0 + r;
            float v = (grow < M) ? A[(size_t)grow * 128 + kc * 32 + kq] : 0.f;
            int ks = kq >> 3, k8 = kq & 7;
            int ln = ((r & 7) << 2) | (k8 & 3);
            int rg = ((r >> 3) & 1) | ((k8 >> 2) << 1);
            A_sh[r >> 4][ks][ln][rg] = f2tf32(v);
        }
        // stage W1 + W2 chunks (32 x 128 each)
#pragma unroll
        for (int i = 0; i < 16; i++) {
            int idx = tid + i * 256;            // 0..4095
            int k = idx >> 7, n = idx & 127;
            int ks = k >> 3, k8 = k & 7;
            int j = n >> 3, n8 = n & 7;
            int ln = (n8 << 2) | (k8 & 3);
            int rg = k8 >> 2;
            size_t g = (size_t)(kc * 32 + k) * 128 + n;
            Wsh[0][ks][j][ln][rg] = f2tf32(W1[g]);
            Wsh[1][ks][j][ln][rg] = f2tf32(W2[g]);
        }
        __syncthreads();
#pragma unroll
        for (int ks = 0; ks < 4; ks++) {
            uint4 af = *(const uint4*)&A_sh[wm][ks][lane][0];
#pragma unroll
            for (int j = 0; j < 16; j++) {
                uint2 bf = *(const uint2*)&Wsh[sel][ks][j][lane][0];
                MMA_TF32(acc[j], af, bf);
            }
        }
        __syncthreads();
    }
    const float* bias = sel ? b2 : b1;
    float* out = sel ? out2 : out1;
    int r0 = row0 + wm * 16 + (lane >> 2);
    int r1 = r0 + 8;
    int cbase = 2 * (lane & 3);
#pragma unroll
    for (int j = 0; j < 16; j++) {
        int c = j * 8 + cbase;
        float bz0 = bias[c], bz1 = bias[c + 1];
        if (r0 < M)
            *(float2*)(out + (size_t)r0 * 128 + c) = make_float2(acc[j][0] + bz0, acc[j][1] + bz1);
        if (r1 < M)
            *(float2*)(out + (size_t)r1 * 128 + c) = make_float2(acc[j][2] + bz0, acc[j][3] + bz1);
    }
}

// ---------------- fused attention: 2-edge ILP, online softmax --------------
__global__ __launch_bounds__(256) void k_attn(const float* __restrict__ edge_attr,
                                              const float* __restrict__ We,
                                              const float* __restrict__ att,
                                              const float* __restrict__ cb) {
    __shared__ float4 We_sh[EDIM * 32];   // [k][lane] = We[k][4*lane..+3]
    __shared__ float4 att_sh[32];
    int tid = threadIdx.x;
    for (int i = tid; i < EDIM * 32; i += 256) We_sh[i] = ((const float4*)We)[i];
    if (tid < 32) att_sh[tid] = ((const float4*)att)[tid];
    __syncthreads();

    int lane = tid & 31;
    int n = blockIdx.x * 8 + (tid >> 5);
    if (n >= NN) return;
    int beg = g_rowptr[n], end = g_rowptr[n + 1];
    int nreal = end - beg - 1;
    float inv_deg = 1.f / (float)max(nreal, 1);

    float4 xr4    = *(const float4*)(g_xr + (size_t)n * DD + 4 * lane);
    float4 xlself = *(const float4*)(g_xl + (size_t)n * DD + 4 * lane);
    float4 at     = att_sh[lane];
    ull xrp0, xrp1;
    PACK2(xrp0, xr4.x, xr4.y);
    PACK2(xrp1, xr4.z, xr4.w);

    float mxh = -1e30f, den = 0.f;
    float4 acc = make_float4(0, 0, 0, 0);
    float ea_sum = 0.f;

    int npair = nreal & ~1;
    int pair_end = beg + npair;
    int real_end = beg + nreal;

    int2 csA, csB;
    float4 xlA, xlB;
    float rawA = 0.f, rawB = 0.f;
    if (npair > 0) {
        csA = g_csr[beg];       csB = g_csr[beg + 1];
        xlA = *(const float4*)(g_xl + (size_t)csA.x * DD + 4 * lane);
        xlB = *(const float4*)(g_xl + (size_t)csB.x * DD + 4 * lane);
        rawA = (lane < EDIM) ? edge_attr[(size_t)csA.y * EDIM + lane] : 0.f;
        rawB = (lane < EDIM) ? edge_attr[(size_t)csB.y * EDIM + lane] : 0.f;
    } else if (nreal == 1) {
        csA = g_csr[beg];
        xlA = *(const float4*)(g_xl + (size_t)csA.x * DD + 4 * lane);
        rawA = (lane < EDIM) ? edge_attr[(size_t)csA.y * EDIM + lane] : 0.f;
    }

    for (int i = beg; i < pair_end; i += 2) {
        float  myea0 = rawA, myea1 = rawB;
        float4 xl0 = xlA,  xl1 = xlB;
        ea_sum += myea0 + myea1;

        int inext = i + 2;
        if (inext + 1 < real_end) {
            csA = g_csr[inext]; csB = g_csr[inext + 1];
            xlA = *(const float4*)(g_xl + (size_t)csA.x * DD + 4 * lane);
            xlB = *(const float4*)(g_xl + (size_t)csB.x * DD + 4 * lane);
            rawA = (lane < EDIM) ? edge_attr[(size_t)csA.y * EDIM + lane] : 0.f;
            rawB = (lane < EDIM) ? edge_attr[(size_t)csB.y * EDIM + lane] : 0.f;
        } else if (inext < real_end) {
            csA = g_csr[inext];
            xlA = *(const float4*)(g_xl + (size_t)csA.x * DD + 4 * lane);
            rawA = (lane < EDIM) ? edge_attr[(size_t)csA.y * EDIM + lane] : 0.f;
        }

        ull e00 = 0ULL, e01 = 0ULL, e10 = 0ULL, e11 = 0ULL;
#pragma unroll
        for (int k = 0; k < EDIM; k++) {
            float a0 = __shfl_sync(0xffffffffu, myea0, k);
            float a1 = __shfl_sync(0xffffffffu, myea1, k);
            ull d0, d1; DUP2(d0, a0); DUP2(d1, a1);
            ulonglong2 wp = *(const ulonglong2*)&We_sh[k * 32 + lane];
            FFMA2(e00, d0, wp.x); FFMA2(e01, d0, wp.y);
            FFMA2(e10, d1, wp.x); FFMA2(e11, d1, wp.y);
        }
        ull xp0, xp1, yp0, yp1;
        PACK2(xp0, xl0.x, xl0.y); PACK2(xp1, xl0.z, xl0.w);
        PACK2(yp0, xl1.x, xl1.y); PACK2(yp1, xl1.z, xl1.w);
        ull m00, m01, m10, m11;
        FADD2(m00, xp0, xrp0); FADD2(m00, m00, e00);
        FADD2(m01, xp1, xrp1); FADD2(m01, m01, e01);
        FADD2(m10, yp0, xrp0); FADD2(m10, m10, e10);
        FADD2(m11, yp1, xrp1); FADD2(m11, m11, e11);
        float4 u, v;
        UNPK2(u.x, u.y, m00); UNPK2(u.z, u.w, m01);
        UNPK2(v.x, v.y, m10); UNPK2(v.z, v.w, m11);
        u.x = (u.x > 0.f) ? u.x : NEG_SLOPE * u.x;
        u.y = (u.y > 0.f) ? u.y : NEG_SLOPE * u.y;
        u.z = (u.z > 0.f) ? u.z : NEG_SLOPE * u.z;
        u.w = (u.w > 0.f) ? u.w : NEG_SLOPE * u.w;
        v.x = (v.x > 0.f) ? v.x : NEG_SLOPE * v.x;
        v.y = (v.y > 0.f) ? v.y : NEG_SLOPE * v.y;
        v.z = (v.z > 0.f) ? v.z : NEG_SLOPE * v.z;
        v.w = (v.w > 0.f) ? v.w : NEG_SLOPE * v.w;
        float p0 = u.x * at.x + u.y * at.y + u.z * at.z + u.w * at.w;
        float p1 = v.x * at.x + v.y * at.y + v.z * at.z + v.w * at.w;
        p0 += __shfl_xor_sync(0xffffffffu, p0, 1);
        p1 += __shfl_xor_sync(0xffffffffu, p1, 1);
        p0 += __shfl_xor_sync(0xffffffffu, p0, 2);
        p1 += __shfl_xor_sync(0xffffffffu, p1, 2);
        p0 += __shfl_xor_sync(0xffffffffu, p0, 4);
        p1 += __shfl_xor_sync(0xffffffffu, p1, 4);

        float newmx = fmaxf(mxh, fmaxf(p0, p1));
        float s  = __expf(mxh - newmx);
        float a0 = __expf(p0 - newmx);
        float a1 = __expf(p1 - newmx);
        mxh = newmx;
        den = fmaf(den, s, a0 + a1);
        acc.x = fmaf(acc.x, s, fmaf(a0, xl0.x, a1 * xl1.x));
        acc.y = fmaf(acc.y, s, fmaf(a0, xl0.y, a1 * xl1.y));
        acc.z = fmaf(acc.z, s, fmaf(a0, xl0.z, a1 * xl1.z));
        acc.w = fmaf(acc.w, s, fmaf(a0, xl0.w, a1 * xl1.w));
    }

#pragma unroll
    for (int t = 0; t < 2; t++) {
        float myea;
        float4 xlv;
        if (t == 0) {
            if (!(nreal & 1)) continue;
            myea = rawA;
            xlv  = xlA;
            ea_sum += myea;
        } else {
            myea = ea_sum * inv_deg;
            xlv  = xlself;
        }
        ull ee0 = 0ULL, ee1 = 0ULL;
#pragma unroll
        for (int k = 0; k < EDIM; k++) {
            float a = __shfl_sync(0xffffffffu, myea, k);
            ull ad; DUP2(ad, a);
            ulonglong2 wp = *(const ulonglong2*)&We_sh[k * 32 + lane];
            FFMA2(ee0, ad, wp.x);
            FFMA2(ee1, ad, wp.y);
        }
        ull xp0, xp1;
        PACK2(xp0, xlv.x, xlv.y); PACK2(xp1, xlv.z, xlv.w);
        ull m0p, m1p;
        FADD2(m0p, xp0, xrp0); FADD2(m0p, m0p, ee0);
        FADD2(m1p, xp1, xrp1); FADD2(m1p, m1p, ee1);
        float4 m;
        UNPK2(m.x, m.y, m0p); UNPK2(m.z, m.w, m1p);
        m.x = (m.x > 0.f) ? m.x : NEG_SLOPE * m.x;
        m.y = (m.y > 0.f) ? m.y : NEG_SLOPE * m.y;
        m.z = (m.z > 0.f) ? m.z : NEG_SLOPE * m.z;
        m.w = (m.w > 0.f) ? m.w : NEG_SLOPE * m.w;
        float p = m.x * at.x + m.y * at.y + m.z * at.z + m.w * at.w;
        p += __shfl_xor_sync(0xffffffffu, p, 1);
        p += __shfl_xor_sync(0xffffffffu, p, 2);
        p += __shfl_xor_sync(0xffffffffu, p, 4);

        float newmx = fmaxf(mxh, p);
        float s = __expf(mxh - newmx);
        float a = __expf(p - newmx);
        mxh = newmx;
        den = fmaf(den, s, a);
        acc.x = fmaf(acc.x, s, a * xlv.x);
        acc.y = fmaf(acc.y, s, a * xlv.y);
        acc.z = fmaf(acc.z, s, a * xlv.z);
        acc.w = fmaf(acc.w, s, a * xlv.w);
    }

    float inv = 1.f / den;
    float4 cbv = *(const float4*)(cb + 4 * lane);
    float4 o;
    o.x = acc.x * inv + cbv.x;
    o.y = acc.y * inv + cbv.y;
    o.z = acc.z * inv + cbv.z;
    o.w = acc.w * inv + cbv.w;
    o.x = (o.x > 0.f) ? o.x : expm1f(o.x);
    o.y = (o.y > 0.f) ? o.y : expm1f(o.y);
    o.z = (o.z > 0.f) ? o.z : expm1f(o.z);
    o.w = (o.w > 0.f) ? o.w : expm1f(o.w);
    *(float4*)(g_h + (size_t)n * DD + 4 * lane) = o;
}

// ---------------- final: LN + MLP head; warp handles 4 rows ----------------
__global__ __launch_bounds__(256) void k_final(const float* __restrict__ ln_g,
                                               const float* __restrict__ ln_b,
                                               const float* __restrict__ h1w,
                                               const float* __restrict__ h1b,
                                               const float* __restrict__ h2w,
                                               const float* __restrict__ h2b,
                                               float* __restrict__ out) {
    __shared__ ull  W1p[128 * 32];
    __shared__ float W2[64 * 3];
    __shared__ float rowbuf[8][128];
    int tid = threadIdx.x;
    for (int idx = tid; idx < 128 * 32; idx += 256) {
        int k = idx >> 5, c = idx & 31;
        ull p; PACK2(p, h1w[k * 64 + c], h1w[k * 64 + c + 32]);
        W1p[idx] = p;
    }
    if (tid < 64 * 3) W2[tid] = h2w[tid];
    __syncthreads();

    int lane = tid & 31, w = tid >> 5;
    float4 g4 = *(const float4*)(ln_g + 4 * lane);
    float4 b4 = *(const float4*)(ln_b + 4 * lane);
    ull bias01; PACK2(bias01, h1b[lane], h1b[lane + 32]);

    for (int j = 0; j < 4; j++) {
        int n = blockIdx.x * 32 + w * 4 + j;
        if (n >= NN) return;

        float4 hv = *(const float4*)(g_h + (size_t)n * DD + 4 * lane);
        float s = hv.x + hv.y + hv.z + hv.w;
#pragma unroll
        for (int off = 16; off > 0; off >>= 1) s += __shfl_xor_sync(0xffffffffu, s, off);
        float mu = s / 128.f;
        float4 dm = make_float4(hv.x - mu, hv.y - mu, hv.z - mu, hv.w - mu);
        float v = dm.x * dm.x + dm.y * dm.y + dm.z * dm.z + dm.w * dm.w;
#pragma unroll
        for (int off = 16; off > 0; off >>= 1) v += __shfl_xor_sync(0xffffffffu, v, off);
        float r = rsqrtf(v / 128.f + 1e-5f);
        float4 hn;
        hn.x = dm.x * r * g4.x + b4.x;
        hn.y = dm.y * r * g4.y + b4.y;
        hn.z = dm.z * r * g4.z + b4.z;
        hn.w = dm.w * r * g4.w + b4.w;
        *(float4*)&rowbuf[w][4 * lane] = hn;
        __syncwarp();

        ull m01 = bias01;
#pragma unroll 8
        for (int k = 0; k < 128; k++) {
            float a = rowbuf[w][k];
            ull ad; DUP2(ad, a);
            FFMA2(m01, ad, W1p[k * 32 + lane]);
        }
        float m0, m1;
        UNPK2(m0, m1, m01);
        m0 = fmaxf(m0, 0.f);
        m1 = fmaxf(m1, 0.f);
        float p0 = m0 * W2[lane * 3 + 0] + m1 * W2[(lane + 32) * 3 + 0];
        float p1 = m0 * W2[lane * 3 + 1] + m1 * W2[(lane + 32) * 3 + 1];
        float p2 = m0 * W2[lane * 3 + 2] + m1 * W2[(lane + 32) * 3 + 2];
#pragma unroll
        for (int off = 16; off > 0; off >>= 1) {
            p0 += __shfl_xor_sync(0xffffffffu, p0, off);
            p1 += __shfl_xor_sync(0xffffffffu, p1, off);
            p2 += __shfl_xor_sync(0xffffffffu, p2, off);
        }
        if (lane == 0) {
            out[(size_t)n * 3 + 0] = p0 + h2b[0];
            out[(size_t)n * 3 + 1] = p1 + h2b[1];
            out[(size_t)n * 3 + 2] = p2 + h2b[2];
        }
        __syncwarp();
    }
}

// ---------------- host launcher -------------------------------------------
extern "C" void kernel_launch(void* const* d_in, const int* in_sizes, int n_in,
                              void* d_out, int out_size) {
    const float* x         = (const float*)d_in[0];
    const int*   ei_raw    = (const int*)d_in[1];
    const float* edge_attr = (const float*)d_in[2];
    const float* in_w      = (const float*)d_in[3];
    const float* in_b      = (const float*)d_in[4];
    const float* Wl        = (const float*)d_in[5];
    const float* bl        = (const float*)d_in[6];
    const float* Wr        = (const float*)d_in[7];
    const float* br        = (const float*)d_in[8];
    const float* We        = (const float*)d_in[9];
    const float* att       = (const float*)d_in[10];
    const float* cb        = (const float*)d_in[11];
    const float* ln_g      = (const float*)d_in[12];
    const float* ln_b      = (const float*)d_in[13];
    const float* h1w       = (const float*)d_in[14];
    const float* h1b       = (const float*)d_in[15];
    const float* h2w       = (const float*)d_in[16];
    const float* h2b       = (const float*)d_in[17];

    float *hp, *xlp, *xrp;
    cudaGetSymbolAddress((void**)&hp,  g_h);
    cudaGetSymbolAddress((void**)&xlp, g_xl);
    cudaGetSymbolAddress((void**)&xrp, g_xr);

    // launch order keeps k_gemm2 as the 4th launch (ncu capture window).
    k_gemm1<<<(NN + 127) / 128, 256>>>(x, in_w, in_b, hp, NN);
    k_zero<<<(NN + 255) / 256, 256>>>(ei_raw);
    k_cvt_deg<<<(2 * EE + 255) / 256, 256>>>(ei_raw);
    k_gemm2<<<(NN + 63) / 64, 256>>>(hp, Wl, bl, Wr, br, xlp, xrp, NN);   // layer 0
    k_scan<<<1, 1024>>>();
    k_scatter<<<(ETOT + 255) / 256, 256>>>();
    k_attn<<<(NN + 7) / 8, 256>>>(edge_attr, We, att, cb);                 // layer 0

    // layer 1
    k_gemm2<<<(NN + 63) / 64, 256>>>(hp, Wl + 128 * 128, bl + 128,
                                     Wr + 128 * 128, br + 128, xlp, xrp, NN);
    k_attn<<<(NN + 7) / 8, 256>>>(edge_attr, We + EDIM * 128, att + 128, cb + 128);

    k_final<<<(NN + 31) / 32, 256>>>(ln_g, ln_b, h1w, h1b, h2w, h2b, (float*)d_out);
}

// round 14
// speedup vs baseline: 1.7111x; 1.0146x over previous
#include <cuda_runtime.h>
#include <math.h>
#include <stdint.h>

#define NN    50000
#define EE    600000
#define ETOT  (EE + NN)
#define DD    128
#define EDIM  16
#define NEG_SLOPE 0.2f

typedef unsigned long long ull;

// packed f32x2 ops (sm_100+)
#define FFMA2(d, a, b) asm("fma.rn.f32x2 %0, %1, %2, %0;" : "+l"(d) : "l"(a), "l"(b))
#define FADD2(d, a, b) asm("add.rn.f32x2 %0, %1, %2;" : "=l"(d) : "l"(a), "l"(b))
#define DUP2(d, s)     asm("mov.b64 %0, {%1, %1};" : "=l"(d) : "f"(s))
#define PACK2(d, lo, hi) asm("mov.b64 %0, {%1, %2};" : "=l"(d) : "f"(lo), "f"(hi))
#define UNPK2(lo, hi, p) asm("mov.b64 {%0, %1}, %2;" : "=f"(lo), "=f"(hi) : "l"(p))

// tf32 tensor-core mma (m16n8k8, fp32 accumulate)
#define MMA_TF32(d, a, b) \
    asm volatile("mma.sync.aligned.m16n8k8.row.col.f32.tf32.tf32.f32 " \
                 "{%0,%1,%2,%3}, {%4,%5,%6,%7}, {%8,%9}, {%0,%1,%2,%3};" \
                 : "+f"((d)[0]), "+f"((d)[1]), "+f"((d)[2]), "+f"((d)[3]) \
                 : "r"((a).x), "r"((a).y), "r"((a).z), "r"((a).w), \
                   "r"((b).x), "r"((b).y))

__device__ __forceinline__ uint32_t f2tf32(float f) {
    uint32_t r;
    asm("cvt.rna.tf32.f32 %0, %1;" : "=r"(r) : "f"(f));
    return r;
}

#define PREFETCH_L2(p) asm volatile("prefetch.global.L2 [%0];" :: "l"(p))

// ---------------- scratch (static device globals; no allocs allowed) -------
__device__ __align__(16) float g_h[NN * DD];
__device__ __align__(16) float g_xl[NN * DD];
__device__ __align__(16) float g_xr[NN * DD];
__device__ __align__(16) uint32_t g_wfrag[5 * 16384];  // tf32 fragment layout
__device__ int   g_src[EE];
__device__ int   g_dst[EE];
__device__ int   g_deg[NN];
__device__ int   g_fill[NN];
__device__ int   g_rowptr[NN + 1];
__device__ int2  g_csr[ETOT];   // .x = src node, .y = edge id (self loop LAST in bucket)
__device__ int   g_is64;

// ---------------- weight pre-conversion to tf32 fragment layout ------------
// frag index within a matrix: (((kc*4+ks)*16+j)*32+ln)*2+rg
__global__ void k_wprep(const float* __restrict__ in_w,
                        const float* __restrict__ Wl,
                        const float* __restrict__ Wr) {
    int mat = blockIdx.x;           // 0=in_w, 1=Wl0, 2=Wr0, 3=Wl1, 4=Wr1
    const float* W = (mat == 0) ? in_w
                   : (mat == 1) ? Wl : (mat == 2) ? Wr
                   : (mat == 3) ? (Wl + 16384) : (Wr + 16384);
    for (int idx = threadIdx.x; idx < 16384; idx += 256) {
        int k = idx >> 7, n = idx & 127;
        int kc = k >> 5, kq = k & 31, ks = kq >> 3, k8 = kq & 7;
        int j = n >> 3, n8 = n & 7;
        int ln = (n8 << 2) | (k8 & 3), rg = k8 >> 2;
        g_wfrag[mat * 16384 + (((kc * 4 + ks) * 16 + j) * 32 + ln) * 2 + rg] =
            f2tf32(W[k * 128 + n]);
    }
}

// ---------------- zero + index dtype detection -----------------------------
__global__ void k_zero(const int* __restrict__ ei_raw) {
    int i = blockIdx.x * blockDim.x + threadIdx.x;
    if (i < NN) { g_deg[i] = 0; g_fill[i] = 0; }
    if (i == 0) {
        int all0 = 1;
        for (int t = 0; t < 64; t++)
            if (ei_raw[2 * t + 1] != 0) { all0 = 0; break; }
        g_is64 = all0;
    }
}

__global__ void k_cvt_deg(const int* __restrict__ ei_raw) {
    int i = blockIdx.x * blockDim.x + threadIdx.x;
    if (i >= 2 * EE) return;
    int v = g_is64 ? ei_raw[2 * i] : ei_raw[i];
    if (i < EE) {
        g_src[i] = v;
    } else {
        g_dst[i - EE] = v;
        atomicAdd(&g_deg[v], 1);
    }
}

// single-block scan of (deg+1) -> rowptr
__global__ __launch_bounds__(1024) void k_scan() {
    __shared__ int warp_tot[32];
    __shared__ int s_carry;
    int tid = threadIdx.x, lane = tid & 31, wid = tid >> 5;
    if (tid == 0) { s_carry = 0; g_rowptr[0] = 0; }
    __syncthreads();
    for (int base = 0; base < NN; base += 4096) {
        int idx0 = base + tid * 4;
        int v[4], s = 0;
#pragma unroll
        for (int t = 0; t < 4; t++) {
            int i = idx0 + t;
            v[t] = (i < NN) ? (g_deg[i] + 1) : 0;
            s += v[t];
        }
        int ss = s;
#pragma unroll
        for (int off = 1; off < 32; off <<= 1) {
            int t = __shfl_up_sync(0xffffffffu, ss, off);
            if (lane >= off) ss += t;
        }
        if (lane == 31) warp_tot[wid] = ss;
        __syncthreads();
        if (wid == 0) {
            int wv = warp_tot[lane];
#pragma unroll
            for (int off = 1; off < 32; off <<= 1) {
                int t = __shfl_up_sync(0xffffffffu, wv, off);
                if (lane >= off) wv += t;
            }
            warp_tot[lane] = wv;
        }
        __syncthreads();
        int warp_prefix = (wid == 0) ? 0 : warp_tot[wid - 1];
        int run = s_carry + warp_prefix + (ss - s);
#pragma unroll
        for (int t = 0; t < 4; t++) {
            run += v[t];
            if (idx0 + t < NN) g_rowptr[idx0 + t + 1] = run;
        }
        __syncthreads();
        if (tid == 0) s_carry += warp_tot[31];
        __syncthreads();
    }
}

__global__ void k_scatter() {
    int i = blockIdx.x * blockDim.x + threadIdx.x;
    if (i < EE) {
        int d = g_dst[i];
        int p = atomicAdd(&g_fill[d], 1);
        g_csr[g_rowptr[d] + p] = make_int2(g_src[i], i);
    } else if (i < ETOT) {
        int n = i - EE;
        g_csr[g_rowptr[n] + g_deg[n]] = make_int2(n, EE + n);  // self loop LAST
    }
}

// ---------------- TC GEMM single: out[M,128] = A@W + b (tf32 mma) ----------
__global__ __launch_bounds__(256) void k_gemm1(const float* __restrict__ A,
                                               int mat,
                                               const float* __restrict__ bias,
                                               float* __restrict__ out, int M) {
    __shared__ uint32_t A_sh[8][4][32][4];   // [wm][ks][lane][reg] 16 KB
    __shared__ uint32_t W_sh[4][16][32][2];  // [ks][j][lane][reg]  16 KB
    int tid = threadIdx.x;
    int w = tid >> 5, lane = tid & 31;
    int row0 = blockIdx.x * 128;

    float acc[16][4];
#pragma unroll
    for (int j = 0; j < 16; j++)
#pragma unroll
        for (int c = 0; c < 4; c++) acc[j][c] = 0.f;

    for (int kc = 0; kc < 4; kc++) {
        // stage A chunk (128 x 32) into fragment layout (per-block unique)
#pragma unroll
        for (int i = 0; i < 16; i++) {
            int idx = tid + i * 256;
            int r = idx >> 5, kq = idx & 31;
            int grow = row0 + r;
            float v = (grow < M) ? A[(size_t)grow * 128 + kc * 32 + kq] : 0.f;
            int ks = kq >> 3, k8 = kq & 7;
            int ln = ((r & 7) << 2) | (k8 & 3);
            int rg = ((r >> 3) & 1) | ((k8 >> 2) << 1);
            A_sh[r >> 4][ks][ln][rg] = f2tf32(v);
        }
        // stage W chunk: straight vector copy of pre-converted fragments
        {
            const uint4* src = (const uint4*)(g_wfrag + mat * 16384 + kc * 4096);
            uint4* dst = (uint4*)&W_sh[0][0][0][0];
#pragma unroll
            for (int t = 0; t < 4; t++) dst[tid + t * 256] = src[tid + t * 256];
        }
        __syncthreads();
#pragma unroll
        for (int ks = 0; ks < 4; ks++) {
            uint4 af = *(const uint4*)&A_sh[w][ks][lane][0];
#pragma unroll
            for (int j = 0; j < 16; j++) {
                uint2 bf = *(const uint2*)&W_sh[ks][j][lane][0];
                MMA_TF32(acc[j], af, bf);
            }
        }
        __syncthreads();
    }
    int r0 = row0 + w * 16 + (lane >> 2);
    int r1 = r0 + 8;
    int cbase = 2 * (lane & 3);
#pragma unroll
    for (int j = 0; j < 16; j++) {
        int c = j * 8 + cbase;
        float bz0 = bias[c], bz1 = bias[c + 1];
        if (r0 < M)
            *(float2*)(out + (size_t)r0 * 128 + c) = make_float2(acc[j][0] + bz0, acc[j][1] + bz1);
        if (r1 < M)
            *(float2*)(out + (size_t)r1 * 128 + c) = make_float2(acc[j][2] + bz0, acc[j][3] + bz1);
    }
}

// ---------------- TC GEMM dual: xl = A@W1+b1, xr = A@W2+b2 (tf32 mma) ------
__global__ __launch_bounds__(256) void k_gemm2(const float* __restrict__ A,
                                               int mat1,
                                               const float* __restrict__ b1,
                                               int mat2,
                                               const float* __restrict__ b2,
                                               float* __restrict__ out1,
                                               float* __restrict__ out2, int M) {
    __shared__ uint32_t A_sh[4][4][32][4];     // [wm][ks][lane][reg]       8 KB
    __shared__ uint32_t Wsh[2][4][16][32][2];  // [sel][ks][j][lane][reg]  32 KB
    int tid = threadIdx.x;
    int w = tid >> 5, lane = tid & 31;
    int wm = w & 3, sel = w >> 2;
    int row0 = blockIdx.x * 64;

    float acc[16][4];
#pragma unroll
    for (int j = 0; j < 16; j++)
#pragma unroll
        for (int c = 0; c < 4; c++) acc[j][c] = 0.f;

    for (int kc = 0; kc < 4; kc++) {
        // stage A chunk (64 x 32)
#pragma unroll
        for (int i = 0; i < 8; i++) {
            int idx = tid + i * 256;
            int r = idx >> 5, kq = idx & 31;
            int grow = row0 + r;
            float v = (grow < M) ? A[(size_t)grow * 128 + kc * 32 + kq] : 0.f;
            int ks = kq >> 3, k8 = kq & 7;
            int ln = ((r & 7) << 2) | (k8 & 3);
            int rg = ((r >> 3) & 1) | ((k8 >> 2) << 1);
            A_sh[r >> 4][ks][ln][rg] = f2tf32(v);
        }
        // stage W1 + W2 fragment chunks: vector copies
        {
            const uint4* s1 = (const uint4*)(g_wfrag + mat1 * 16384 + kc * 4096);
            const uint4* s2 = (const uint4*)(g_wfrag + mat2 * 16384 + kc * 4096);
            uint4* d1 = (uint4*)&Wsh[0][0][0][0][0];
            uint4* d2 = (uint4*)&Wsh[1][0][0][0][0];
#pragma unroll
            for (int t = 0; t < 4; t++) {
                d1[tid + t * 256] = s1[tid + t * 256];
                d2[tid + t * 256] = s2[tid + t * 256];
            }
        }
        __syncthreads();
#pragma unroll
        for (int ks = 0; ks < 4; ks++) {
            uint4 af = *(const uint4*)&A_sh[wm][ks][lane][0];
#pragma unroll
            for (int j = 0; j < 16; j++) {
                uint2 bf = *(const uint2*)&Wsh[sel][ks][j][lane][0];
                MMA_TF32(acc[j], af, bf);
            }
        }
        __syncthreads();
    }
    const float* bias = sel ? b2 : b1;
    float* out = sel ? out2 : out1;
    int r0 = row0 + wm * 16 + (lane >> 2);
    int r1 = r0 + 8;
    int cbase = 2 * (lane & 3);
#pragma unroll
    for (int j = 0; j < 16; j++) {
        int c = j * 8 + cbase;
        float bz0 = bias[c], bz1 = bias[c + 1];
        if (r0 < M)
            *(float2*)(out + (size_t)r0 * 128 + c) = make_float2(acc[j][0] + bz0, acc[j][1] + bz1);
        if (r1 < M)
            *(float2*)(out + (size_t)r1 * 128 + c) = make_float2(acc[j][2] + bz0, acc[j][3] + bz1);
    }
}

// ---------------- fused attention: 2-edge ILP + L2 prefetch ----------------
__global__ __launch_bounds__(256) void k_attn(const float* __restrict__ edge_attr,
                                              const float* __restrict__ We,
                                              const float* __restrict__ att,
                                              const float* __restrict__ cb) {
    __shared__ float4 We_sh[EDIM * 32];   // [k][lane] = We[k][4*lane..+3]
    __shared__ float4 att_sh[32];
    int tid = threadIdx.x;
    for (int i = tid; i < EDIM * 32; i += 256) We_sh[i] = ((const float4*)We)[i];
    if (tid < 32) att_sh[tid] = ((const float4*)att)[tid];
    __syncthreads();

    int lane = tid & 31;
    int n = blockIdx.x * 8 + (tid >> 5);
    if (n >= NN) return;
    int beg = g_rowptr[n], end = g_rowptr[n + 1];
    int nreal = end - beg - 1;
    float inv_deg = 1.f / (float)max(nreal, 1);

    float4 xr4    = *(const float4*)(g_xr + (size_t)n * DD + 4 * lane);
    float4 xlself = *(const float4*)(g_xl + (size_t)n * DD + 4 * lane);
    float4 at     = att_sh[lane];
    ull xrp0, xrp1;
    PACK2(xrp0, xr4.x, xr4.y);
    PACK2(xrp1, xr4.z, xr4.w);

    float mxh = -1e30f, den = 0.f;
    float4 acc = make_float4(0, 0, 0, 0);
    float ea_sum = 0.f;

    int npair = nreal & ~1;
    int pair_end = beg + npair;
    int real_end = beg + nreal;

    int2 csA, csB;
    float4 xlA, xlB;
    float rawA = 0.f, rawB = 0.f;
    if (npair > 0) {
        csA = g_csr[beg];       csB = g_csr[beg + 1];
        xlA = *(const float4*)(g_xl + (size_t)csA.x * DD + 4 * lane);
        xlB = *(const float4*)(g_xl + (size_t)csB.x * DD + 4 * lane);
        rawA = (lane < EDIM) ? edge_attr[(size_t)csA.y * EDIM + lane] : 0.f;
        rawB = (lane < EDIM) ? edge_attr[(size_t)csB.y * EDIM + lane] : 0.f;
    } else if (nreal == 1) {
        csA = g_csr[beg];
        xlA = *(const float4*)(g_xl + (size_t)csA.x * DD + 4 * lane);
        rawA = (lane < EDIM) ? edge_attr[(size_t)csA.y * EDIM + lane] : 0.f;
    }

    for (int i = beg; i < pair_end; i += 2) {
        float  myea0 = rawA, myea1 = rawB;
        float4 xl0 = xlA,  xl1 = xlB;
        ea_sum += myea0 + myea1;

        // stage next pair (1 ahead)
        int inext = i + 2;
        if (inext + 1 < real_end) {
            csA = g_csr[inext]; csB = g_csr[inext + 1];
            xlA = *(const float4*)(g_xl + (size_t)csA.x * DD + 4 * lane);
            xlB = *(const float4*)(g_xl + (size_t)csB.x * DD + 4 * lane);
            rawA = (lane < EDIM) ? edge_attr[(size_t)csA.y * EDIM + lane] : 0.f;
            rawB = (lane < EDIM) ? edge_attr[(size_t)csB.y * EDIM + lane] : 0.f;
        } else if (inext < real_end) {
            csA = g_csr[inext];
            xlA = *(const float4*)(g_xl + (size_t)csA.x * DD + 4 * lane);
            rawA = (lane < EDIM) ? edge_attr[(size_t)csA.y * EDIM + lane] : 0.f;
        }

        // L2 prefetch (2 pairs ahead) — no registers held, hides DRAM depth
        if (i + 4 < real_end) {
            int2 c4 = g_csr[i + 4];
            PREFETCH_L2(g_xl + (size_t)c4.x * DD + 4 * lane);
            if (lane == 0) PREFETCH_L2(edge_attr + (size_t)c4.y * EDIM);
            if (i + 5 < real_end) {
                int2 c5 = g_csr[i + 5];
                PREFETCH_L2(g_xl + (size_t)c5.x * DD + 4 * lane);
                if (lane == 0) PREFETCH_L2(edge_attr + (size_t)c5.y * EDIM);
            }
        }

        ull e00 = 0ULL, e01 = 0ULL, e10 = 0ULL, e11 = 0ULL;
#pragma unroll
        for (int k = 0; k < EDIM; k++) {
            float a0 = __shfl_sync(0xffffffffu, myea0, k);
            float a1 = __shfl_sync(0xffffffffu, myea1, k);
            ull d0, d1; DUP2(d0, a0); DUP2(d1, a1);
            ulonglong2 wp = *(const ulonglong2*)&We_sh[k * 32 + lane];
            FFMA2(e00, d0, wp.x); FFMA2(e01, d0, wp.y);
            FFMA2(e10, d1, wp.x); FFMA2(e11, d1, wp.y);
        }
        ull xp0, xp1, yp0, yp1;
        PACK2(xp0, xl0.x, xl0.y); PACK2(xp1, xl0.z, xl0.w);
        PACK2(yp0, xl1.x, xl1.y); PACK2(yp1, xl1.z, xl1.w);
        ull m00, m01, m10, m11;
        FADD2(m00, xp0, xrp0); FADD2(m00, m00, e00);
        FADD2(m01, xp1, xrp1); FADD2(m01, m01, e01);
        FADD2(m10, yp0, xrp0); FADD2(m10, m10, e10);
        FADD2(m11, yp1, xrp1); FADD2(m11, m11, e11);
        float4 u, v;
        UNPK2(u.x, u.y, m00); UNPK2(u.z, u.w, m01);
        UNPK2(v.x, v.y, m10); UNPK2(v.z, v.w, m11);
        u.x = (u.x > 0.f) ? u.x : NEG_SLOPE * u.x;
        u.y = (u.y > 0.f) ? u.y : NEG_SLOPE * u.y;
        u.z = (u.z > 0.f) ? u.z : NEG_SLOPE * u.z;
        u.w = (u.w > 0.f) ? u.w : NEG_SLOPE * u.w;
        v.x = (v.x > 0.f) ? v.x : NEG_SLOPE * v.x;
        v.y = (v.y > 0.f) ? v.y : NEG_SLOPE * v.y;
        v.z = (v.z > 0.f) ? v.z : NEG_SLOPE * v.z;
        v.w = (v.w > 0.f) ? v.w : NEG_SLOPE * v.w;
        float p0 = u.x * at.x + u.y * at.y + u.z * at.z + u.w * at.w;
        float p1 = v.x * at.x + v.y * at.y + v.z * at.z + v.w * at.w;
        p0 += __shfl_xor_sync(0xffffffffu, p0, 1);
        p1 += __shfl_xor_sync(0xffffffffu, p1, 1);
        p0 += __shfl_xor_sync(0xffffffffu, p0, 2);
        p1 += __shfl_xor_sync(0xffffffffu, p1, 2);
        p0 += __shfl_xor_sync(0xffffffffu, p0, 4);
        p1 += __shfl_xor_sync(0xffffffffu, p1, 4);

        float newmx = fmaxf(mxh, fmaxf(p0, p1));
        float s  = __expf(mxh - newmx);
        float a0 = __expf(p0 - newmx);
        float a1 = __expf(p1 - newmx);
        mxh = newmx;
        den = fmaf(den, s, a0 + a1);
        acc.x = fmaf(acc.x, s, fmaf(a0, xl0.x, a1 * xl1.x));
        acc.y = fmaf(acc.y, s, fmaf(a0, xl0.y, a1 * xl1.y));
        acc.z = fmaf(acc.z, s, fmaf(a0, xl0.z, a1 * xl1.z));
        acc.w = fmaf(acc.w, s, fmaf(a0, xl0.w, a1 * xl1.w));
    }

#pragma unroll
    for (int t = 0; t < 2; t++) {
        float myea;
        float4 xlv;
        if (t == 0) {
            if (!(nreal & 1)) continue;
            myea = rawA;
            xlv  = xlA;
            ea_sum += myea;
        } else {
            myea = ea_sum * inv_deg;
            xlv  = xlself;
        }
        ull ee0 = 0ULL, ee1 = 0ULL;
#pragma unroll
        for (int k = 0; k < EDIM; k++) {
            float a = __shfl_sync(0xffffffffu, myea, k);
            ull ad; DUP2(ad, a);
            ulonglong2 wp = *(const ulonglong2*)&We_sh[k * 32 + lane];
            FFMA2(ee0, ad, wp.x);
            FFMA2(ee1, ad, wp.y);
        }
        ull xp0, xp1;
        PACK2(xp0, xlv.x, xlv.y); PACK2(xp1, xlv.z, xlv.w);
        ull m0p, m1p;
        FADD2(m0p, xp0, xrp0); FADD2(m0p, m0p, ee0);
        FADD2(m1p, xp1, xrp1); FADD2(m1p, m1p, ee1);
        float4 m;
        UNPK2(m.x, m.y, m0p); UNPK2(m.z, m.w, m1p);
        m.x = (m.x > 0.f) ? m.x : NEG_SLOPE * m.x;
        m.y = (m.y > 0.f) ? m.y : NEG_SLOPE * m.y;
        m.z = (m.z > 0.f) ? m.z : NEG_SLOPE * m.z;
        m.w = (m.w > 0.f) ? m.w : NEG_SLOPE * m.w;
        float p = m.x * at.x + m.y * at.y + m.z * at.z + m.w * at.w;
        p += __shfl_xor_sync(0xffffffffu, p, 1);
        p += __shfl_xor_sync(0xffffffffu, p, 2);
        p += __shfl_xor_sync(0xffffffffu, p, 4);

        float newmx = fmaxf(mxh, p);
        float s = __expf(mxh - newmx);
        float a = __expf(p - newmx);
        mxh = newmx;
        den = fmaf(den, s, a);
        acc.x = fmaf(acc.x, s, a * xlv.x);
        acc.y = fmaf(acc.y, s, a * xlv.y);
        acc.z = fmaf(acc.z, s, a * xlv.z);
        acc.w = fmaf(acc.w, s, a * xlv.w);
    }

    float inv = 1.f / den;
    float4 cbv = *(const float4*)(cb + 4 * lane);
    float4 o;
    o.x = acc.x * inv + cbv.x;
    o.y = acc.y * inv + cbv.y;
    o.z = acc.z * inv + cbv.z;
    o.w = acc.w * inv + cbv.w;
    o.x = (o.x > 0.f) ? o.x : expm1f(o.x);
    o.y = (o.y > 0.f) ? o.y : expm1f(o.y);
    o.z = (o.z > 0.f) ? o.z : expm1f(o.z);
    o.w = (o.w > 0.f) ? o.w : expm1f(o.w);
    *(float4*)(g_h + (size_t)n * DD + 4 * lane) = o;
}

// ---------------- final: LN + MLP head; warp handles 4 rows ----------------
__global__ __launch_bounds__(256) void k_final(const float* __restrict__ ln_g,
                                               const float* __restrict__ ln_b,
                                               const float* __restrict__ h1w,
                                               const float* __restrict__ h1b,
                                               const float* __restrict__ h2w,
                                               const float* __restrict__ h2b,
                                               float* __restrict__ out) {
    __shared__ ull  W1p[128 * 32];
    __shared__ float W2[64 * 3];
    __shared__ float rowbuf[8][128];
    int tid = threadIdx.x;
    for (int idx = tid; idx < 128 * 32; idx += 256) {
        int k = idx >> 5, c = idx & 31;
        ull p; PACK2(p, h1w[k * 64 + c], h1w[k * 64 + c + 32]);
        W1p[idx] = p;
    }
    if (tid < 64 * 3) W2[tid] = h2w[tid];
    __syncthreads();

    int lane = tid & 31, w = tid >> 5;
    float4 g4 = *(const float4*)(ln_g + 4 * lane);
    float4 b4 = *(const float4*)(ln_b + 4 * lane);
    ull bias01; PACK2(bias01, h1b[lane], h1b[lane + 32]);

    for (int j = 0; j < 4; j++) {
        int n = blockIdx.x * 32 + w * 4 + j;
        if (n >= NN) return;

        float4 hv = *(const float4*)(g_h + (size_t)n * DD + 4 * lane);
        float s = hv.x + hv.y + hv.z + hv.w;
#pragma unroll
        for (int off = 16; off > 0; off >>= 1) s += __shfl_xor_sync(0xffffffffu, s, off);
        float mu = s / 128.f;
        float4 dm = make_float4(hv.x - mu, hv.y - mu, hv.z - mu, hv.w - mu);
        float v = dm.x * dm.x + dm.y * dm.y + dm.z * dm.z + dm.w * dm.w;
#pragma unroll
        for (int off = 16; off > 0; off >>= 1) v += __shfl_xor_sync(0xffffffffu, v, off);
        float r = rsqrtf(v / 128.f + 1e-5f);
        float4 hn;
        hn.x = dm.x * r * g4.x + b4.x;
        hn.y = dm.y * r * g4.y + b4.y;
        hn.z = dm.z * r * g4.z + b4.z;
        hn.w = dm.w * r * g4.w + b4.w;
        *(float4*)&rowbuf[w][4 * lane] = hn;
        __syncwarp();

        ull m01 = bias01;
#pragma unroll 8
        for (int k = 0; k < 128; k++) {
            float a = rowbuf[w][k];
            ull ad; DUP2(ad, a);
            FFMA2(m01, ad, W1p[k * 32 + lane]);
        }
        float m0, m1;
        UNPK2(m0, m1, m01);
        m0 = fmaxf(m0, 0.f);
        m1 = fmaxf(m1, 0.f);
        float p0 = m0 * W2[lane * 3 + 0] + m1 * W2[(lane + 32) * 3 + 0];
        float p1 = m0 * W2[lane * 3 + 1] + m1 * W2[(lane + 32) * 3 + 1];
        float p2 = m0 * W2[lane * 3 + 2] + m1 * W2[(lane + 32) * 3 + 2];
#pragma unroll
        for (int off = 16; off > 0; off >>= 1) {
            p0 += __shfl_xor_sync(0xffffffffu, p0, off);
            p1 += __shfl_xor_sync(0xffffffffu, p1, off);
            p2 += __shfl_xor_sync(0xffffffffu, p2, off);
        }
        if (lane == 0) {
            out[(size_t)n * 3 + 0] = p0 + h2b[0];
            out[(size_t)n * 3 + 1] = p1 + h2b[1];
            out[(size_t)n * 3 + 2] = p2 + h2b[2];
        }
        __syncwarp();
    }
}

// ---------------- host launcher -------------------------------------------
extern "C" void kernel_launch(void* const* d_in, const int* in_sizes, int n_in,
                              void* d_out, int out_size) {
    const float* x         = (const float*)d_in[0];
    const int*   ei_raw    = (const int*)d_in[1];
    const float* edge_attr = (const float*)d_in[2];
    const float* in_w      = (const float*)d_in[3];
    const float* in_b      = (const float*)d_in[4];
    const float* Wl        = (const float*)d_in[5];
    const float* bl        = (const float*)d_in[6];
    const float* Wr        = (const float*)d_in[7];
    const float* br        = (const float*)d_in[8];
    const float* We        = (const float*)d_in[9];
    const float* att       = (const float*)d_in[10];
    const float* cb        = (const float*)d_in[11];
    const float* ln_g      = (const float*)d_in[12];
    const float* ln_b      = (const float*)d_in[13];
    const float* h1w       = (const float*)d_in[14];
    const float* h1b       = (const float*)d_in[15];
    const float* h2w       = (const float*)d_in[16];
    const float* h2b       = (const float*)d_in[17];

    float *hp, *xlp, *xrp;
    cudaGetSymbolAddress((void**)&hp,  g_h);
    cudaGetSymbolAddress((void**)&xlp, g_xl);
    cudaGetSymbolAddress((void**)&xrp, g_xr);

    // order keeps k_gemm2 as the 4th launch (ncu capture window).
    k_wprep<<<5, 256>>>(in_w, Wl, Wr);
    k_gemm1<<<(NN + 127) / 128, 256>>>(x, 0, in_b, hp, NN);
    k_zero<<<(NN + 255) / 256, 256>>>(ei_raw);
    k_gemm2<<<(NN + 63) / 64, 256>>>(hp, 1, bl, 2, br, xlp, xrp, NN);   // layer 0
    k_cvt_deg<<<(2 * EE + 255) / 256, 256>>>(ei_raw);
    k_scan<<<1, 1024>>>();
    k_scatter<<<(ETOT + 255) / 256, 256>>>();
    k_attn<<<(NN + 7) / 8, 256>>>(edge_attr, We, att, cb);               // layer 0

    // layer 1
    k_gemm2<<<(NN + 63) / 64, 256>>>(hp, 3, bl + 128, 4, br + 128, xlp, xrp, NN);
    k_attn<<<(NN + 7) / 8, 256>>>(edge_attr, We + EDIM * 128, att + 128, cb + 128);

    k_final<<<(NN + 31) / 32, 256>>>(ln_g, ln_b, h1w, h1b, h2w, h2b, (float*)d_out);
}

// round 16
// speedup vs baseline: 1.7522x; 1.0241x over previous
#include <cuda_runtime.h>
#include <math.h>
#include <stdint.h>

#define NN    50000
#define EE    600000
#define ETOT  (EE + NN)
#define DD    128
#define EDIM  16
#define NEG_SLOPE 0.2f

typedef unsigned long long ull;

// packed f32x2 ops (sm_100+)
#define FFMA2(d, a, b) asm("fma.rn.f32x2 %0, %1, %2, %0;" : "+l"(d) : "l"(a), "l"(b))
#define FADD2(d, a, b) asm("add.rn.f32x2 %0, %1, %2;" : "=l"(d) : "l"(a), "l"(b))
#define DUP2(d, s)     asm("mov.b64 %0, {%1, %1};" : "=l"(d) : "f"(s))
#define PACK2(d, lo, hi) asm("mov.b64 %0, {%1, %2};" : "=l"(d) : "f"(lo), "f"(hi))
#define UNPK2(lo, hi, p) asm("mov.b64 {%0, %1}, %2;" : "=f"(lo), "=f"(hi) : "l"(p))

// tf32 tensor-core mma (m16n8k8, fp32 accumulate)
#define MMA_TF32(d, a, b) \
    asm volatile("mma.sync.aligned.m16n8k8.row.col.f32.tf32.tf32.f32 " \
                 "{%0,%1,%2,%3}, {%4,%5,%6,%7}, {%8,%9}, {%0,%1,%2,%3};" \
                 : "+f"((d)[0]), "+f"((d)[1]), "+f"((d)[2]), "+f"((d)[3]) \
                 : "r"((a).x), "r"((a).y), "r"((a).z), "r"((a).w), \
                   "r"((b).x), "r"((b).y))

__device__ __forceinline__ uint32_t f2tf32(float f) {
    uint32_t r;
    asm("cvt.rna.tf32.f32 %0, %1;" : "=r"(r) : "f"(f));
    return r;
}

// ---------------- scratch (static device globals; no allocs allowed) -------
__device__ __align__(16) float g_h[NN * DD];
__device__ __align__(16) float g_xl[NN * DD];
__device__ __align__(16) float g_xr[NN * DD];
__device__ __align__(16) uint32_t g_wfrag[5 * 16384];  // tf32 fragment layout
__device__ int   g_src[EE];
__device__ int   g_dst[EE];
__device__ int   g_deg[NN];
__device__ int   g_fill[NN];
__device__ int   g_rowptr[NN + 1];
__device__ int2  g_csr[ETOT];   // .x = src node, .y = edge id (self loop LAST in bucket)
__device__ int   g_is64;

// ---------------- weight pre-conversion to tf32 fragment layout ------------
// frag index within a matrix: (((kc*4+ks)*16+j)*32+ln)*2+rg
__global__ void k_wprep(const float* __restrict__ in_w,
                        const float* __restrict__ Wl,
                        const float* __restrict__ Wr) {
    int mat = blockIdx.x;           // 0=in_w, 1=Wl0, 2=Wr0, 3=Wl1, 4=Wr1
    const float* W = (mat == 0) ? in_w
                   : (mat == 1) ? Wl : (mat == 2) ? Wr
                   : (mat == 3) ? (Wl + 16384) : (Wr + 16384);
    for (int idx = threadIdx.x; idx < 16384; idx += 256) {
        int k = idx >> 7, n = idx & 127;
        int kc = k >> 5, kq = k & 31, ks = kq >> 3, k8 = kq & 7;
        int j = n >> 3, n8 = n & 7;
        int ln = (n8 << 2) | (k8 & 3), rg = k8 >> 2;
        g_wfrag[mat * 16384 + (((kc * 4 + ks) * 16 + j) * 32 + ln) * 2 + rg] =
            f2tf32(W[k * 128 + n]);
    }
}

// ---------------- zero + index dtype detection -----------------------------
__global__ void k_zero(const int* __restrict__ ei_raw) {
    int i = blockIdx.x * blockDim.x + threadIdx.x;
    if (i < NN) { g_deg[i] = 0; g_fill[i] = 0; }
    if (i == 0) {
        int all0 = 1;
        for (int t = 0; t < 64; t++)
            if (ei_raw[2 * t + 1] != 0) { all0 = 0; break; }
        g_is64 = all0;
    }
}

__global__ void k_cvt_deg(const int* __restrict__ ei_raw) {
    int i = blockIdx.x * blockDim.x + threadIdx.x;
    if (i >= 2 * EE) return;
    int v = g_is64 ? ei_raw[2 * i] : ei_raw[i];
    if (i < EE) {
        g_src[i] = v;
    } else {
        g_dst[i - EE] = v;
        atomicAdd(&g_deg[v], 1);
    }
}

// single-block scan of (deg+1) -> rowptr
__global__ __launch_bounds__(1024) void k_scan() {
    __shared__ int warp_tot[32];
    __shared__ int s_carry;
    int tid = threadIdx.x, lane = tid & 31, wid = tid >> 5;
    if (tid == 0) { s_carry = 0; g_rowptr[0] = 0; }
    __syncthreads();
    for (int base = 0; base < NN; base += 4096) {
        int idx0 = base + tid * 4;
        int v[4], s = 0;
#pragma unroll
        for (int t = 0; t < 4; t++) {
            int i = idx0 + t;
            v[t] = (i < NN) ? (g_deg[i] + 1) : 0;
            s += v[t];
        }
        int ss = s;
#pragma unroll
        for (int off = 1; off < 32; off <<= 1) {
            int t = __shfl_up_sync(0xffffffffu, ss, off);
            if (lane >= off) ss += t;
        }
        if (lane == 31) warp_tot[wid] = ss;
        __syncthreads();
        if (wid == 0) {
            int wv = warp_tot[lane];
#pragma unroll
            for (int off = 1; off < 32; off <<= 1) {
                int t = __shfl_up_sync(0xffffffffu, wv, off);
                if (lane >= off) wv += t;
            }
            warp_tot[lane] = wv;
        }
        __syncthreads();
        int warp_prefix = (wid == 0) ? 0 : warp_tot[wid - 1];
        int run = s_carry + warp_prefix + (ss - s);
#pragma unroll
        for (int t = 0; t < 4; t++) {
            run += v[t];
            if (idx0 + t < NN) g_rowptr[idx0 + t + 1] = run;
        }
        __syncthreads();
        if (tid == 0) s_carry += warp_tot[31];
        __syncthreads();
    }
}

__global__ void k_scatter() {
    int i = blockIdx.x * blockDim.x + threadIdx.x;
    if (i < EE) {
        int d = g_dst[i];
        int p = atomicAdd(&g_fill[d], 1);
        g_csr[g_rowptr[d] + p] = make_int2(g_src[i], i);
    } else if (i < ETOT) {
        int n = i - EE;
        g_csr[g_rowptr[n] + g_deg[n]] = make_int2(n, EE + n);  // self loop LAST
    }
}

// ---------------- TC GEMM single: out[M,128] = A@W + b (tf32 mma) ----------
__global__ __launch_bounds__(256) void k_gemm1(const float* __restrict__ A,
                                               int mat,
                                               const float* __restrict__ bias,
                                               float* __restrict__ out, int M) {
    __shared__ uint32_t A_sh[8][4][32][4];   // [wm][ks][lane][reg] 16 KB
    __shared__ uint32_t W_sh[4][16][32][2];  // [ks][j][lane][reg]  16 KB
    int tid = threadIdx.x;
    int w = tid >> 5, lane = tid & 31;
    int row0 = blockIdx.x * 128;

    float acc[16][4];
#pragma unroll
    for (int j = 0; j < 16; j++)
#pragma unroll
        for (int c = 0; c < 4; c++) acc[j][c] = 0.f;

    for (int kc = 0; kc < 4; kc++) {
        // stage A chunk (128 x 32) into fragment layout (per-block unique)
#pragma unroll
        for (int i = 0; i < 16; i++) {
            int idx = tid + i * 256;
            int r = idx >> 5, kq = idx & 31;
            int grow = row0 + r;
            float v = (grow < M) ? A[(size_t)grow * 128 + kc * 32 + kq] : 0.f;
            int ks = kq >> 3, k8 = kq & 7;
            int ln = ((r & 7) << 2) | (k8 & 3);
            int rg = ((r >> 3) & 1) | ((k8 >> 2) << 1);
            A_sh[r >> 4][ks][ln][rg] = f2tf32(v);
        }
        // stage W chunk: straight vector copy of pre-converted fragments
        {
            const uint4* src = (const uint4*)(g_wfrag + mat * 16384 + kc * 4096);
            uint4* dst = (uint4*)&W_sh[0][0][0][0];
#pragma unroll
            for (int t = 0; t < 4; t++) dst[tid + t * 256] = src[tid + t * 256];
        }
        __syncthreads();
#pragma unroll
        for (int ks = 0; ks < 4; ks++) {
            uint4 af = *(const uint4*)&A_sh[w][ks][lane][0];
#pragma unroll
            for (int j = 0; j < 16; j++) {
                uint2 bf = *(const uint2*)&W_sh[ks][j][lane][0];
                MMA_TF32(acc[j], af, bf);
            }
        }
        __syncthreads();
    }
    int r0 = row0 + w * 16 + (lane >> 2);
    int r1 = r0 + 8;
    int cbase = 2 * (lane & 3);
#pragma unroll
    for (int j = 0; j < 16; j++) {
        int c = j * 8 + cbase;
        float bz0 = bias[c], bz1 = bias[c + 1];
        if (r0 < M)
            *(float2*)(out + (size_t)r0 * 128 + c) = make_float2(acc[j][0] + bz0, acc[j][1] + bz1);
        if (r1 < M)
            *(float2*)(out + (size_t)r1 * 128 + c) = make_float2(acc[j][2] + bz0, acc[j][3] + bz1);
    }
}

// ---------------- TC GEMM dual: xl = A@W1+b1, xr = A@W2+b2 (tf32 mma) ------
__global__ __launch_bounds__(256) void k_gemm2(const float* __restrict__ A,
                                               int mat1,
                                               const float* __restrict__ b1,
                                               int mat2,
                                               const float* __restrict__ b2,
                                               float* __restrict__ out1,
                                               float* __restrict__ out2, int M) {
    __shared__ uint32_t A_sh[4][4][32][4];     // [wm][ks][lane][reg]       8 KB
    __shared__ uint32_t Wsh[2][4][16][32][2];  // [sel][ks][j][lane][reg]  32 KB
    int tid = threadIdx.x;
    int w = tid >> 5, lane = tid & 31;
    int wm = w & 3, sel = w >> 2;
    int row0 = blockIdx.x * 64;

    float acc[16][4];
#pragma unroll
    for (int j = 0; j < 16; j++)
#pragma unroll
        for (int c = 0; c < 4; c++) acc[j][c] = 0.f;

    for (int kc = 0; kc < 4; kc++) {
        // stage A chunk (64 x 32)
#pragma unroll
        for (int i = 0; i < 8; i++) {
            int idx = tid + i * 256;
            int r = idx >> 5, kq = idx & 31;
            int grow = row0 + r;
            float v = (grow < M) ? A[(size_t)grow * 128 + kc * 32 + kq] : 0.f;
            int ks = kq >> 3, k8 = kq & 7;
            int ln = ((r & 7) << 2) | (k8 & 3);
            int rg = ((r >> 3) & 1) | ((k8 >> 2) << 1);
            A_sh[r >> 4][ks][ln][rg] = f2tf32(v);
        }
        // stage W1 + W2 fragment chunks: vector copies
        {
            const uint4* s1 = (const uint4*)(g_wfrag + mat1 * 16384 + kc * 4096);
            const uint4* s2 = (const uint4*)(g_wfrag + mat2 * 16384 + kc * 4096);
            uint4* d1 = (uint4*)&Wsh[0][0][0][0][0];
            uint4* d2 = (uint4*)&Wsh[1][0][0][0][0];
#pragma unroll
            for (int t = 0; t < 4; t++) {
                d1[tid + t * 256] = s1[tid + t * 256];
                d2[tid + t * 256] = s2[tid + t * 256];
            }
        }
        __syncthreads();
#pragma unroll
        for (int ks = 0; ks < 4; ks++) {
            uint4 af = *(const uint4*)&A_sh[wm][ks][lane][0];
#pragma unroll
            for (int j = 0; j < 16; j++) {
                uint2 bf = *(const uint2*)&Wsh[sel][ks][j][lane][0];
                MMA_TF32(acc[j], af, bf);
            }
        }
        __syncthreads();
    }
    const float* bias = sel ? b2 : b1;
    float* out = sel ? out2 : out1;
    int r0 = row0 + wm * 16 + (lane >> 2);
    int r1 = r0 + 8;
    int cbase = 2 * (lane & 3);
#pragma unroll
    for (int j = 0; j < 16; j++) {
        int c = j * 8 + cbase;
        float bz0 = bias[c], bz1 = bias[c + 1];
        if (r0 < M)
            *(float2*)(out + (size_t)r0 * 128 + c) = make_float2(acc[j][0] + bz0, acc[j][1] + bz1);
        if (r1 < M)
            *(float2*)(out + (size_t)r1 * 128 + c) = make_float2(acc[j][2] + bz0, acc[j][3] + bz1);
    }
}

// ---------------- fused attention: 2-edge ILP, online softmax --------------
// (R14's L2 prefetch removed — it stuffed the L1tex queue and regressed.)
__global__ __launch_bounds__(256) void k_attn(const float* __restrict__ edge_attr,
                                              const float* __restrict__ We,
                                              const float* __restrict__ att,
                                              const float* __restrict__ cb) {
    __shared__ float4 We_sh[EDIM * 32];   // [k][lane] = We[k][4*lane..+3]
    __shared__ float4 att_sh[32];
    int tid = threadIdx.x;
    for (int i = tid; i < EDIM * 32; i += 256) We_sh[i] = ((const float4*)We)[i];
    if (tid < 32) att_sh[tid] = ((const float4*)att)[tid];
    __syncthreads();

    int lane = tid & 31;
    int n = blockIdx.x * 8 + (tid >> 5);
    if (n >= NN) return;
    int beg = g_rowptr[n], end = g_rowptr[n + 1];
    int nreal = end - beg - 1;
    float inv_deg = 1.f / (float)max(nreal, 1);

    float4 xr4    = *(const float4*)(g_xr + (size_t)n * DD + 4 * lane);
    float4 xlself = *(const float4*)(g_xl + (size_t)n * DD + 4 * lane);
    float4 at     = att_sh[lane];
    ull xrp0, xrp1;
    PACK2(xrp0, xr4.x, xr4.y);
    PACK2(xrp1, xr4.z, xr4.w);

    float mxh = -1e30f, den = 0.f;
    float4 acc = make_float4(0, 0, 0, 0);
    float ea_sum = 0.f;

    int npair = nreal & ~1;
    int pair_end = beg + npair;
    int real_end = beg + nreal;

    int2 csA, csB;
    float4 xlA, xlB;
    float rawA = 0.f, rawB = 0.f;
    if (npair > 0) {
        csA = g_csr[beg];       csB = g_csr[beg + 1];
        xlA = *(const float4*)(g_xl + (size_t)csA.x * DD + 4 * lane);
        xlB = *(const float4*)(g_xl + (size_t)csB.x * DD + 4 * lane);
        rawA = (lane < EDIM) ? edge_attr[(size_t)csA.y * EDIM + lane] : 0.f;
        rawB = (lane < EDIM) ? edge_attr[(size_t)csB.y * EDIM + lane] : 0.f;
    } else if (nreal == 1) {
        csA = g_csr[beg];
        xlA = *(const float4*)(g_xl + (size_t)csA.x * DD + 4 * lane);
        rawA = (lane < EDIM) ? edge_attr[(size_t)csA.y * EDIM + lane] : 0.f;
    }

    for (int i = beg; i < pair_end; i += 2) {
        float  myea0 = rawA, myea1 = rawB;
        float4 xl0 = xlA,  xl1 = xlB;
        ea_sum += myea0 + myea1;

        // stage next pair (loads overlap compute below)
        int inext = i + 2;
        if (inext + 1 < real_end) {
            csA = g_csr[inext]; csB = g_csr[inext + 1];
            xlA = *(const float4*)(g_xl + (size_t)csA.x * DD + 4 * lane);
            xlB = *(const float4*)(g_xl + (size_t)csB.x * DD + 4 * lane);
            rawA = (lane < EDIM) ? edge_attr[(size_t)csA.y * EDIM + lane] : 0.f;
            rawB = (lane < EDIM) ? edge_attr[(size_t)csB.y * EDIM + lane] : 0.f;
        } else if (inext < real_end) {
            csA = g_csr[inext];
            xlA = *(const float4*)(g_xl + (size_t)csA.x * DD + 4 * lane);
            rawA = (lane < EDIM) ? edge_attr[(size_t)csA.y * EDIM + lane] : 0.f;
        }

        ull e00 = 0ULL, e01 = 0ULL, e10 = 0ULL, e11 = 0ULL;
#pragma unroll
        for (int k = 0; k < EDIM; k++) {
            float a0 = __shfl_sync(0xffffffffu, myea0, k);
            float a1 = __shfl_sync(0xffffffffu, myea1, k);
            ull d0, d1; DUP2(d0, a0); DUP2(d1, a1);
            ulonglong2 wp = *(const ulonglong2*)&We_sh[k * 32 + lane];
            FFMA2(e00, d0, wp.x); FFMA2(e01, d0, wp.y);
            FFMA2(e10, d1, wp.x); FFMA2(e11, d1, wp.y);
        }
        ull xp0, xp1, yp0, yp1;
        PACK2(xp0, xl0.x, xl0.y); PACK2(xp1, xl0.z, xl0.w);
        PACK2(yp0, xl1.x, xl1.y); PACK2(yp1, xl1.z, xl1.w);
        ull m00, m01, m10, m11;
        FADD2(m00, xp0, xrp0); FADD2(m00, m00, e00);
        FADD2(m01, xp1, xrp1); FADD2(m01, m01, e01);
        FADD2(m10, yp0, xrp0); FADD2(m10, m10, e10);
        FADD2(m11, yp1, xrp1); FADD2(m11, m11, e11);
        float4 u, v;
        UNPK2(u.x, u.y, m00); UNPK2(u.z, u.w, m01);
        UNPK2(v.x, v.y, m10); UNPK2(v.z, v.w, m11);
        u.x = (u.x > 0.f) ? u.x : NEG_SLOPE * u.x;
        u.y = (u.y > 0.f) ? u.y : NEG_SLOPE * u.y;
        u.z = (u.z > 0.f) ? u.z : NEG_SLOPE * u.z;
        u.w = (u.w > 0.f) ? u.w : NEG_SLOPE * u.w;
        v.x = (v.x > 0.f) ? v.x : NEG_SLOPE * v.x;
        v.y = (v.y > 0.f) ? v.y : NEG_SLOPE * v.y;
        v.z = (v.z > 0.f) ? v.z : NEG_SLOPE * v.z;
        v.w = (v.w > 0.f) ? v.w : NEG_SLOPE * v.w;
        float p0 = u.x * at.x + u.y * at.y + u.z * at.z + u.w * at.w;
        float p1 = v.x * at.x + v.y * at.y + v.z * at.z + v.w * at.w;
        p0 += __shfl_xor_sync(0xffffffffu, p0, 1);
        p1 += __shfl_xor_sync(0xffffffffu, p1, 1);
        p0 += __shfl_xor_sync(0xffffffffu, p0, 2);
        p1 += __shfl_xor_sync(0xffffffffu, p1, 2);
        p0 += __shfl_xor_sync(0xffffffffu, p0, 4);
        p1 += __shfl_xor_sync(0xffffffffu, p1, 4);

        float newmx = fmaxf(mxh, fmaxf(p0, p1));
        float s  = __expf(mxh - newmx);
        float a0 = __expf(p0 - newmx);
        float a1 = __expf(p1 - newmx);
        mxh = newmx;
        den = fmaf(den, s, a0 + a1);
        acc.x = fmaf(acc.x, s, fmaf(a0, xl0.x, a1 * xl1.x));
        acc.y = fmaf(acc.y, s, fmaf(a0, xl0.y, a1 * xl1.y));
        acc.z = fmaf(acc.z, s, fmaf(a0, xl0.z, a1 * xl1.z));
        acc.w = fmaf(acc.w, s, fmaf(a0, xl0.w, a1 * xl1.w));
    }

#pragma unroll
    for (int t = 0; t < 2; t++) {
        float myea;
        float4 xlv;
        if (t == 0) {
            if (!(nreal & 1)) continue;
            myea = rawA;
            xlv  = xlA;
            ea_sum += myea;
        } else {
            myea = ea_sum * inv_deg;
            xlv  = xlself;
        }
        ull ee0 = 0ULL, ee1 = 0ULL;
#pragma unroll
        for (int k = 0; k < EDIM; k++) {
            float a = __shfl_sync(0xffffffffu, myea, k);
            ull ad; DUP2(ad, a);
            ulonglong2 wp = *(const ulonglong2*)&We_sh[k * 32 + lane];
            FFMA2(ee0, ad, wp.x);
            FFMA2(ee1, ad, wp.y);
        }
        ull xp0, xp1;
        PACK2(xp0, xlv.x, xlv.y); PACK2(xp1, xlv.z, xlv.w);
        ull m0p, m1p;
        FADD2(m0p, xp0, xrp0); FADD2(m0p, m0p, ee0);
        FADD2(m1p, xp1, xrp1); FADD2(m1p, m1p, ee1);
        float4 m;
        UNPK2(m.x, m.y, m0p); UNPK2(m.z, m.w, m1p);
        m.x = (m.x > 0.f) ? m.x : NEG_SLOPE * m.x;
        m.y = (m.y > 0.f) ? m.y : NEG_SLOPE * m.y;
        m.z = (m.z > 0.f) ? m.z : NEG_SLOPE * m.z;
        m.w = (m.w > 0.f) ? m.w : NEG_SLOPE * m.w;
        float p = m.x * at.x + m.y * at.y + m.z * at.z + m.w * at.w;
        p += __shfl_xor_sync(0xffffffffu, p, 1);
        p += __shfl_xor_sync(0xffffffffu, p, 2);
        p += __shfl_xor_sync(0xffffffffu, p, 4);

        float newmx = fmaxf(mxh, p);
        float s = __expf(mxh - newmx);
        float a = __expf(p - newmx);
        mxh = newmx;
        den = fmaf(den, s, a);
        acc.x = fmaf(acc.x, s, a * xlv.x);
        acc.y = fmaf(acc.y, s, a * xlv.y);
        acc.z = fmaf(acc.z, s, a * xlv.z);
        acc.w = fmaf(acc.w, s, a * xlv.w);
    }

    float inv = 1.f / den;
    float4 cbv = *(const float4*)(cb + 4 * lane);
    float4 o;
    o.x = acc.x * inv + cbv.x;
    o.y = acc.y * inv + cbv.y;
    o.z = acc.z * inv + cbv.z;
    o.w = acc.w * inv + cbv.w;
    o.x = (o.x > 0.f) ? o.x : expm1f(o.x);
    o.y = (o.y > 0.f) ? o.y : expm1f(o.y);
    o.z = (o.z > 0.f) ? o.z : expm1f(o.z);
    o.w = (o.w > 0.f) ? o.w : expm1f(o.w);
    *(float4*)(g_h + (size_t)n * DD + 4 * lane) = o;
}

// ---------------- final: LN + MLP head; warp handles 4 rows ----------------
__global__ __launch_bounds__(256) void k_final(const float* __restrict__ ln_g,
                                               const float* __restrict__ ln_b,
                                               const float* __restrict__ h1w,
                                               const float* __restrict__ h1b,
                                               const float* __restrict__ h2w,
                                               const float* __restrict__ h2b,
                                               float* __restrict__ out) {
    __shared__ ull  W1p[128 * 32];
    __shared__ float W2[64 * 3];
    __shared__ float rowbuf[8][128];
    int tid = threadIdx.x;
    for (int idx = tid; idx < 128 * 32; idx += 256) {
        int k = idx >> 5, c = idx & 31;
        ull p; PACK2(p, h1w[k * 64 + c], h1w[k * 64 + c + 32]);
        W1p[idx] = p;
    }
    if (tid < 64 * 3) W2[tid] = h2w[tid];
    __syncthreads();

    int lane = tid & 31, w = tid >> 5;
    float4 g4 = *(const float4*)(ln_g + 4 * lane);
    float4 b4 = *(const float4*)(ln_b + 4 * lane);
    ull bias01; PACK2(bias01, h1b[lane], h1b[lane + 32]);

    for (int j = 0; j < 4; j++) {
        int n = blockIdx.x * 32 + w * 4 + j;
        if (n >= NN) return;

        float4 hv = *(const float4*)(g_h + (size_t)n * DD + 4 * lane);
        float s = hv.x + hv.y + hv.z + hv.w;
#pragma unroll
        for (int off = 16; off > 0; off >>= 1) s += __shfl_xor_sync(0xffffffffu, s, off);
        float mu = s / 128.f;
        float4 dm = make_float4(hv.x - mu, hv.y - mu, hv.z - mu, hv.w - mu);
        float v = dm.x * dm.x + dm.y * dm.y + dm.z * dm.z + dm.w * dm.w;
#pragma unroll
        for (int off = 16; off > 0; off >>= 1) v += __shfl_xor_sync(0xffffffffu, v, off);
        float r = rsqrtf(v / 128.f + 1e-5f);
        float4 hn;
        hn.x = dm.x * r * g4.x + b4.x;
        hn.y = dm.y * r * g4.y + b4.y;
        hn.z = dm.z * r * g4.z + b4.z;
        hn.w = dm.w * r * g4.w + b4.w;
        *(float4*)&rowbuf[w][4 * lane] = hn;
        __syncwarp();

        ull m01 = bias01;
#pragma unroll 8
        for (int k = 0; k < 128; k++) {
            float a = rowbuf[w][k];
            ull ad; DUP2(ad, a);
            FFMA2(m01, ad, W1p[k * 32 + lane]);
        }
        float m0, m1;
        UNPK2(m0, m1, m01);
        m0 = fmaxf(m0, 0.f);
        m1 = fmaxf(m1, 0.f);
        float p0 = m0 * W2[lane * 3 + 0] + m1 * W2[(lane + 32) * 3 + 0];
        float p1 = m0 * W2[lane * 3 + 1] + m1 * W2[(lane + 32) * 3 + 1];
        float p2 = m0 * W2[lane * 3 + 2] + m1 * W2[(lane + 32) * 3 + 2];
#pragma unroll
        for (int off = 16; off > 0; off >>= 1) {
            p0 += __shfl_xor_sync(0xffffffffu, p0, off);
            p1 += __shfl_xor_sync(0xffffffffu, p1, off);
            p2 += __shfl_xor_sync(0xffffffffu, p2, off);
        }
        if (lane == 0) {
            out[(size_t)n * 3 + 0] = p0 + h2b[0];
            out[(size_t)n * 3 + 1] = p1 + h2b[1];
            out[(size_t)n * 3 + 2] = p2 + h2b[2];
        }
        __syncwarp();
    }
}

// ---------------- host launcher -------------------------------------------
extern "C" void kernel_launch(void* const* d_in, const int* in_sizes, int n_in,
                              void* d_out, int out_size) {
    const float* x         = (const float*)d_in[0];
    const int*   ei_raw    = (const int*)d_in[1];
    const float* edge_attr = (const float*)d_in[2];
    const float* in_w      = (const float*)d_in[3];
    const float* in_b      = (const float*)d_in[4];
    const float* Wl        = (const float*)d_in[5];
    const float* bl        = (const float*)d_in[6];
    const float* Wr        = (const float*)d_in[7];
    const float* br        = (const float*)d_in[8];
    const float* We        = (const float*)d_in[9];
    const float* att       = (const float*)d_in[10];
    const float* cb        = (const float*)d_in[11];
    const float* ln_g      = (const float*)d_in[12];
    const float* ln_b      = (const float*)d_in[13];
    const float* h1w       = (const float*)d_in[14];
    const float* h1b       = (const float*)d_in[15];
    const float* h2w       = (const float*)d_in[16];
    const float* h2b       = (const float*)d_in[17];

    float *hp, *xlp, *xrp;
    cudaGetSymbolAddress((void**)&hp,  g_h);
    cudaGetSymbolAddress((void**)&xlp, g_xl);
    cudaGetSymbolAddress((void**)&xrp, g_xr);

    // order keeps k_gemm2 as the 4th launch (ncu capture window).
    k_wprep<<<5, 256>>>(in_w, Wl, Wr);
    k_gemm1<<<(NN + 127) / 128, 256>>>(x, 0, in_b, hp, NN);
    k_zero<<<(NN + 255) / 256, 256>>>(ei_raw);
    k_gemm2<<<(NN + 63) / 64, 256>>>(hp, 1, bl, 2, br, xlp, xrp, NN);   // layer 0
    k_cvt_deg<<<(2 * EE + 255) / 256, 256>>>(ei_raw);
    k_scan<<<1, 1024>>>();
    k_scatter<<<(ETOT + 255) / 256, 256>>>();
    k_attn<<<(NN + 7) / 8, 256>>>(edge_attr, We, att, cb);               // layer 0

    // layer 1
    k_gemm2<<<(NN + 63) / 64, 256>>>(hp, 3, bl + 128, 4, br + 128, xlp, xrp, NN);
    k_attn<<<(NN + 7) / 8, 256>>>(edge_attr, We + EDIM * 128, att + 128, cb + 128);

    k_final<<<(NN + 31) / 32, 256>>>(ln_g, ln_b, h1w, h1b, h2w, h2b, (float*)d_out);
}